// round 5
// baseline (speedup 1.0000x reference)
#include <cuda_runtime.h>
#include <cstdint>
#include <cstddef>

#define BATCH 32
#define C_CH  2048
#define N_SP  1152   // 48*24
#define MIDC  128

// ---------------- scratch (device globals; no allocation allowed) ----------------
__device__ __align__(128) float g_q[(size_t)BATCH * N_SP * MIDC];     // [b][n][m]
__device__ __align__(128) float g_k[(size_t)BATCH * MIDC * N_SP];     // [b][m][n]
__device__ __align__(128) float g_attn[(size_t)BATCH * N_SP * N_SP];  // [b][i][j]
__device__ __align__(128) float g_Whi[2][(size_t)MIDC * C_CH];        // tf32 hi of Wq/Wk
__device__ __align__(128) float g_Wlo[2][(size_t)MIDC * C_CH];        // tf32 lo

// ---------------- helpers ----------------
__device__ __forceinline__ uint32_t f32_to_tf32(float x) {
    uint32_t r;
    asm("cvt.rna.tf32.f32 %0, %1;" : "=r"(r) : "f"(x));
    return r;
}
__device__ __forceinline__ void split_tf32(float x, uint32_t& hi, uint32_t& lo) {
    hi = f32_to_tf32(x);
    lo = f32_to_tf32(x - __uint_as_float(hi));
}
__device__ __forceinline__ void cp_async16(void* smem, const void* gmem) {
    uint32_t s = (uint32_t)__cvta_generic_to_shared(smem);
    asm volatile("cp.async.cg.shared.global [%0], [%1], 16;" :: "r"(s), "l"(gmem));
}
__device__ __forceinline__ void cp_commit() {
    asm volatile("cp.async.commit_group;" ::: "memory");
}
template <int NN>
__device__ __forceinline__ void cp_wait() {
    asm volatile("cp.async.wait_group %0;" :: "n"(NN) : "memory");
}
__device__ __forceinline__ void mma_tf32(float c[4], const uint32_t a[4], const uint32_t b[2]) {
    asm volatile(
        "mma.sync.aligned.m16n8k8.row.col.f32.tf32.tf32.f32 "
        "{%0,%1,%2,%3}, {%4,%5,%6,%7}, {%8,%9}, {%0,%1,%2,%3};"
        : "+f"(c[0]), "+f"(c[1]), "+f"(c[2]), "+f"(c[3])
        : "r"(a[0]), "r"(a[1]), "r"(a[2]), "r"(a[3]), "r"(b[0]), "r"(b[1]));
}

// ---- shared geometry ----
#define AS_ELEMS (128 * 20)
#define BS_ELEMS (16 * 132)
#define NSTAGE 3
#define K1_SMEM (NSTAGE * (2 * AS_ELEMS + BS_ELEMS) * 4)
#define K2_SMEM (NSTAGE * (AS_ELEMS + BS_ELEMS) * 4)
// K3: 256x128 block tile, BK=32, 3 stages
#define AS3_ELEMS (256 * 36)
#define BS3_ELEMS (32 * 136)
#define K3_SMEM (NSTAGE * (AS3_ELEMS + BS3_ELEMS) * 4)   // 162816 B

// ============================================================================
// K0: one-time tf32 split of Wq/Wk (tiny).
// ============================================================================
__global__ void k0_splitW(const float* __restrict__ Wq, const float* __restrict__ Wk)
{
    const int i = blockIdx.x * 256 + threadIdx.x;
    if (i >= MIDC * C_CH) return;
    uint32_t h, l;
    split_tf32(Wq[i], h, l);
    g_Whi[0][i] = __uint_as_float(h); g_Wlo[0][i] = __uint_as_float(l);
    split_tf32(Wk[i], h, l);
    g_Whi[1][i] = __uint_as_float(h); g_Wlo[1][i] = __uint_as_float(l);
}

// ============================================================================
// K1: projections via 3xTF32 mma.sync. Wsel[128,2048] @ x[2048,1152].
//   mblk=0 -> q stored transposed g_q[b][n][m];  mblk=1 -> k stored g_k[b][m][n]
// A-side (W) pre-split by k0 (hi/lo tiles via cp.async, no in-loop split).
// ============================================================================
__global__ __launch_bounds__(256, 2) void k1_proj(const float* __restrict__ feat)
{
    const int nblk = blockIdx.x;          // 0..8
    const int mblk = blockIdx.y;          // 0..1
    const int b    = blockIdx.z;
    const float* Whi = g_Whi[mblk];
    const float* Wlo = g_Wlo[mblk];
    const float* X = feat + (size_t)b * C_CH * N_SP;

    extern __shared__ float smem[];
    float (*Ah)[128][20] = (float(*)[128][20])smem;
    float (*Al)[128][20] = (float(*)[128][20])(smem + NSTAGE * AS_ELEMS);
    float (*Bs)[16][132] = (float(*)[16][132])(smem + 2 * NSTAGE * AS_ELEMS);

    const int tid  = threadIdx.x;
    const int warp = tid >> 5, lane = tid & 31;
    const int wm = warp >> 2, wn = warp & 3;
    const int g = lane >> 2, tig = lane & 3;
    const int n0 = nblk * 128;

    float acc[4][4][4] = {};

    auto loadStage = [&](int kt, int buf) {
        const int k0 = kt * 16;
        #pragma unroll
        for (int it = 0; it < 2; it++) {          // A hi: 128x16
            int id  = tid + it * 256;
            int row = id >> 2;
            int c4  = (id & 3) * 4;
            cp_async16(&Ah[buf][row][c4], Whi + (size_t)row * C_CH + k0 + c4);
        }
        #pragma unroll
        for (int it = 0; it < 2; it++) {          // A lo
            int id  = tid + it * 256;
            int row = id >> 2;
            int c4  = (id & 3) * 4;
            cp_async16(&Al[buf][row][c4], Wlo + (size_t)row * C_CH + k0 + c4);
        }
        #pragma unroll
        for (int it = 0; it < 2; it++) {          // B: 16x128
            int id  = tid + it * 256;
            int row = id >> 5;
            int c4  = (id & 31) * 4;
            cp_async16(&Bs[buf][row][c4], X + (size_t)(k0 + row) * N_SP + n0 + c4);
        }
    };

    const int KT = C_CH / 16;   // 128
    loadStage(0, 0); cp_commit();
    loadStage(1, 1); cp_commit();

    for (int kt = 0; kt < KT; kt++) {
        if (kt + 1 < KT) cp_wait<1>(); else cp_wait<0>();
        __syncthreads();
        const int buf = kt % 3;
        if (kt + 2 < KT) { loadStage(kt + 2, (kt + 2) % 3); cp_commit(); }

        #pragma unroll
        for (int ks = 0; ks < 2; ks++) {
            const int kb = ks * 8;
            uint32_t bhi[4][2], blo[4][2];
            #pragma unroll
            for (int fn = 0; fn < 4; fn++) {
                int jc = wn * 32 + fn * 8;
                split_tf32(Bs[buf][kb + tig    ][jc + g], bhi[fn][0], blo[fn][0]);
                split_tf32(Bs[buf][kb + tig + 4][jc + g], bhi[fn][1], blo[fn][1]);
            }
            #pragma unroll
            for (int fm = 0; fm < 4; fm++) {
                int mr = wm * 64 + fm * 16;
                uint32_t ahi[4], alo[4];
                ahi[0] = __float_as_uint(Ah[buf][mr + g    ][kb + tig    ]);
                ahi[1] = __float_as_uint(Ah[buf][mr + g + 8][kb + tig    ]);
                ahi[2] = __float_as_uint(Ah[buf][mr + g    ][kb + tig + 4]);
                ahi[3] = __float_as_uint(Ah[buf][mr + g + 8][kb + tig + 4]);
                alo[0] = __float_as_uint(Al[buf][mr + g    ][kb + tig    ]);
                alo[1] = __float_as_uint(Al[buf][mr + g + 8][kb + tig    ]);
                alo[2] = __float_as_uint(Al[buf][mr + g    ][kb + tig + 4]);
                alo[3] = __float_as_uint(Al[buf][mr + g + 8][kb + tig + 4]);
                #pragma unroll
                for (int fn = 0; fn < 4; fn++) {
                    mma_tf32(acc[fm][fn], ahi, bhi[fn]);
                    mma_tf32(acc[fm][fn], alo, bhi[fn]);
                    mma_tf32(acc[fm][fn], ahi, blo[fn]);
                }
            }
        }
    }

    if (mblk == 0) {
        float* q = g_q + (size_t)b * N_SP * MIDC;   // [n][m]
        #pragma unroll
        for (int fm = 0; fm < 4; fm++) {
            #pragma unroll
            for (int fn = 0; fn < 4; fn++) {
                int m   = wm * 64 + fm * 16 + g;
                int col = n0 + wn * 32 + fn * 8 + tig * 2;
                q[(size_t)(col    ) * MIDC + m    ] = acc[fm][fn][0];
                q[(size_t)(col + 1) * MIDC + m    ] = acc[fm][fn][1];
                q[(size_t)(col    ) * MIDC + m + 8] = acc[fm][fn][2];
                q[(size_t)(col + 1) * MIDC + m + 8] = acc[fm][fn][3];
            }
        }
    } else {
        float* kp = g_k + (size_t)b * MIDC * N_SP;  // [m][n]
        #pragma unroll
        for (int fm = 0; fm < 4; fm++) {
            #pragma unroll
            for (int fn = 0; fn < 4; fn++) {
                int m   = wm * 64 + fm * 16 + g;
                int col = n0 + wn * 32 + fn * 8 + tig * 2;
                *(float2*)(kp + (size_t)m * N_SP + col)       = make_float2(acc[fm][fn][0], acc[fm][fn][1]);
                *(float2*)(kp + (size_t)(m + 8) * N_SP + col) = make_float2(acc[fm][fn][2], acc[fm][fn][3]);
            }
        }
    }
}

// ============================================================================
// K2a: logits L[b][i][j] = sum_m q[b][i][m] * k[b][m][j]. 3xTF32, K=128.
// ============================================================================
__global__ __launch_bounds__(256, 2) void k2_logits()
{
    const int jblk = blockIdx.x;   // 0..8
    const int iblk = blockIdx.y;   // 0..8
    const int b    = blockIdx.z;
    const float* A = g_q + (size_t)b * N_SP * MIDC;    // [1152][128]
    const float* B = g_k + (size_t)b * MIDC * N_SP;    // [128][1152]
    float* L = g_attn + (size_t)b * N_SP * N_SP;

    extern __shared__ float smem[];
    float (*As)[128][20] = (float(*)[128][20])smem;
    float (*Bs)[16][132] = (float(*)[16][132])(smem + NSTAGE * AS_ELEMS);

    const int tid  = threadIdx.x;
    const int warp = tid >> 5, lane = tid & 31;
    const int wm = warp >> 2, wn = warp & 3;
    const int g = lane >> 2, tig = lane & 3;
    const int i0 = iblk * 128, j0 = jblk * 128;

    float acc[4][4][4] = {};

    auto loadStage = [&](int kt, int buf) {
        const int k0 = kt * 16;
        #pragma unroll
        for (int it = 0; it < 2; it++) {
            int id  = tid + it * 256;
            int row = id >> 2;
            int c4  = (id & 3) * 4;
            cp_async16(&As[buf][row][c4], A + (size_t)(i0 + row) * MIDC + k0 + c4);
        }
        #pragma unroll
        for (int it = 0; it < 2; it++) {
            int id  = tid + it * 256;
            int row = id >> 5;
            int c4  = (id & 31) * 4;
            cp_async16(&Bs[buf][row][c4], B + (size_t)(k0 + row) * N_SP + j0 + c4);
        }
    };

    const int KT = MIDC / 16;   // 8
    loadStage(0, 0); cp_commit();
    loadStage(1, 1); cp_commit();

    for (int kt = 0; kt < KT; kt++) {
        if (kt + 1 < KT) cp_wait<1>(); else cp_wait<0>();
        __syncthreads();
        const int buf = kt % 3;
        if (kt + 2 < KT) { loadStage(kt + 2, (kt + 2) % 3); cp_commit(); }

        #pragma unroll
        for (int ks = 0; ks < 2; ks++) {
            const int kb = ks * 8;
            uint32_t bhi[4][2], blo[4][2];
            #pragma unroll
            for (int fn = 0; fn < 4; fn++) {
                int jc = wn * 32 + fn * 8;
                split_tf32(Bs[buf][kb + tig    ][jc + g], bhi[fn][0], blo[fn][0]);
                split_tf32(Bs[buf][kb + tig + 4][jc + g], bhi[fn][1], blo[fn][1]);
            }
            #pragma unroll
            for (int fm = 0; fm < 4; fm++) {
                int mr = wm * 64 + fm * 16;
                uint32_t ahi[4], alo[4];
                split_tf32(As[buf][mr + g    ][kb + tig    ], ahi[0], alo[0]);
                split_tf32(As[buf][mr + g + 8][kb + tig    ], ahi[1], alo[1]);
                split_tf32(As[buf][mr + g    ][kb + tig + 4], ahi[2], alo[2]);
                split_tf32(As[buf][mr + g + 8][kb + tig + 4], ahi[3], alo[3]);
                #pragma unroll
                for (int fn = 0; fn < 4; fn++) {
                    mma_tf32(acc[fm][fn], ahi, bhi[fn]);
                    mma_tf32(acc[fm][fn], alo, bhi[fn]);
                    mma_tf32(acc[fm][fn], ahi, blo[fn]);
                }
            }
        }
    }

    #pragma unroll
    for (int fm = 0; fm < 4; fm++) {
        #pragma unroll
        for (int fn = 0; fn < 4; fn++) {
            int ii  = i0 + wm * 64 + fm * 16 + g;
            int col = j0 + wn * 32 + fn * 8 + tig * 2;
            *(float2*)(L + (size_t)ii * N_SP + col)       = make_float2(acc[fm][fn][0], acc[fm][fn][1]);
            *(float2*)(L + (size_t)(ii + 8) * N_SP + col) = make_float2(acc[fm][fn][2], acc[fm][fn][3]);
        }
    }
}

// ============================================================================
// K2b: row softmax (length 1152), one warp per row. Output tf32-rounded (RNA)
// so K3's B operand is exact tf32.
// ============================================================================
__global__ void k2_softmax()
{
    const int row  = blockIdx.x * 8 + (threadIdx.x >> 5);
    const int lane = threadIdx.x & 31;
    float* r = g_attn + (size_t)row * N_SP;

    float f[36];
    float mx = -1e30f;
    #pragma unroll
    for (int t = 0; t < 36; t++) {
        f[t] = r[lane + 32 * t];
        mx = fmaxf(mx, f[t]);
    }
    #pragma unroll
    for (int o = 16; o > 0; o >>= 1) mx = fmaxf(mx, __shfl_xor_sync(0xffffffffu, mx, o));

    float s = 0.0f;
    #pragma unroll
    for (int t = 0; t < 36; t++) {
        f[t] = __expf(f[t] - mx);
        s += f[t];
    }
    #pragma unroll
    for (int o = 16; o > 0; o >>= 1) s += __shfl_xor_sync(0xffffffffu, s, o);

    const float inv = 1.0f / s;
    #pragma unroll
    for (int t = 0; t < 36; t++)
        r[lane + 32 * t] = __uint_as_float(f32_to_tf32(f[t] * inv));
}

// ============================================================================
// K3: refined = cam[b] @ attn[b]; out = alpha*refined + cam.
// TF32 mma.sync. Block tile 256x128, 8 warps (4m x 2n) of 64x64, BK=32,
// 3-stage cp.async (162KB smem, 1 CTA/SM). A fed raw f32 (HW tf32 truncation);
// B pre-rounded RNA by softmax.
// ============================================================================
__global__ __launch_bounds__(256) void k3_refined(
    const float* __restrict__ cam,
    const float* __restrict__ alphaPtr,
    float* __restrict__ out)
{
    const int jblk = blockIdx.x;   // 0..8
    const int cblk = blockIdx.y;   // 0..7
    const int b    = blockIdx.z;

    const float* A  = cam    + (size_t)b * C_CH * N_SP;   // [2048][1152]
    const float* Bm = g_attn + (size_t)b * N_SP * N_SP;   // [1152][1152] tf32-rounded

    extern __shared__ float smem[];
    float (*As)[256][36] = (float(*)[256][36])smem;
    float (*Bs)[32][136] = (float(*)[32][136])(smem + NSTAGE * AS3_ELEMS);

    const int tid  = threadIdx.x;
    const int warp = tid >> 5, lane = tid & 31;
    const int wm = warp >> 1, wn = warp & 1;   // 4 x 2 warps, 64x64 each
    const int g = lane >> 2, tig = lane & 3;
    const int c0 = cblk * 256, j0 = jblk * 128;

    float acc[4][8][4] = {};

    auto loadStage = [&](int kt, int buf) {
        const int k0 = kt * 32;
        #pragma unroll
        for (int it = 0; it < 8; it++) {              // A: 256x32 = 2048 float4
            int id  = tid + it * 256;
            int row = id >> 3;
            int c4  = (id & 7) * 4;
            cp_async16(&As[buf][row][c4], A + (size_t)(c0 + row) * N_SP + k0 + c4);
        }
        #pragma unroll
        for (int it = 0; it < 4; it++) {              // B: 32x128 = 1024 float4
            int id  = tid + it * 256;
            int row = id >> 5;
            int c4  = (id & 31) * 4;
            cp_async16(&Bs[buf][row][c4], Bm + (size_t)(k0 + row) * N_SP + j0 + c4);
        }
    };

    const int KT = N_SP / 32;   // 36
    loadStage(0, 0); cp_commit();
    loadStage(1, 1); cp_commit();

    for (int kt = 0; kt < KT; kt++) {
        if (kt + 1 < KT) cp_wait<1>(); else cp_wait<0>();
        __syncthreads();
        const int buf = kt % 3;
        if (kt + 2 < KT) { loadStage(kt + 2, (kt + 2) % 3); cp_commit(); }

        #pragma unroll
        for (int ks = 0; ks < 4; ks++) {
            const int kb = ks * 8;
            uint32_t bfr[8][2];
            #pragma unroll
            for (int fn = 0; fn < 8; fn++) {
                int jc = wn * 64 + fn * 8;
                bfr[fn][0] = __float_as_uint(Bs[buf][kb + tig    ][jc + g]);
                bfr[fn][1] = __float_as_uint(Bs[buf][kb + tig + 4][jc + g]);
            }
            #pragma unroll
            for (int fm = 0; fm < 4; fm++) {
                int mr = wm * 64 + fm * 16;
                uint32_t afr[4];
                // raw f32 bits: HMMA truncates mantissa to tf32 internally
                afr[0] = __float_as_uint(As[buf][mr + g    ][kb + tig    ]);
                afr[1] = __float_as_uint(As[buf][mr + g + 8][kb + tig    ]);
                afr[2] = __float_as_uint(As[buf][mr + g    ][kb + tig + 4]);
                afr[3] = __float_as_uint(As[buf][mr + g + 8][kb + tig + 4]);
                #pragma unroll
                for (int fn = 0; fn < 8; fn++)
                    mma_tf32(acc[fm][fn], afr, bfr[fn]);
            }
        }
    }

    const float alpha = alphaPtr[0];
    const size_t base = (size_t)b * C_CH * N_SP;
    #pragma unroll
    for (int fm = 0; fm < 4; fm++) {
        #pragma unroll
        for (int fn = 0; fn < 8; fn++) {
            int mrow = c0 + wm * 64 + fm * 16 + g;
            int col  = j0 + wn * 64 + fn * 8 + tig * 2;
            const float2 cv0 = *(const float2*)(A + (size_t)mrow * N_SP + col);
            const float2 cv1 = *(const float2*)(A + (size_t)(mrow + 8) * N_SP + col);
            float2 r0, r1;
            r0.x = fmaf(alpha, acc[fm][fn][0], cv0.x);
            r0.y = fmaf(alpha, acc[fm][fn][1], cv0.y);
            r1.x = fmaf(alpha, acc[fm][fn][2], cv1.x);
            r1.y = fmaf(alpha, acc[fm][fn][3], cv1.y);
            *(float2*)(out + base + (size_t)mrow * N_SP + col)       = r0;
            *(float2*)(out + base + (size_t)(mrow + 8) * N_SP + col) = r1;
        }
    }
}

// ============================================================================
extern "C" void kernel_launch(void* const* d_in, const int* in_sizes, int n_in,
                              void* d_out, int out_size)
{
    (void)in_sizes; (void)n_in; (void)out_size;
    const float* feat  = (const float*)d_in[0];
    const float* cam   = (const float*)d_in[1];
    const float* Wq    = (const float*)d_in[2];
    const float* Wk    = (const float*)d_in[3];
    const float* alpha = (const float*)d_in[4];
    float* out = (float*)d_out;

    cudaFuncSetAttribute(k1_proj,    cudaFuncAttributeMaxDynamicSharedMemorySize, K1_SMEM);
    cudaFuncSetAttribute(k2_logits,  cudaFuncAttributeMaxDynamicSharedMemorySize, K2_SMEM);
    cudaFuncSetAttribute(k3_refined, cudaFuncAttributeMaxDynamicSharedMemorySize, K3_SMEM);

    k0_splitW<<<(MIDC * C_CH + 255) / 256, 256>>>(Wq, Wk);
    k1_proj<<<dim3(9, 2, BATCH), 256, K1_SMEM>>>(feat);
    k2_logits<<<dim3(9, 9, BATCH), 256, K2_SMEM>>>();
    k2_softmax<<<(BATCH * N_SP) / 8, 256>>>();
    k3_refined<<<dim3(9, 8, BATCH), 256, K3_SMEM>>>(cam, alpha, out);
}

// round 6
// speedup vs baseline: 1.2518x; 1.2518x over previous
#include <cuda_runtime.h>
#include <cuda_fp16.h>
#include <cstdint>
#include <cstddef>

#define BATCH 32
#define C_CH  2048
#define N_SP  1152   // 48*24
#define MIDC  128

// ---------------- scratch (device globals; no allocation allowed) ----------------
__device__ __align__(128) float  g_q[(size_t)BATCH * N_SP * MIDC];       // [b][n][m]
__device__ __align__(128) float  g_k[(size_t)BATCH * MIDC * N_SP];       // [b][m][n]
__device__ __align__(128) float  g_attn[(size_t)BATCH * N_SP * N_SP];    // [b][i][j]
__device__ __align__(128) __half g_attnT[(size_t)BATCH * N_SP * N_SP];   // [b][j][i] fp16
__device__ __align__(128) __half g_camh[(size_t)BATCH * C_CH * N_SP];    // cam fp16
__device__ __align__(128) float  g_Whi[2][(size_t)MIDC * C_CH];          // tf32 hi of Wq/Wk
__device__ __align__(128) float  g_Wlo[2][(size_t)MIDC * C_CH];          // tf32 lo

// ---------------- helpers ----------------
__device__ __forceinline__ uint32_t f32_to_tf32(float x) {
    uint32_t r;
    asm("cvt.rna.tf32.f32 %0, %1;" : "=r"(r) : "f"(x));
    return r;
}
__device__ __forceinline__ void split_tf32(float x, uint32_t& hi, uint32_t& lo) {
    hi = f32_to_tf32(x);
    lo = f32_to_tf32(x - __uint_as_float(hi));
}
__device__ __forceinline__ void cp_async16(void* smem, const void* gmem) {
    uint32_t s = (uint32_t)__cvta_generic_to_shared(smem);
    asm volatile("cp.async.cg.shared.global [%0], [%1], 16;" :: "r"(s), "l"(gmem));
}
__device__ __forceinline__ void cp_commit() {
    asm volatile("cp.async.commit_group;" ::: "memory");
}
template <int NN>
__device__ __forceinline__ void cp_wait() {
    asm volatile("cp.async.wait_group %0;" :: "n"(NN) : "memory");
}
__device__ __forceinline__ void mma_tf32(float c[4], const uint32_t a[4], const uint32_t b[2]) {
    asm volatile(
        "mma.sync.aligned.m16n8k8.row.col.f32.tf32.tf32.f32 "
        "{%0,%1,%2,%3}, {%4,%5,%6,%7}, {%8,%9}, {%0,%1,%2,%3};"
        : "+f"(c[0]), "+f"(c[1]), "+f"(c[2]), "+f"(c[3])
        : "r"(a[0]), "r"(a[1]), "r"(a[2]), "r"(a[3]), "r"(b[0]), "r"(b[1]));
}
__device__ __forceinline__ void mma_f16(float c[4], const uint32_t a[4], const uint32_t b[2]) {
    asm volatile(
        "mma.sync.aligned.m16n8k16.row.col.f32.f16.f16.f32 "
        "{%0,%1,%2,%3}, {%4,%5,%6,%7}, {%8,%9}, {%0,%1,%2,%3};"
        : "+f"(c[0]), "+f"(c[1]), "+f"(c[2]), "+f"(c[3])
        : "r"(a[0]), "r"(a[1]), "r"(a[2]), "r"(a[3]), "r"(b[0]), "r"(b[1]));
}

// ---- shared geometry ----
#define AS_ELEMS (128 * 20)
#define BS_ELEMS (16 * 132)
#define NSTAGE 3
#define K1_SMEM (NSTAGE * (2 * AS_ELEMS + BS_ELEMS) * 4)
#define K2_SMEM (NSTAGE * (AS_ELEMS + BS_ELEMS) * 4)
// K3 fp16: 128x128 block tile, BK=32; tiles [128][40] halves (pad 8 -> 20-word stride)
#define A3H_ELEMS (128 * 40)
#define K3_SMEM (NSTAGE * 2 * A3H_ELEMS * 2)   // 61440 B

// ============================================================================
// K0: one-time tf32 split of Wq/Wk (tiny).
// ============================================================================
__global__ void k0_splitW(const float* __restrict__ Wq, const float* __restrict__ Wk)
{
    const int i = blockIdx.x * 256 + threadIdx.x;
    if (i >= MIDC * C_CH) return;
    uint32_t h, l;
    split_tf32(Wq[i], h, l);
    g_Whi[0][i] = __uint_as_float(h); g_Wlo[0][i] = __uint_as_float(l);
    split_tf32(Wk[i], h, l);
    g_Whi[1][i] = __uint_as_float(h); g_Wlo[1][i] = __uint_as_float(l);
}

// ============================================================================
// K0b: cam -> fp16 (elementwise, vectorized).
// ============================================================================
__global__ void k0_camh(const float* __restrict__ cam)
{
    const size_t i4 = (size_t)blockIdx.x * 256 + threadIdx.x;
    const size_t n4 = (size_t)BATCH * C_CH * N_SP / 4;
    if (i4 >= n4) return;
    float4 v = ((const float4*)cam)[i4];
    __half2 h0 = __floats2half2_rn(v.x, v.y);
    __half2 h1 = __floats2half2_rn(v.z, v.w);
    ((__half2*)g_camh)[i4 * 2]     = h0;
    ((__half2*)g_camh)[i4 * 2 + 1] = h1;
}

// ============================================================================
// K1: projections via 3xTF32 mma.sync. Wsel[128,2048] @ x[2048,1152].
//   mblk=0 -> q stored transposed g_q[b][n][m];  mblk=1 -> k stored g_k[b][m][n]
// ============================================================================
__global__ __launch_bounds__(256, 2) void k1_proj(const float* __restrict__ feat)
{
    const int nblk = blockIdx.x;          // 0..8
    const int mblk = blockIdx.y;          // 0..1
    const int b    = blockIdx.z;
    const float* Whi = g_Whi[mblk];
    const float* Wlo = g_Wlo[mblk];
    const float* X = feat + (size_t)b * C_CH * N_SP;

    extern __shared__ float smem[];
    float (*Ah)[128][20] = (float(*)[128][20])smem;
    float (*Al)[128][20] = (float(*)[128][20])(smem + NSTAGE * AS_ELEMS);
    float (*Bs)[16][132] = (float(*)[16][132])(smem + 2 * NSTAGE * AS_ELEMS);

    const int tid  = threadIdx.x;
    const int warp = tid >> 5, lane = tid & 31;
    const int wm = warp >> 2, wn = warp & 3;
    const int g = lane >> 2, tig = lane & 3;
    const int n0 = nblk * 128;

    float acc[4][4][4] = {};

    auto loadStage = [&](int kt, int buf) {
        const int k0 = kt * 16;
        #pragma unroll
        for (int it = 0; it < 2; it++) {
            int id  = tid + it * 256;
            int row = id >> 2;
            int c4  = (id & 3) * 4;
            cp_async16(&Ah[buf][row][c4], Whi + (size_t)row * C_CH + k0 + c4);
        }
        #pragma unroll
        for (int it = 0; it < 2; it++) {
            int id  = tid + it * 256;
            int row = id >> 2;
            int c4  = (id & 3) * 4;
            cp_async16(&Al[buf][row][c4], Wlo + (size_t)row * C_CH + k0 + c4);
        }
        #pragma unroll
        for (int it = 0; it < 2; it++) {
            int id  = tid + it * 256;
            int row = id >> 5;
            int c4  = (id & 31) * 4;
            cp_async16(&Bs[buf][row][c4], X + (size_t)(k0 + row) * N_SP + n0 + c4);
        }
    };

    const int KT = C_CH / 16;   // 128
    loadStage(0, 0); cp_commit();
    loadStage(1, 1); cp_commit();

    for (int kt = 0; kt < KT; kt++) {
        if (kt + 1 < KT) cp_wait<1>(); else cp_wait<0>();
        __syncthreads();
        const int buf = kt % 3;
        if (kt + 2 < KT) { loadStage(kt + 2, (kt + 2) % 3); cp_commit(); }

        #pragma unroll
        for (int ks = 0; ks < 2; ks++) {
            const int kb = ks * 8;
            uint32_t bhi[4][2], blo[4][2];
            #pragma unroll
            for (int fn = 0; fn < 4; fn++) {
                int jc = wn * 32 + fn * 8;
                split_tf32(Bs[buf][kb + tig    ][jc + g], bhi[fn][0], blo[fn][0]);
                split_tf32(Bs[buf][kb + tig + 4][jc + g], bhi[fn][1], blo[fn][1]);
            }
            #pragma unroll
            for (int fm = 0; fm < 4; fm++) {
                int mr = wm * 64 + fm * 16;
                uint32_t ahi[4], alo[4];
                ahi[0] = __float_as_uint(Ah[buf][mr + g    ][kb + tig    ]);
                ahi[1] = __float_as_uint(Ah[buf][mr + g + 8][kb + tig    ]);
                ahi[2] = __float_as_uint(Ah[buf][mr + g    ][kb + tig + 4]);
                ahi[3] = __float_as_uint(Ah[buf][mr + g + 8][kb + tig + 4]);
                alo[0] = __float_as_uint(Al[buf][mr + g    ][kb + tig    ]);
                alo[1] = __float_as_uint(Al[buf][mr + g + 8][kb + tig    ]);
                alo[2] = __float_as_uint(Al[buf][mr + g    ][kb + tig + 4]);
                alo[3] = __float_as_uint(Al[buf][mr + g + 8][kb + tig + 4]);
                #pragma unroll
                for (int fn = 0; fn < 4; fn++) {
                    mma_tf32(acc[fm][fn], ahi, bhi[fn]);
                    mma_tf32(acc[fm][fn], alo, bhi[fn]);
                    mma_tf32(acc[fm][fn], ahi, blo[fn]);
                }
            }
        }
    }

    if (mblk == 0) {
        float* q = g_q + (size_t)b * N_SP * MIDC;   // [n][m]
        #pragma unroll
        for (int fm = 0; fm < 4; fm++) {
            #pragma unroll
            for (int fn = 0; fn < 4; fn++) {
                int m   = wm * 64 + fm * 16 + g;
                int col = n0 + wn * 32 + fn * 8 + tig * 2;
                q[(size_t)(col    ) * MIDC + m    ] = acc[fm][fn][0];
                q[(size_t)(col + 1) * MIDC + m    ] = acc[fm][fn][1];
                q[(size_t)(col    ) * MIDC + m + 8] = acc[fm][fn][2];
                q[(size_t)(col + 1) * MIDC + m + 8] = acc[fm][fn][3];
            }
        }
    } else {
        float* kp = g_k + (size_t)b * MIDC * N_SP;  // [m][n]
        #pragma unroll
        for (int fm = 0; fm < 4; fm++) {
            #pragma unroll
            for (int fn = 0; fn < 4; fn++) {
                int m   = wm * 64 + fm * 16 + g;
                int col = n0 + wn * 32 + fn * 8 + tig * 2;
                *(float2*)(kp + (size_t)m * N_SP + col)       = make_float2(acc[fm][fn][0], acc[fm][fn][1]);
                *(float2*)(kp + (size_t)(m + 8) * N_SP + col) = make_float2(acc[fm][fn][2], acc[fm][fn][3]);
            }
        }
    }
}

// ============================================================================
// K2a: logits L[b][i][j] = sum_m q[b][i][m] * k[b][m][j]. 3xTF32, K=128.
// ============================================================================
__global__ __launch_bounds__(256, 2) void k2_logits()
{
    const int jblk = blockIdx.x;   // 0..8
    const int iblk = blockIdx.y;   // 0..8
    const int b    = blockIdx.z;
    const float* A = g_q + (size_t)b * N_SP * MIDC;    // [1152][128]
    const float* B = g_k + (size_t)b * MIDC * N_SP;    // [128][1152]
    float* L = g_attn + (size_t)b * N_SP * N_SP;

    extern __shared__ float smem[];
    float (*As)[128][20] = (float(*)[128][20])smem;
    float (*Bs)[16][132] = (float(*)[16][132])(smem + NSTAGE * AS_ELEMS);

    const int tid  = threadIdx.x;
    const int warp = tid >> 5, lane = tid & 31;
    const int wm = warp >> 2, wn = warp & 3;
    const int g = lane >> 2, tig = lane & 3;
    const int i0 = iblk * 128, j0 = jblk * 128;

    float acc[4][4][4] = {};

    auto loadStage = [&](int kt, int buf) {
        const int k0 = kt * 16;
        #pragma unroll
        for (int it = 0; it < 2; it++) {
            int id  = tid + it * 256;
            int row = id >> 2;
            int c4  = (id & 3) * 4;
            cp_async16(&As[buf][row][c4], A + (size_t)(i0 + row) * MIDC + k0 + c4);
        }
        #pragma unroll
        for (int it = 0; it < 2; it++) {
            int id  = tid + it * 256;
            int row = id >> 5;
            int c4  = (id & 31) * 4;
            cp_async16(&Bs[buf][row][c4], B + (size_t)(k0 + row) * N_SP + j0 + c4);
        }
    };

    const int KT = MIDC / 16;   // 8
    loadStage(0, 0); cp_commit();
    loadStage(1, 1); cp_commit();

    for (int kt = 0; kt < KT; kt++) {
        if (kt + 1 < KT) cp_wait<1>(); else cp_wait<0>();
        __syncthreads();
        const int buf = kt % 3;
        if (kt + 2 < KT) { loadStage(kt + 2, (kt + 2) % 3); cp_commit(); }

        #pragma unroll
        for (int ks = 0; ks < 2; ks++) {
            const int kb = ks * 8;
            uint32_t bhi[4][2], blo[4][2];
            #pragma unroll
            for (int fn = 0; fn < 4; fn++) {
                int jc = wn * 32 + fn * 8;
                split_tf32(Bs[buf][kb + tig    ][jc + g], bhi[fn][0], blo[fn][0]);
                split_tf32(Bs[buf][kb + tig + 4][jc + g], bhi[fn][1], blo[fn][1]);
            }
            #pragma unroll
            for (int fm = 0; fm < 4; fm++) {
                int mr = wm * 64 + fm * 16;
                uint32_t ahi[4], alo[4];
                split_tf32(As[buf][mr + g    ][kb + tig    ], ahi[0], alo[0]);
                split_tf32(As[buf][mr + g + 8][kb + tig    ], ahi[1], alo[1]);
                split_tf32(As[buf][mr + g    ][kb + tig + 4], ahi[2], alo[2]);
                split_tf32(As[buf][mr + g + 8][kb + tig + 4], ahi[3], alo[3]);
                #pragma unroll
                for (int fn = 0; fn < 4; fn++) {
                    mma_tf32(acc[fm][fn], ahi, bhi[fn]);
                    mma_tf32(acc[fm][fn], alo, bhi[fn]);
                    mma_tf32(acc[fm][fn], ahi, blo[fn]);
                }
            }
        }
    }

    #pragma unroll
    for (int fm = 0; fm < 4; fm++) {
        #pragma unroll
        for (int fn = 0; fn < 4; fn++) {
            int ii  = i0 + wm * 64 + fm * 16 + g;
            int col = j0 + wn * 32 + fn * 8 + tig * 2;
            *(float2*)(L + (size_t)ii * N_SP + col)       = make_float2(acc[fm][fn][0], acc[fm][fn][1]);
            *(float2*)(L + (size_t)(ii + 8) * N_SP + col) = make_float2(acc[fm][fn][2], acc[fm][fn][3]);
        }
    }
}

// ============================================================================
// K2b: row softmax (length 1152), one warp per row. Plain f32 store.
// ============================================================================
__global__ void k2_softmax()
{
    const int row  = blockIdx.x * 8 + (threadIdx.x >> 5);
    const int lane = threadIdx.x & 31;
    float* r = g_attn + (size_t)row * N_SP;

    float f[36];
    float mx = -1e30f;
    #pragma unroll
    for (int t = 0; t < 36; t++) {
        f[t] = r[lane + 32 * t];
        mx = fmaxf(mx, f[t]);
    }
    #pragma unroll
    for (int o = 16; o > 0; o >>= 1) mx = fmaxf(mx, __shfl_xor_sync(0xffffffffu, mx, o));

    float s = 0.0f;
    #pragma unroll
    for (int t = 0; t < 36; t++) {
        f[t] = __expf(f[t] - mx);
        s += f[t];
    }
    #pragma unroll
    for (int o = 16; o > 0; o >>= 1) s += __shfl_xor_sync(0xffffffffu, s, o);

    const float inv = 1.0f / s;
    #pragma unroll
    for (int t = 0; t < 36; t++)
        r[lane + 32 * t] = f[t] * inv;
}

// ============================================================================
// K2t: transpose + fp16: g_attnT[b][j][i] = (half)g_attn[b][i][j].
// 32x32 tiles, 256 threads (8 rows/pass, 4 passes each way).
// ============================================================================
__global__ void k2t_transpose()
{
    __shared__ float tile[32][33];
    const int i0 = blockIdx.x * 32;
    const int j0 = blockIdx.y * 32;
    const int b  = blockIdx.z;
    const float* src = g_attn  + (size_t)b * N_SP * N_SP;
    __half*      dst = g_attnT + (size_t)b * N_SP * N_SP;

    const int r = threadIdx.x >> 5;     // 0..7
    const int c = threadIdx.x & 31;

    #pragma unroll
    for (int w = 0; w < 4; w++)
        tile[r + w * 8][c] = src[(size_t)(i0 + r + w * 8) * N_SP + j0 + c];
    __syncthreads();
    #pragma unroll
    for (int w = 0; w < 4; w++)
        dst[(size_t)(j0 + r + w * 8) * N_SP + i0 + c] = __float2half_rn(tile[c][r + w * 8]);
}

// ============================================================================
// K3: refined = cam @ attn via FP16 mma m16n8k16.
// D[c][j] = sum_i camh[c][i] * attnT[j][i]. Block 128x128, 4 warps (2x2) of
// 64x64, BK=32 (2 k16-substeps), 3-stage cp.async. Residual reads f32 cam.
// ============================================================================
__global__ __launch_bounds__(128, 2) void k3_refined(
    const float* __restrict__ cam,
    const float* __restrict__ alphaPtr,
    float* __restrict__ out)
{
    const int jblk = blockIdx.x;   // 0..8
    const int cblk = blockIdx.y;   // 0..15
    const int b    = blockIdx.z;

    const __half* Ah = g_camh  + (size_t)b * C_CH * N_SP;   // [2048][1152]
    const __half* Bh = g_attnT + (size_t)b * N_SP * N_SP;   // [1152][1152] (j rows, i cols)
    const float*  Af = cam     + (size_t)b * C_CH * N_SP;

    extern __shared__ __half smemh[];
    __half (*As)[128][40] = (__half(*)[128][40])smemh;                       // [c][k]
    __half (*Bs)[128][40] = (__half(*)[128][40])(smemh + NSTAGE * A3H_ELEMS); // [j][k]

    const int tid  = threadIdx.x;
    const int warp = tid >> 5, lane = tid & 31;
    const int wm = warp >> 1, wn = warp & 1;   // 2 x 2 warps, 64x64 each
    const int g = lane >> 2, tig = lane & 3;
    const int c0 = cblk * 128, j0 = jblk * 128;

    float acc[4][8][4] = {};

    auto loadStage = [&](int kt, int buf) {
        const int k0 = kt * 32;
        #pragma unroll
        for (int it = 0; it < 4; it++) {              // A: 128 rows x 32 halves = 512 x 16B
            int id  = tid + it * 128;
            int row = id >> 2;
            int ch  = (id & 3) * 8;
            cp_async16(&As[buf][row][ch], Ah + (size_t)(c0 + row) * N_SP + k0 + ch);
        }
        #pragma unroll
        for (int it = 0; it < 4; it++) {              // B: 128 rows x 32 halves
            int id  = tid + it * 128;
            int row = id >> 2;
            int ch  = (id & 3) * 8;
            cp_async16(&Bs[buf][row][ch], Bh + (size_t)(j0 + row) * N_SP + k0 + ch);
        }
    };

    const int KT = N_SP / 32;   // 36
    loadStage(0, 0); cp_commit();
    loadStage(1, 1); cp_commit();

    for (int kt = 0; kt < KT; kt++) {
        if (kt + 1 < KT) cp_wait<1>(); else cp_wait<0>();
        __syncthreads();
        const int buf = kt % 3;
        if (kt + 2 < KT) { loadStage(kt + 2, (kt + 2) % 3); cp_commit(); }

        #pragma unroll
        for (int ks = 0; ks < 2; ks++) {
            const int kb = ks * 16;
            uint32_t bfr[8][2];
            #pragma unroll
            for (int fn = 0; fn < 8; fn++) {
                int jc = wn * 64 + fn * 8;
                bfr[fn][0] = *(const uint32_t*)&Bs[buf][jc + g][kb + 2 * tig];
                bfr[fn][1] = *(const uint32_t*)&Bs[buf][jc + g][kb + 2 * tig + 8];
            }
            #pragma unroll
            for (int fm = 0; fm < 4; fm++) {
                int mr = wm * 64 + fm * 16;
                uint32_t afr[4];
                afr[0] = *(const uint32_t*)&As[buf][mr + g    ][kb + 2 * tig    ];
                afr[1] = *(const uint32_t*)&As[buf][mr + g + 8][kb + 2 * tig    ];
                afr[2] = *(const uint32_t*)&As[buf][mr + g    ][kb + 2 * tig + 8];
                afr[3] = *(const uint32_t*)&As[buf][mr + g + 8][kb + 2 * tig + 8];
                #pragma unroll
                for (int fn = 0; fn < 8; fn++)
                    mma_f16(acc[fm][fn], afr, bfr[fn]);
            }
        }
    }

    const float alpha = alphaPtr[0];
    const size_t base = (size_t)b * C_CH * N_SP;
    #pragma unroll
    for (int fm = 0; fm < 4; fm++) {
        #pragma unroll
        for (int fn = 0; fn < 8; fn++) {
            int mrow = c0 + wm * 64 + fm * 16 + g;
            int col  = j0 + wn * 64 + fn * 8 + tig * 2;
            const float2 cv0 = *(const float2*)(Af + (size_t)mrow * N_SP + col);
            const float2 cv1 = *(const float2*)(Af + (size_t)(mrow + 8) * N_SP + col);
            float2 r0, r1;
            r0.x = fmaf(alpha, acc[fm][fn][0], cv0.x);
            r0.y = fmaf(alpha, acc[fm][fn][1], cv0.y);
            r1.x = fmaf(alpha, acc[fm][fn][2], cv1.x);
            r1.y = fmaf(alpha, acc[fm][fn][3], cv1.y);
            *(float2*)(out + base + (size_t)mrow * N_SP + col)       = r0;
            *(float2*)(out + base + (size_t)(mrow + 8) * N_SP + col) = r1;
        }
    }
}

// ============================================================================
extern "C" void kernel_launch(void* const* d_in, const int* in_sizes, int n_in,
                              void* d_out, int out_size)
{
    (void)in_sizes; (void)n_in; (void)out_size;
    const float* feat  = (const float*)d_in[0];
    const float* cam   = (const float*)d_in[1];
    const float* Wq    = (const float*)d_in[2];
    const float* Wk    = (const float*)d_in[3];
    const float* alpha = (const float*)d_in[4];
    float* out = (float*)d_out;

    cudaFuncSetAttribute(k1_proj,    cudaFuncAttributeMaxDynamicSharedMemorySize, K1_SMEM);
    cudaFuncSetAttribute(k2_logits,  cudaFuncAttributeMaxDynamicSharedMemorySize, K2_SMEM);
    cudaFuncSetAttribute(k3_refined, cudaFuncAttributeMaxDynamicSharedMemorySize, K3_SMEM);

    k0_splitW<<<(MIDC * C_CH + 255) / 256, 256>>>(Wq, Wk);
    k0_camh<<<(int)(((size_t)BATCH * C_CH * N_SP / 4 + 255) / 256), 256>>>(cam);
    k1_proj<<<dim3(9, 2, BATCH), 256, K1_SMEM>>>(feat);
    k2_logits<<<dim3(9, 9, BATCH), 256, K2_SMEM>>>();
    k2_softmax<<<(BATCH * N_SP) / 8, 256>>>();
    k2t_transpose<<<dim3(36, 36, BATCH), 256>>>();
    k3_refined<<<dim3(9, 16, BATCH), 128, K3_SMEM>>>(cam, alpha, out);
}

// round 7
// speedup vs baseline: 1.3433x; 1.0731x over previous
#include <cuda_runtime.h>
#include <cuda_fp16.h>
#include <cstdint>
#include <cstddef>

#define BATCH 32
#define C_CH  2048
#define N_SP  1152   // 48*24
#define MIDC  128

// ---------------- scratch (device globals; no allocation allowed) ----------------
__device__ __align__(128) float  g_q[(size_t)BATCH * N_SP * MIDC];       // [b][n][m]
__device__ __align__(128) float  g_k[(size_t)BATCH * MIDC * N_SP];       // [b][m][n]
__device__ __align__(128) float  g_attn[(size_t)BATCH * N_SP * N_SP];    // logits [b][i][j] f32
__device__ __align__(128) __half g_attn16[(size_t)BATCH * N_SP * N_SP];  // softmax [b][i][j] fp16
__device__ __align__(128) __half g_attnT[(size_t)BATCH * N_SP * N_SP];   // [b][j][i] fp16
__device__ __align__(128) __half g_camh[(size_t)BATCH * C_CH * N_SP];    // cam fp16
__device__ __align__(128) float  g_Whi[2][(size_t)MIDC * C_CH];          // tf32 hi of Wq/Wk
__device__ __align__(128) float  g_Wlo[2][(size_t)MIDC * C_CH];          // tf32 lo

// ---------------- helpers ----------------
__device__ __forceinline__ uint32_t f32_to_tf32(float x) {
    uint32_t r;
    asm("cvt.rna.tf32.f32 %0, %1;" : "=r"(r) : "f"(x));
    return r;
}
__device__ __forceinline__ void split_tf32(float x, uint32_t& hi, uint32_t& lo) {
    hi = f32_to_tf32(x);
    lo = f32_to_tf32(x - __uint_as_float(hi));
}
__device__ __forceinline__ void cp_async16(void* smem, const void* gmem) {
    uint32_t s = (uint32_t)__cvta_generic_to_shared(smem);
    asm volatile("cp.async.cg.shared.global [%0], [%1], 16;" :: "r"(s), "l"(gmem));
}
__device__ __forceinline__ void cp_commit() {
    asm volatile("cp.async.commit_group;" ::: "memory");
}
template <int NN>
__device__ __forceinline__ void cp_wait() {
    asm volatile("cp.async.wait_group %0;" :: "n"(NN) : "memory");
}
__device__ __forceinline__ void mma_tf32(float c[4], const uint32_t a[4], const uint32_t b[2]) {
    asm volatile(
        "mma.sync.aligned.m16n8k8.row.col.f32.tf32.tf32.f32 "
        "{%0,%1,%2,%3}, {%4,%5,%6,%7}, {%8,%9}, {%0,%1,%2,%3};"
        : "+f"(c[0]), "+f"(c[1]), "+f"(c[2]), "+f"(c[3])
        : "r"(a[0]), "r"(a[1]), "r"(a[2]), "r"(a[3]), "r"(b[0]), "r"(b[1]));
}
__device__ __forceinline__ void mma_f16(float c[4], const uint32_t a[4], const uint32_t b[2]) {
    asm volatile(
        "mma.sync.aligned.m16n8k16.row.col.f32.f16.f16.f32 "
        "{%0,%1,%2,%3}, {%4,%5,%6,%7}, {%8,%9}, {%0,%1,%2,%3};"
        : "+f"(c[0]), "+f"(c[1]), "+f"(c[2]), "+f"(c[3])
        : "r"(a[0]), "r"(a[1]), "r"(a[2]), "r"(a[3]), "r"(b[0]), "r"(b[1]));
}
__device__ __forceinline__ void ldsm_x4(uint32_t& r0, uint32_t& r1, uint32_t& r2, uint32_t& r3,
                                        uint32_t saddr) {
    asm volatile("ldmatrix.sync.aligned.m8n8.x4.shared.b16 {%0,%1,%2,%3}, [%4];"
                 : "=r"(r0), "=r"(r1), "=r"(r2), "=r"(r3) : "r"(saddr));
}

// ---- shared geometry ----
#define AS_ELEMS (128 * 20)
#define BS_ELEMS (16 * 132)
#define NSTAGE 3
#define K1_SMEM (NSTAGE * (2 * AS_ELEMS + BS_ELEMS) * 4)
#define K2_SMEM (NSTAGE * (AS_ELEMS + BS_ELEMS) * 4)
// K3 fp16: 128x128 block tile, BK=32, 4 stages; tile [128][40] halves
#define K3_NS 4
#define A3H_ELEMS (128 * 40)
#define A3H_BYTES (A3H_ELEMS * 2)          // 10240
#define K3_SMEM (K3_NS * 2 * A3H_BYTES)    // 81920

// ============================================================================
// K0: one-time tf32 split of Wq/Wk (tiny).
// ============================================================================
__global__ void k0_splitW(const float* __restrict__ Wq, const float* __restrict__ Wk)
{
    const int i = blockIdx.x * 256 + threadIdx.x;
    if (i >= MIDC * C_CH) return;
    uint32_t h, l;
    split_tf32(Wq[i], h, l);
    g_Whi[0][i] = __uint_as_float(h); g_Wlo[0][i] = __uint_as_float(l);
    split_tf32(Wk[i], h, l);
    g_Whi[1][i] = __uint_as_float(h); g_Wlo[1][i] = __uint_as_float(l);
}

// ============================================================================
// K0b: cam -> fp16 (elementwise, vectorized).
// ============================================================================
__global__ void k0_camh(const float* __restrict__ cam)
{
    const size_t i4 = (size_t)blockIdx.x * 256 + threadIdx.x;
    const size_t n4 = (size_t)BATCH * C_CH * N_SP / 4;
    if (i4 >= n4) return;
    float4 v = ((const float4*)cam)[i4];
    ((__half2*)g_camh)[i4 * 2]     = __floats2half2_rn(v.x, v.y);
    ((__half2*)g_camh)[i4 * 2 + 1] = __floats2half2_rn(v.z, v.w);
}

// ============================================================================
// K1: projections via 3xTF32 mma.sync. Wsel[128,2048] @ x[2048,1152].
//   mblk=0 -> q stored transposed g_q[b][n][m];  mblk=1 -> k stored g_k[b][m][n]
// ============================================================================
__global__ __launch_bounds__(256, 2) void k1_proj(const float* __restrict__ feat)
{
    const int nblk = blockIdx.x;          // 0..8
    const int mblk = blockIdx.y;          // 0..1
    const int b    = blockIdx.z;
    const float* Whi = g_Whi[mblk];
    const float* Wlo = g_Wlo[mblk];
    const float* X = feat + (size_t)b * C_CH * N_SP;

    extern __shared__ float smem[];
    float (*Ah)[128][20] = (float(*)[128][20])smem;
    float (*Al)[128][20] = (float(*)[128][20])(smem + NSTAGE * AS_ELEMS);
    float (*Bs)[16][132] = (float(*)[16][132])(smem + 2 * NSTAGE * AS_ELEMS);

    const int tid  = threadIdx.x;
    const int warp = tid >> 5, lane = tid & 31;
    const int wm = warp >> 2, wn = warp & 3;
    const int g = lane >> 2, tig = lane & 3;
    const int n0 = nblk * 128;

    float acc[4][4][4] = {};

    auto loadStage = [&](int kt, int buf) {
        const int k0 = kt * 16;
        #pragma unroll
        for (int it = 0; it < 2; it++) {
            int id  = tid + it * 256;
            int row = id >> 2;
            int c4  = (id & 3) * 4;
            cp_async16(&Ah[buf][row][c4], Whi + (size_t)row * C_CH + k0 + c4);
        }
        #pragma unroll
        for (int it = 0; it < 2; it++) {
            int id  = tid + it * 256;
            int row = id >> 2;
            int c4  = (id & 3) * 4;
            cp_async16(&Al[buf][row][c4], Wlo + (size_t)row * C_CH + k0 + c4);
        }
        #pragma unroll
        for (int it = 0; it < 2; it++) {
            int id  = tid + it * 256;
            int row = id >> 5;
            int c4  = (id & 31) * 4;
            cp_async16(&Bs[buf][row][c4], X + (size_t)(k0 + row) * N_SP + n0 + c4);
        }
    };

    const int KT = C_CH / 16;   // 128
    loadStage(0, 0); cp_commit();
    loadStage(1, 1); cp_commit();

    for (int kt = 0; kt < KT; kt++) {
        if (kt + 1 < KT) cp_wait<1>(); else cp_wait<0>();
        __syncthreads();
        const int buf = kt % 3;
        if (kt + 2 < KT) { loadStage(kt + 2, (kt + 2) % 3); cp_commit(); }

        #pragma unroll
        for (int ks = 0; ks < 2; ks++) {
            const int kb = ks * 8;
            uint32_t bhi[4][2], blo[4][2];
            #pragma unroll
            for (int fn = 0; fn < 4; fn++) {
                int jc = wn * 32 + fn * 8;
                split_tf32(Bs[buf][kb + tig    ][jc + g], bhi[fn][0], blo[fn][0]);
                split_tf32(Bs[buf][kb + tig + 4][jc + g], bhi[fn][1], blo[fn][1]);
            }
            #pragma unroll
            for (int fm = 0; fm < 4; fm++) {
                int mr = wm * 64 + fm * 16;
                uint32_t ahi[4], alo[4];
                ahi[0] = __float_as_uint(Ah[buf][mr + g    ][kb + tig    ]);
                ahi[1] = __float_as_uint(Ah[buf][mr + g + 8][kb + tig    ]);
                ahi[2] = __float_as_uint(Ah[buf][mr + g    ][kb + tig + 4]);
                ahi[3] = __float_as_uint(Ah[buf][mr + g + 8][kb + tig + 4]);
                alo[0] = __float_as_uint(Al[buf][mr + g    ][kb + tig    ]);
                alo[1] = __float_as_uint(Al[buf][mr + g + 8][kb + tig    ]);
                alo[2] = __float_as_uint(Al[buf][mr + g    ][kb + tig + 4]);
                alo[3] = __float_as_uint(Al[buf][mr + g + 8][kb + tig + 4]);
                #pragma unroll
                for (int fn = 0; fn < 4; fn++) {
                    mma_tf32(acc[fm][fn], ahi, bhi[fn]);
                    mma_tf32(acc[fm][fn], alo, bhi[fn]);
                    mma_tf32(acc[fm][fn], ahi, blo[fn]);
                }
            }
        }
    }

    if (mblk == 0) {
        float* q = g_q + (size_t)b * N_SP * MIDC;   // [n][m]
        #pragma unroll
        for (int fm = 0; fm < 4; fm++) {
            #pragma unroll
            for (int fn = 0; fn < 4; fn++) {
                int m   = wm * 64 + fm * 16 + g;
                int col = n0 + wn * 32 + fn * 8 + tig * 2;
                q[(size_t)(col    ) * MIDC + m    ] = acc[fm][fn][0];
                q[(size_t)(col + 1) * MIDC + m    ] = acc[fm][fn][1];
                q[(size_t)(col    ) * MIDC + m + 8] = acc[fm][fn][2];
                q[(size_t)(col + 1) * MIDC + m + 8] = acc[fm][fn][3];
            }
        }
    } else {
        float* kp = g_k + (size_t)b * MIDC * N_SP;  // [m][n]
        #pragma unroll
        for (int fm = 0; fm < 4; fm++) {
            #pragma unroll
            for (int fn = 0; fn < 4; fn++) {
                int m   = wm * 64 + fm * 16 + g;
                int col = n0 + wn * 32 + fn * 8 + tig * 2;
                *(float2*)(kp + (size_t)m * N_SP + col)       = make_float2(acc[fm][fn][0], acc[fm][fn][1]);
                *(float2*)(kp + (size_t)(m + 8) * N_SP + col) = make_float2(acc[fm][fn][2], acc[fm][fn][3]);
            }
        }
    }
}

// ============================================================================
// K2a: logits L[b][i][j] = sum_m q[b][i][m] * k[b][m][j]. 3xTF32, K=128.
// ============================================================================
__global__ __launch_bounds__(256, 2) void k2_logits()
{
    const int jblk = blockIdx.x;   // 0..8
    const int iblk = blockIdx.y;   // 0..8
    const int b    = blockIdx.z;
    const float* A = g_q + (size_t)b * N_SP * MIDC;    // [1152][128]
    const float* B = g_k + (size_t)b * MIDC * N_SP;    // [128][1152]
    float* L = g_attn + (size_t)b * N_SP * N_SP;

    extern __shared__ float smem[];
    float (*As)[128][20] = (float(*)[128][20])smem;
    float (*Bs)[16][132] = (float(*)[16][132])(smem + NSTAGE * AS_ELEMS);

    const int tid  = threadIdx.x;
    const int warp = tid >> 5, lane = tid & 31;
    const int wm = warp >> 2, wn = warp & 3;
    const int g = lane >> 2, tig = lane & 3;
    const int i0 = iblk * 128, j0 = jblk * 128;

    float acc[4][4][4] = {};

    auto loadStage = [&](int kt, int buf) {
        const int k0 = kt * 16;
        #pragma unroll
        for (int it = 0; it < 2; it++) {
            int id  = tid + it * 256;
            int row = id >> 2;
            int c4  = (id & 3) * 4;
            cp_async16(&As[buf][row][c4], A + (size_t)(i0 + row) * MIDC + k0 + c4);
        }
        #pragma unroll
        for (int it = 0; it < 2; it++) {
            int id  = tid + it * 256;
            int row = id >> 5;
            int c4  = (id & 31) * 4;
            cp_async16(&Bs[buf][row][c4], B + (size_t)(k0 + row) * N_SP + j0 + c4);
        }
    };

    const int KT = MIDC / 16;   // 8
    loadStage(0, 0); cp_commit();
    loadStage(1, 1); cp_commit();

    for (int kt = 0; kt < KT; kt++) {
        if (kt + 1 < KT) cp_wait<1>(); else cp_wait<0>();
        __syncthreads();
        const int buf = kt % 3;
        if (kt + 2 < KT) { loadStage(kt + 2, (kt + 2) % 3); cp_commit(); }

        #pragma unroll
        for (int ks = 0; ks < 2; ks++) {
            const int kb = ks * 8;
            uint32_t bhi[4][2], blo[4][2];
            #pragma unroll
            for (int fn = 0; fn < 4; fn++) {
                int jc = wn * 32 + fn * 8;
                split_tf32(Bs[buf][kb + tig    ][jc + g], bhi[fn][0], blo[fn][0]);
                split_tf32(Bs[buf][kb + tig + 4][jc + g], bhi[fn][1], blo[fn][1]);
            }
            #pragma unroll
            for (int fm = 0; fm < 4; fm++) {
                int mr = wm * 64 + fm * 16;
                uint32_t ahi[4], alo[4];
                split_tf32(As[buf][mr + g    ][kb + tig    ], ahi[0], alo[0]);
                split_tf32(As[buf][mr + g + 8][kb + tig    ], ahi[1], alo[1]);
                split_tf32(As[buf][mr + g    ][kb + tig + 4], ahi[2], alo[2]);
                split_tf32(As[buf][mr + g + 8][kb + tig + 4], ahi[3], alo[3]);
                #pragma unroll
                for (int fn = 0; fn < 4; fn++) {
                    mma_tf32(acc[fm][fn], ahi, bhi[fn]);
                    mma_tf32(acc[fm][fn], alo, bhi[fn]);
                    mma_tf32(acc[fm][fn], ahi, blo[fn]);
                }
            }
        }
    }

    #pragma unroll
    for (int fm = 0; fm < 4; fm++) {
        #pragma unroll
        for (int fn = 0; fn < 4; fn++) {
            int ii  = i0 + wm * 64 + fm * 16 + g;
            int col = j0 + wn * 32 + fn * 8 + tig * 2;
            *(float2*)(L + (size_t)ii * N_SP + col)       = make_float2(acc[fm][fn][0], acc[fm][fn][1]);
            *(float2*)(L + (size_t)(ii + 8) * N_SP + col) = make_float2(acc[fm][fn][2], acc[fm][fn][3]);
        }
    }
}

// ============================================================================
// K2b: row softmax (length 1152), one warp per row. f32 in, fp16 out.
// ============================================================================
__global__ void k2_softmax()
{
    const int row  = blockIdx.x * 8 + (threadIdx.x >> 5);
    const int lane = threadIdx.x & 31;
    const float* r = g_attn   + (size_t)row * N_SP;
    __half*     r16 = g_attn16 + (size_t)row * N_SP;

    float f[36];
    float mx = -1e30f;
    #pragma unroll
    for (int t = 0; t < 36; t++) {
        f[t] = r[lane + 32 * t];
        mx = fmaxf(mx, f[t]);
    }
    #pragma unroll
    for (int o = 16; o > 0; o >>= 1) mx = fmaxf(mx, __shfl_xor_sync(0xffffffffu, mx, o));

    float s = 0.0f;
    #pragma unroll
    for (int t = 0; t < 36; t++) {
        f[t] = __expf(f[t] - mx);
        s += f[t];
    }
    #pragma unroll
    for (int o = 16; o > 0; o >>= 1) s += __shfl_xor_sync(0xffffffffu, s, o);

    const float inv = 1.0f / s;
    #pragma unroll
    for (int t = 0; t < 36; t++)
        r16[lane + 32 * t] = __float2half_rn(f[t] * inv);
}

// ============================================================================
// K2t: fp16 transpose: g_attnT[b][j][i] = g_attn16[b][i][j]. 64x64 tiles.
// ============================================================================
__global__ void k2t_transpose()
{
    __shared__ __half tile[64][65];
    const int i0 = blockIdx.x * 64;
    const int j0 = blockIdx.y * 64;
    const int b  = blockIdx.z;
    const __half* src = g_attn16 + (size_t)b * N_SP * N_SP;
    __half*       dst = g_attnT  + (size_t)b * N_SP * N_SP;

    const int r = threadIdx.x >> 5;     // 0..7
    const int c2 = (threadIdx.x & 31) * 2;

    #pragma unroll
    for (int w = 0; w < 8; w++) {
        __half2 v = *(const __half2*)(src + (size_t)(i0 + r + w * 8) * N_SP + j0 + c2);
        tile[r + w * 8][c2]     = __low2half(v);
        tile[r + w * 8][c2 + 1] = __high2half(v);
    }
    __syncthreads();
    #pragma unroll
    for (int w = 0; w < 8; w++) {
        __half2 v = __halves2half2(tile[c2][r + w * 8], tile[c2 + 1][r + w * 8]);
        *(__half2*)(dst + (size_t)(j0 + r + w * 8) * N_SP + i0 + c2) = v;
    }
}

// ============================================================================
// K3: refined = cam @ attn via FP16 mma m16n8k16 + ldmatrix.x4.
// Block 128x128, 4 warps (2x2) of 64x64, BK=32, 4-stage cp.async.
// ============================================================================
__global__ __launch_bounds__(128, 2) void k3_refined(
    const float* __restrict__ cam,
    const float* __restrict__ alphaPtr,
    float* __restrict__ out)
{
    const int jblk = blockIdx.x;   // 0..8
    const int cblk = blockIdx.y;   // 0..15
    const int b    = blockIdx.z;

    const __half* Ahg = g_camh  + (size_t)b * C_CH * N_SP;   // [2048][1152]
    const __half* Bhg = g_attnT + (size_t)b * N_SP * N_SP;   // [1152][1152] (j rows, i cols)
    const float*  Af  = cam     + (size_t)b * C_CH * N_SP;

    extern __shared__ __half smemh[];
    const uint32_t sbase = (uint32_t)__cvta_generic_to_shared(smemh);
    __half (*As)[128][40] = (__half(*)[128][40])smemh;                           // [c][k]
    __half (*Bs)[128][40] = (__half(*)[128][40])(smemh + K3_NS * A3H_ELEMS);     // [j][k]
    const uint32_t aB = sbase;
    const uint32_t bB = sbase + K3_NS * A3H_BYTES;

    const int tid  = threadIdx.x;
    const int warp = tid >> 5, lane = tid & 31;
    const int wm = warp >> 1, wn = warp & 1;   // 2 x 2 warps, 64x64 each
    const int g = lane >> 2, tig = lane & 3;
    const int c0 = cblk * 128, j0 = jblk * 128;

    // ldmatrix lane-address components
    const uint32_t aRow = lane & 15;                    // row within 16
    const uint32_t aCol = (lane >> 4) << 3;             // 0 or 8 (k offset)
    const uint32_t bRow = (lane & 7) + ((lane >> 4) << 3);   // row within fn-pair block
    const uint32_t bCol = ((lane >> 3) & 1) << 3;            // 0 or 8

    float acc[4][8][4] = {};

    auto loadStage = [&](int kt, int buf) {
        const int k0 = kt * 32;
        #pragma unroll
        for (int it = 0; it < 4; it++) {              // A: 128 rows x 32 halves
            int id  = tid + it * 128;
            int row = id >> 2;
            int ch  = (id & 3) * 8;
            cp_async16(&As[buf][row][ch], Ahg + (size_t)(c0 + row) * N_SP + k0 + ch);
        }
        #pragma unroll
        for (int it = 0; it < 4; it++) {              // B: 128 rows x 32 halves
            int id  = tid + it * 128;
            int row = id >> 2;
            int ch  = (id & 3) * 8;
            cp_async16(&Bs[buf][row][ch], Bhg + (size_t)(j0 + row) * N_SP + k0 + ch);
        }
    };

    const int KT = N_SP / 32;   // 36
    loadStage(0, 0); cp_commit();
    loadStage(1, 1); cp_commit();
    loadStage(2, 2); cp_commit();

    for (int kt = 0; kt < KT; kt++) {
        if (kt < KT - 2) cp_wait<2>(); else if (kt == KT - 2) cp_wait<1>(); else cp_wait<0>();
        __syncthreads();
        const int buf = kt % K3_NS;
        if (kt + 3 < KT) { loadStage(kt + 3, (kt + 3) % K3_NS); cp_commit(); }

        const uint32_t aStage = aB + buf * A3H_BYTES;
        const uint32_t bStage = bB + buf * A3H_BYTES;

        #pragma unroll
        for (int ks = 0; ks < 2; ks++) {
            const int kb = ks * 16;
            uint32_t bfr[8][2];
            #pragma unroll
            for (int fnp = 0; fnp < 4; fnp++) {
                uint32_t addr = bStage +
                    ((wn * 64 + fnp * 16 + bRow) * 40 + kb + bCol) * 2;
                ldsm_x4(bfr[fnp * 2][0], bfr[fnp * 2][1],
                        bfr[fnp * 2 + 1][0], bfr[fnp * 2 + 1][1], addr);
            }
            #pragma unroll
            for (int fm = 0; fm < 4; fm++) {
                uint32_t addr = aStage +
                    ((wm * 64 + fm * 16 + aRow) * 40 + kb + aCol) * 2;
                uint32_t afr[4];
                ldsm_x4(afr[0], afr[1], afr[2], afr[3], addr);
                #pragma unroll
                for (int fn = 0; fn < 8; fn++)
                    mma_f16(acc[fm][fn], afr, bfr[fn]);
            }
        }
    }

    const float alpha = alphaPtr[0];
    const size_t base = (size_t)b * C_CH * N_SP;
    #pragma unroll
    for (int fm = 0; fm < 4; fm++) {
        #pragma unroll
        for (int fn = 0; fn < 8; fn++) {
            int mrow = c0 + wm * 64 + fm * 16 + g;
            int col  = j0 + wn * 64 + fn * 8 + tig * 2;
            const float2 cv0 = *(const float2*)(Af + (size_t)mrow * N_SP + col);
            const float2 cv1 = *(const float2*)(Af + (size_t)(mrow + 8) * N_SP + col);
            float2 r0, r1;
            r0.x = fmaf(alpha, acc[fm][fn][0], cv0.x);
            r0.y = fmaf(alpha, acc[fm][fn][1], cv0.y);
            r1.x = fmaf(alpha, acc[fm][fn][2], cv1.x);
            r1.y = fmaf(alpha, acc[fm][fn][3], cv1.y);
            *(float2*)(out + base + (size_t)mrow * N_SP + col)       = r0;
            *(float2*)(out + base + (size_t)(mrow + 8) * N_SP + col) = r1;
        }
    }
}

// ============================================================================
extern "C" void kernel_launch(void* const* d_in, const int* in_sizes, int n_in,
                              void* d_out, int out_size)
{
    (void)in_sizes; (void)n_in; (void)out_size;
    const float* feat  = (const float*)d_in[0];
    const float* cam   = (const float*)d_in[1];
    const float* Wq    = (const float*)d_in[2];
    const float* Wk    = (const float*)d_in[3];
    const float* alpha = (const float*)d_in[4];
    float* out = (float*)d_out;

    cudaFuncSetAttribute(k1_proj,    cudaFuncAttributeMaxDynamicSharedMemorySize, K1_SMEM);
    cudaFuncSetAttribute(k2_logits,  cudaFuncAttributeMaxDynamicSharedMemorySize, K2_SMEM);
    cudaFuncSetAttribute(k3_refined, cudaFuncAttributeMaxDynamicSharedMemorySize, K3_SMEM);

    k0_splitW<<<(MIDC * C_CH + 255) / 256, 256>>>(Wq, Wk);
    k0_camh<<<(int)(((size_t)BATCH * C_CH * N_SP / 4 + 255) / 256), 256>>>(cam);
    k1_proj<<<dim3(9, 2, BATCH), 256, K1_SMEM>>>(feat);
    k2_logits<<<dim3(9, 9, BATCH), 256, K2_SMEM>>>();
    k2_softmax<<<(BATCH * N_SP) / 8, 256>>>();
    k2t_transpose<<<dim3(18, 18, BATCH), 256>>>();
    k3_refined<<<dim3(9, 16, BATCH), 128, K3_SMEM>>>(cam, alpha, out);
}

// round 8
// speedup vs baseline: 1.7387x; 1.2943x over previous
#include <cuda_runtime.h>
#include <cuda_fp16.h>
#include <cstdint>
#include <cstddef>

#define BATCH 32
#define C_CH  2048
#define N_SP  1152   // 48*24
#define MIDC  128

// ---------------- scratch (device globals; no allocation allowed) ----------------
__device__ __align__(128) float  g_attn[(size_t)BATCH * N_SP * N_SP];    // logits [b][i][j] f32
__device__ __align__(128) __half g_attn16[(size_t)BATCH * N_SP * N_SP];  // softmax [b][i][j] fp16
__device__ __align__(128) __half g_attnT[(size_t)BATCH * N_SP * N_SP];   // [b][j][i] fp16
__device__ __align__(128) __half g_camh[(size_t)BATCH * C_CH * N_SP];    // cam fp16
__device__ __align__(128) __half g_Wh[2][(size_t)MIDC * C_CH];           // fp16 hi of 2^13*W
__device__ __align__(128) __half g_Wl[2][(size_t)MIDC * C_CH];           // fp16 lo
__device__ __align__(128) __half g_xTh[(size_t)BATCH * N_SP * C_CH];     // featT hi [b][n][k]
__device__ __align__(128) __half g_xTl[(size_t)BATCH * N_SP * C_CH];     // featT lo
__device__ __align__(128) __half g_qh[(size_t)BATCH * N_SP * MIDC];      // split(2^6 q) [n][m]
__device__ __align__(128) __half g_ql[(size_t)BATCH * N_SP * MIDC];
__device__ __align__(128) __half g_kh[(size_t)BATCH * N_SP * MIDC];      // split(2^6 k) [n][m]
__device__ __align__(128) __half g_kl[(size_t)BATCH * N_SP * MIDC];

// ---------------- helpers ----------------
__device__ __forceinline__ void split_h16(float x, __half& h, __half& l) {
    h = __float2half_rn(x);
    l = __float2half_rn(x - __half2float(h));
}
__device__ __forceinline__ void cp_async16(void* smem, const void* gmem) {
    uint32_t s = (uint32_t)__cvta_generic_to_shared(smem);
    asm volatile("cp.async.cg.shared.global [%0], [%1], 16;" :: "r"(s), "l"(gmem));
}
__device__ __forceinline__ void cp_commit() {
    asm volatile("cp.async.commit_group;" ::: "memory");
}
template <int NN>
__device__ __forceinline__ void cp_wait() {
    asm volatile("cp.async.wait_group %0;" :: "n"(NN) : "memory");
}
__device__ __forceinline__ void mma_f16(float c[4], const uint32_t a[4], const uint32_t b[2]) {
    asm volatile(
        "mma.sync.aligned.m16n8k16.row.col.f32.f16.f16.f32 "
        "{%0,%1,%2,%3}, {%4,%5,%6,%7}, {%8,%9}, {%0,%1,%2,%3};"
        : "+f"(c[0]), "+f"(c[1]), "+f"(c[2]), "+f"(c[3])
        : "r"(a[0]), "r"(a[1]), "r"(a[2]), "r"(a[3]), "r"(b[0]), "r"(b[1]));
}
__device__ __forceinline__ void ldsm_x4(uint32_t& r0, uint32_t& r1, uint32_t& r2, uint32_t& r3,
                                        uint32_t saddr) {
    asm volatile("ldmatrix.sync.aligned.m8n8.x4.shared.b16 {%0,%1,%2,%3}, [%4];"
                 : "=r"(r0), "=r"(r1), "=r"(r2), "=r"(r3) : "r"(saddr));
}

// ---- shared geometry ----
// Split-fp16 GEMMs (K1/K2a): 4 tiles [128][40] halves per stage, 2 stages.
#define T_ELEM   (128 * 40)                  // halves per tile
#define STG_ELEM (4 * T_ELEM)                // AH, AL, BH, BL
#define K12_SMEM (2 * STG_ELEM * 2)          // bytes = 81920
// K3: 128x128 block tile, BK=32, 4 stages; tile [128][40] halves
#define K3_NS 4
#define A3H_ELEMS (128 * 40)
#define A3H_BYTES (A3H_ELEMS * 2)
#define K3_SMEM (K3_NS * 2 * A3H_BYTES)      // 81920

// ============================================================================
// K0a: split 2^13*W into fp16 hi/lo (tiny).
// ============================================================================
__global__ void k0_splitW(const float* __restrict__ Wq, const float* __restrict__ Wk)
{
    const int i = blockIdx.x * 256 + threadIdx.x;
    if (i >= MIDC * C_CH) return;
    __half h, l;
    split_h16(Wq[i] * 8192.0f, h, l);
    g_Wh[0][i] = h; g_Wl[0][i] = l;
    split_h16(Wk[i] * 8192.0f, h, l);
    g_Wh[1][i] = h; g_Wl[1][i] = l;
}

// ============================================================================
// K0b: cam -> fp16 (elementwise, vectorized).
// ============================================================================
__global__ void k0_camh(const float* __restrict__ cam)
{
    const size_t i4 = (size_t)blockIdx.x * 256 + threadIdx.x;
    const size_t n4 = (size_t)BATCH * C_CH * N_SP / 4;
    if (i4 >= n4) return;
    float4 v = ((const float4*)cam)[i4];
    ((__half2*)g_camh)[i4 * 2]     = __floats2half2_rn(v.x, v.y);
    ((__half2*)g_camh)[i4 * 2 + 1] = __floats2half2_rn(v.z, v.w);
}

// ============================================================================
// K0c: feat [b][c][n] f32 -> xT hi/lo fp16 [b][n][c]. 64x64 smem transpose.
// ============================================================================
__global__ void k0_featT(const float* __restrict__ feat)
{
    __shared__ float tile[64][65];
    const int n0 = blockIdx.x * 64;
    const int c0 = blockIdx.y * 64;
    const int b  = blockIdx.z;
    const float* src = feat + (size_t)b * C_CH * N_SP;
    __half* dh = g_xTh + (size_t)b * N_SP * C_CH;
    __half* dl = g_xTl + (size_t)b * N_SP * C_CH;

    const int r  = threadIdx.x >> 5;      // 0..7
    const int c2 = (threadIdx.x & 31) * 2;

    #pragma unroll
    for (int w = 0; w < 8; w++) {
        float2 v = *(const float2*)(src + (size_t)(c0 + r + w * 8) * N_SP + n0 + c2);
        tile[r + w * 8][c2]     = v.x;
        tile[r + w * 8][c2 + 1] = v.y;
    }
    __syncthreads();
    #pragma unroll
    for (int w = 0; w < 8; w++) {
        int nl = r + w * 8;
        float x0 = tile[c2][nl], x1 = tile[c2 + 1][nl];
        __half h0, l0, h1, l1;
        split_h16(x0, h0, l0);
        split_h16(x1, h1, l1);
        size_t o = (size_t)(n0 + nl) * C_CH + c0 + c2;
        *(__half2*)(dh + o) = __halves2half2(h0, h1);
        *(__half2*)(dl + o) = __halves2half2(l0, l1);
    }
}

// ============================================================================
// K1: projections via split-fp16 (3-term) mma m16n8k16 + ldmatrix.
// D[m][n] = sum_k (2^13 W)[m,k] * x[k,n];  output split(2^6 q|k) at [n][m].
// Block 128x128, 4 warps (2x2) of 64x64, BK=32, double-buffered cp.async.
// ============================================================================
__global__ __launch_bounds__(128, 2) void k1_proj(void)
{
    const int nblk = blockIdx.x;          // 0..8
    const int mblk = blockIdx.y;          // 0..1
    const int b    = blockIdx.z;
    const __half* Wh = g_Wh[mblk];
    const __half* Wl = g_Wl[mblk];
    const __half* Xh = g_xTh + ((size_t)b * N_SP + nblk * 128) * C_CH;
    const __half* Xl = g_xTl + ((size_t)b * N_SP + nblk * 128) * C_CH;

    extern __shared__ __half smemh[];
    const uint32_t sb = (uint32_t)__cvta_generic_to_shared(smemh);

    const int tid  = threadIdx.x;
    const int warp = tid >> 5, lane = tid & 31;
    const int wm = warp >> 1, wn = warp & 1;
    const int g = lane >> 2, tig = lane & 3;
    const int n0 = nblk * 128;

    const uint32_t aRow = lane & 15;
    const uint32_t aCol = (lane >> 4) << 3;
    const uint32_t bRow = (lane & 7) + ((lane >> 4) << 3);
    const uint32_t bCol = ((lane >> 3) & 1) << 3;

    float acc[4][8][4] = {};

    auto loadStage = [&](int kt, int buf) {
        const int k0 = kt * 32;
        __half* st = smemh + buf * STG_ELEM;
        #pragma unroll
        for (int it = 0; it < 4; it++) {
            int id = tid + it * 128;
            int row = id >> 2;
            int ch  = (id & 3) * 8;
            cp_async16(st +              row * 40 + ch, Wh + (size_t)row * C_CH + k0 + ch);
            cp_async16(st + T_ELEM     + row * 40 + ch, Wl + (size_t)row * C_CH + k0 + ch);
            cp_async16(st + 2 * T_ELEM + row * 40 + ch, Xh + (size_t)row * C_CH + k0 + ch);
            cp_async16(st + 3 * T_ELEM + row * 40 + ch, Xl + (size_t)row * C_CH + k0 + ch);
        }
    };

    const int KT = C_CH / 32;   // 64
    loadStage(0, 0); cp_commit();

    for (int kt = 0; kt < KT; kt++) {
        cp_wait<0>();
        __syncthreads();
        const int buf = kt & 1;
        if (kt + 1 < KT) { loadStage(kt + 1, (kt + 1) & 1); cp_commit(); }

        const uint32_t stg = sb + buf * (STG_ELEM * 2);
        #pragma unroll
        for (int ks = 0; ks < 2; ks++) {
            const int kb = ks * 16;
            uint32_t bh[8][2], bl[8][2];
            #pragma unroll
            for (int fnp = 0; fnp < 4; fnp++) {
                uint32_t ad = stg + (2 * T_ELEM + (wn * 64 + fnp * 16 + bRow) * 40 + kb + bCol) * 2;
                ldsm_x4(bh[fnp * 2][0], bh[fnp * 2][1], bh[fnp * 2 + 1][0], bh[fnp * 2 + 1][1], ad);
                ldsm_x4(bl[fnp * 2][0], bl[fnp * 2][1], bl[fnp * 2 + 1][0], bl[fnp * 2 + 1][1],
                        ad + T_ELEM * 2);
            }
            #pragma unroll
            for (int fm = 0; fm < 4; fm++) {
                uint32_t ad = stg + ((wm * 64 + fm * 16 + aRow) * 40 + kb + aCol) * 2;
                uint32_t ah[4], al[4];
                ldsm_x4(ah[0], ah[1], ah[2], ah[3], ad);
                ldsm_x4(al[0], al[1], al[2], al[3], ad + T_ELEM * 2);
                #pragma unroll
                for (int fn = 0; fn < 8; fn++) {
                    mma_f16(acc[fm][fn], ah, bh[fn]);
                    mma_f16(acc[fm][fn], al, bh[fn]);
                    mma_f16(acc[fm][fn], ah, bl[fn]);
                }
            }
        }
    }

    // epilogue: v = acc * 2^-7 = 2^6 * (q|k); store split fp16 at [n][m]
    __half* oh = (mblk == 0 ? g_qh : g_kh) + (size_t)b * N_SP * MIDC;
    __half* ol = (mblk == 0 ? g_ql : g_kl) + (size_t)b * N_SP * MIDC;
    #pragma unroll
    for (int fm = 0; fm < 4; fm++) {
        #pragma unroll
        for (int fn = 0; fn < 8; fn++) {
            int m = wm * 64 + fm * 16 + g;
            int n = n0 + wn * 64 + fn * 8 + tig * 2;
            #pragma unroll
            for (int e = 0; e < 4; e++) {
                int mm = m + (e >> 1) * 8;
                int nn = n + (e & 1);
                float v = acc[fm][fn][e] * 0.0078125f;
                __half h, l;
                split_h16(v, h, l);
                oh[(size_t)nn * MIDC + mm] = h;
                ol[(size_t)nn * MIDC + mm] = l;
            }
        }
    }
}

// ============================================================================
// K2a: logits via split-fp16 (3-term). L[i][j] = 2^-12 * sum_m (2^6 q)(2^6 k).
// A = qh/ql [i][m], B = kh/kl [j][m], K=128, BK=32, KT=4, double-buffered.
// ============================================================================
__global__ __launch_bounds__(128, 2) void k2_logits(void)
{
    const int jblk = blockIdx.x;   // 0..8
    const int iblk = blockIdx.y;   // 0..8
    const int b    = blockIdx.z;
    const __half* Qh = g_qh + ((size_t)b * N_SP + iblk * 128) * MIDC;
    const __half* Ql = g_ql + ((size_t)b * N_SP + iblk * 128) * MIDC;
    const __half* Kh = g_kh + ((size_t)b * N_SP + jblk * 128) * MIDC;
    const __half* Kl = g_kl + ((size_t)b * N_SP + jblk * 128) * MIDC;
    float* L = g_attn + (size_t)b * N_SP * N_SP;

    extern __shared__ __half smemh[];
    const uint32_t sb = (uint32_t)__cvta_generic_to_shared(smemh);

    const int tid  = threadIdx.x;
    const int warp = tid >> 5, lane = tid & 31;
    const int wm = warp >> 1, wn = warp & 1;
    const int g = lane >> 2, tig = lane & 3;
    const int i0 = iblk * 128, j0 = jblk * 128;

    const uint32_t aRow = lane & 15;
    const uint32_t aCol = (lane >> 4) << 3;
    const uint32_t bRow = (lane & 7) + ((lane >> 4) << 3);
    const uint32_t bCol = ((lane >> 3) & 1) << 3;

    float acc[4][8][4] = {};

    auto loadStage = [&](int kt, int buf) {
        const int k0 = kt * 32;
        __half* st = smemh + buf * STG_ELEM;
        #pragma unroll
        for (int it = 0; it < 4; it++) {
            int id = tid + it * 128;
            int row = id >> 2;
            int ch  = (id & 3) * 8;
            cp_async16(st +              row * 40 + ch, Qh + (size_t)row * MIDC + k0 + ch);
            cp_async16(st + T_ELEM     + row * 40 + ch, Ql + (size_t)row * MIDC + k0 + ch);
            cp_async16(st + 2 * T_ELEM + row * 40 + ch, Kh + (size_t)row * MIDC + k0 + ch);
            cp_async16(st + 3 * T_ELEM + row * 40 + ch, Kl + (size_t)row * MIDC + k0 + ch);
        }
    };

    const int KT = MIDC / 32;   // 4
    loadStage(0, 0); cp_commit();

    for (int kt = 0; kt < KT; kt++) {
        cp_wait<0>();
        __syncthreads();
        const int buf = kt & 1;
        if (kt + 1 < KT) { loadStage(kt + 1, (kt + 1) & 1); cp_commit(); }

        const uint32_t stg = sb + buf * (STG_ELEM * 2);
        #pragma unroll
        for (int ks = 0; ks < 2; ks++) {
            const int kb = ks * 16;
            uint32_t bh[8][2], bl[8][2];
            #pragma unroll
            for (int fnp = 0; fnp < 4; fnp++) {
                uint32_t ad = stg + (2 * T_ELEM + (wn * 64 + fnp * 16 + bRow) * 40 + kb + bCol) * 2;
                ldsm_x4(bh[fnp * 2][0], bh[fnp * 2][1], bh[fnp * 2 + 1][0], bh[fnp * 2 + 1][1], ad);
                ldsm_x4(bl[fnp * 2][0], bl[fnp * 2][1], bl[fnp * 2 + 1][0], bl[fnp * 2 + 1][1],
                        ad + T_ELEM * 2);
            }
            #pragma unroll
            for (int fm = 0; fm < 4; fm++) {
                uint32_t ad = stg + ((wm * 64 + fm * 16 + aRow) * 40 + kb + aCol) * 2;
                uint32_t ah[4], al[4];
                ldsm_x4(ah[0], ah[1], ah[2], ah[3], ad);
                ldsm_x4(al[0], al[1], al[2], al[3], ad + T_ELEM * 2);
                #pragma unroll
                for (int fn = 0; fn < 8; fn++) {
                    mma_f16(acc[fm][fn], ah, bh[fn]);
                    mma_f16(acc[fm][fn], al, bh[fn]);
                    mma_f16(acc[fm][fn], ah, bl[fn]);
                }
            }
        }
    }

    const float s = 2.44140625e-4f;   // 2^-12
    #pragma unroll
    for (int fm = 0; fm < 4; fm++) {
        #pragma unroll
        for (int fn = 0; fn < 8; fn++) {
            int ii  = i0 + wm * 64 + fm * 16 + g;
            int col = j0 + wn * 64 + fn * 8 + tig * 2;
            *(float2*)(L + (size_t)ii * N_SP + col) =
                make_float2(acc[fm][fn][0] * s, acc[fm][fn][1] * s);
            *(float2*)(L + (size_t)(ii + 8) * N_SP + col) =
                make_float2(acc[fm][fn][2] * s, acc[fm][fn][3] * s);
        }
    }
}

// ============================================================================
// K2b: row softmax (length 1152), one warp per row. f32 in, fp16 out.
// ============================================================================
__global__ void k2_softmax()
{
    const int row  = blockIdx.x * 8 + (threadIdx.x >> 5);
    const int lane = threadIdx.x & 31;
    const float* r  = g_attn   + (size_t)row * N_SP;
    __half*      r16 = g_attn16 + (size_t)row * N_SP;

    float f[36];
    float mx = -1e30f;
    #pragma unroll
    for (int t = 0; t < 36; t++) {
        f[t] = r[lane + 32 * t];
        mx = fmaxf(mx, f[t]);
    }
    #pragma unroll
    for (int o = 16; o > 0; o >>= 1) mx = fmaxf(mx, __shfl_xor_sync(0xffffffffu, mx, o));

    float s = 0.0f;
    #pragma unroll
    for (int t = 0; t < 36; t++) {
        f[t] = __expf(f[t] - mx);
        s += f[t];
    }
    #pragma unroll
    for (int o = 16; o > 0; o >>= 1) s += __shfl_xor_sync(0xffffffffu, s, o);

    const float inv = 1.0f / s;
    #pragma unroll
    for (int t = 0; t < 36; t++)
        r16[lane + 32 * t] = __float2half_rn(f[t] * inv);
}

// ============================================================================
// K2t: fp16 transpose: g_attnT[b][j][i] = g_attn16[b][i][j]. 64x64 tiles.
// ============================================================================
__global__ void k2t_transpose()
{
    __shared__ __half tile[64][65];
    const int i0 = blockIdx.x * 64;
    const int j0 = blockIdx.y * 64;
    const int b  = blockIdx.z;
    const __half* src = g_attn16 + (size_t)b * N_SP * N_SP;
    __half*       dst = g_attnT  + (size_t)b * N_SP * N_SP;

    const int r = threadIdx.x >> 5;
    const int c2 = (threadIdx.x & 31) * 2;

    #pragma unroll
    for (int w = 0; w < 8; w++) {
        __half2 v = *(const __half2*)(src + (size_t)(i0 + r + w * 8) * N_SP + j0 + c2);
        tile[r + w * 8][c2]     = __low2half(v);
        tile[r + w * 8][c2 + 1] = __high2half(v);
    }
    __syncthreads();
    #pragma unroll
    for (int w = 0; w < 8; w++) {
        __half2 v = __halves2half2(tile[c2][r + w * 8], tile[c2 + 1][r + w * 8]);
        *(__half2*)(dst + (size_t)(j0 + r + w * 8) * N_SP + i0 + c2) = v;
    }
}

// ============================================================================
// K3: refined = cam @ attn via FP16 mma m16n8k16 + ldmatrix.x4.
// Block 128x128, 4 warps (2x2) of 64x64, BK=32, 4-stage cp.async.
// ============================================================================
__global__ __launch_bounds__(128, 2) void k3_refined(
    const float* __restrict__ cam,
    const float* __restrict__ alphaPtr,
    float* __restrict__ out)
{
    const int jblk = blockIdx.x;   // 0..8
    const int cblk = blockIdx.y;   // 0..15
    const int b    = blockIdx.z;

    const __half* Ahg = g_camh  + (size_t)b * C_CH * N_SP;
    const __half* Bhg = g_attnT + (size_t)b * N_SP * N_SP;
    const float*  Af  = cam     + (size_t)b * C_CH * N_SP;

    extern __shared__ __half smemh[];
    const uint32_t sbase = (uint32_t)__cvta_generic_to_shared(smemh);
    __half (*As)[128][40] = (__half(*)[128][40])smemh;
    __half (*Bs)[128][40] = (__half(*)[128][40])(smemh + K3_NS * A3H_ELEMS);
    const uint32_t aB = sbase;
    const uint32_t bB = sbase + K3_NS * A3H_BYTES;

    const int tid  = threadIdx.x;
    const int warp = tid >> 5, lane = tid & 31;
    const int wm = warp >> 1, wn = warp & 1;
    const int g = lane >> 2, tig = lane & 3;
    const int c0 = cblk * 128, j0 = jblk * 128;

    const uint32_t aRow = lane & 15;
    const uint32_t aCol = (lane >> 4) << 3;
    const uint32_t bRow = (lane & 7) + ((lane >> 4) << 3);
    const uint32_t bCol = ((lane >> 3) & 1) << 3;

    float acc[4][8][4] = {};

    auto loadStage = [&](int kt, int buf) {
        const int k0 = kt * 32;
        #pragma unroll
        for (int it = 0; it < 4; it++) {
            int id  = tid + it * 128;
            int row = id >> 2;
            int ch  = (id & 3) * 8;
            cp_async16(&As[buf][row][ch], Ahg + (size_t)(c0 + row) * N_SP + k0 + ch);
        }
        #pragma unroll
        for (int it = 0; it < 4; it++) {
            int id  = tid + it * 128;
            int row = id >> 2;
            int ch  = (id & 3) * 8;
            cp_async16(&Bs[buf][row][ch], Bhg + (size_t)(j0 + row) * N_SP + k0 + ch);
        }
    };

    const int KT = N_SP / 32;   // 36
    loadStage(0, 0); cp_commit();
    loadStage(1, 1); cp_commit();
    loadStage(2, 2); cp_commit();

    for (int kt = 0; kt < KT; kt++) {
        if (kt < KT - 2) cp_wait<2>(); else if (kt == KT - 2) cp_wait<1>(); else cp_wait<0>();
        __syncthreads();
        const int buf = kt % K3_NS;
        if (kt + 3 < KT) { loadStage(kt + 3, (kt + 3) % K3_NS); cp_commit(); }

        const uint32_t aStage = aB + buf * A3H_BYTES;
        const uint32_t bStage = bB + buf * A3H_BYTES;

        #pragma unroll
        for (int ks = 0; ks < 2; ks++) {
            const int kb = ks * 16;
            uint32_t bfr[8][2];
            #pragma unroll
            for (int fnp = 0; fnp < 4; fnp++) {
                uint32_t addr = bStage + ((wn * 64 + fnp * 16 + bRow) * 40 + kb + bCol) * 2;
                ldsm_x4(bfr[fnp * 2][0], bfr[fnp * 2][1],
                        bfr[fnp * 2 + 1][0], bfr[fnp * 2 + 1][1], addr);
            }
            #pragma unroll
            for (int fm = 0; fm < 4; fm++) {
                uint32_t addr = aStage + ((wm * 64 + fm * 16 + aRow) * 40 + kb + aCol) * 2;
                uint32_t afr[4];
                ldsm_x4(afr[0], afr[1], afr[2], afr[3], addr);
                #pragma unroll
                for (int fn = 0; fn < 8; fn++)
                    mma_f16(acc[fm][fn], afr, bfr[fn]);
            }
        }
    }

    const float alpha = alphaPtr[0];
    const size_t base = (size_t)b * C_CH * N_SP;
    #pragma unroll
    for (int fm = 0; fm < 4; fm++) {
        #pragma unroll
        for (int fn = 0; fn < 8; fn++) {
            int mrow = c0 + wm * 64 + fm * 16 + g;
            int col  = j0 + wn * 64 + fn * 8 + tig * 2;
            const float2 cv0 = *(const float2*)(Af + (size_t)mrow * N_SP + col);
            const float2 cv1 = *(const float2*)(Af + (size_t)(mrow + 8) * N_SP + col);
            float2 r0, r1;
            r0.x = fmaf(alpha, acc[fm][fn][0], cv0.x);
            r0.y = fmaf(alpha, acc[fm][fn][1], cv0.y);
            r1.x = fmaf(alpha, acc[fm][fn][2], cv1.x);
            r1.y = fmaf(alpha, acc[fm][fn][3], cv1.y);
            *(float2*)(out + base + (size_t)mrow * N_SP + col)       = r0;
            *(float2*)(out + base + (size_t)(mrow + 8) * N_SP + col) = r1;
        }
    }
}

// ============================================================================
extern "C" void kernel_launch(void* const* d_in, const int* in_sizes, int n_in,
                              void* d_out, int out_size)
{
    (void)in_sizes; (void)n_in; (void)out_size;
    const float* feat  = (const float*)d_in[0];
    const float* cam   = (const float*)d_in[1];
    const float* Wq    = (const float*)d_in[2];
    const float* Wk    = (const float*)d_in[3];
    const float* alpha = (const float*)d_in[4];
    float* out = (float*)d_out;

    cudaFuncSetAttribute(k1_proj,    cudaFuncAttributeMaxDynamicSharedMemorySize, K12_SMEM);
    cudaFuncSetAttribute(k2_logits,  cudaFuncAttributeMaxDynamicSharedMemorySize, K12_SMEM);
    cudaFuncSetAttribute(k3_refined, cudaFuncAttributeMaxDynamicSharedMemorySize, K3_SMEM);

    k0_splitW<<<(MIDC * C_CH + 255) / 256, 256>>>(Wq, Wk);
    k0_camh<<<(int)(((size_t)BATCH * C_CH * N_SP / 4 + 255) / 256), 256>>>(cam);
    k0_featT<<<dim3(N_SP / 64, C_CH / 64, BATCH), 256>>>(feat);
    k1_proj<<<dim3(9, 2, BATCH), 128, K12_SMEM>>>();
    k2_logits<<<dim3(9, 9, BATCH), 128, K12_SMEM>>>();
    k2_softmax<<<(BATCH * N_SP) / 8, 256>>>();
    k2t_transpose<<<dim3(18, 18, BATCH), 256>>>();
    k3_refined<<<dim3(9, 16, BATCH), 128, K3_SMEM>>>(cam, alpha, out);
}

// round 9
// speedup vs baseline: 1.7488x; 1.0058x over previous
#include <cuda_runtime.h>
#include <cuda_fp16.h>
#include <cstdint>
#include <cstddef>

#define BATCH 32
#define C_CH  2048
#define N_SP  1152   // 48*24
#define MIDC  128

// ---------------- scratch (device globals; no allocation allowed) ----------------
__device__ __align__(128) float  g_attn[(size_t)BATCH * N_SP * N_SP];    // logits [b][i][j] f32
__device__ __align__(128) __half g_attn16[(size_t)BATCH * N_SP * N_SP];  // softmax [b][i][j] fp16
__device__ __align__(128) __half g_camh[(size_t)BATCH * C_CH * N_SP];    // cam fp16
__device__ __align__(128) __half g_Wh[2][(size_t)MIDC * C_CH];           // fp16 hi of 2^13*W
__device__ __align__(128) __half g_Wl[2][(size_t)MIDC * C_CH];           // fp16 lo
__device__ __align__(128) __half g_xTh[(size_t)BATCH * N_SP * C_CH];     // featT hi [b][n][k]
__device__ __align__(128) __half g_xTl[(size_t)BATCH * N_SP * C_CH];     // featT lo
__device__ __align__(128) __half g_qh[(size_t)BATCH * N_SP * MIDC];      // split(2^6 q) [n][m]
__device__ __align__(128) __half g_ql[(size_t)BATCH * N_SP * MIDC];
__device__ __align__(128) __half g_kh[(size_t)BATCH * N_SP * MIDC];      // split(2^6 k) [n][m]
__device__ __align__(128) __half g_kl[(size_t)BATCH * N_SP * MIDC];

// ---------------- helpers ----------------
__device__ __forceinline__ void split_h16(float x, __half& h, __half& l) {
    h = __float2half_rn(x);
    l = __float2half_rn(x - __half2float(h));
}
__device__ __forceinline__ void cp_async16(void* smem, const void* gmem) {
    uint32_t s = (uint32_t)__cvta_generic_to_shared(smem);
    asm volatile("cp.async.cg.shared.global [%0], [%1], 16;" :: "r"(s), "l"(gmem));
}
__device__ __forceinline__ void cp_commit() {
    asm volatile("cp.async.commit_group;" ::: "memory");
}
template <int NN>
__device__ __forceinline__ void cp_wait() {
    asm volatile("cp.async.wait_group %0;" :: "n"(NN) : "memory");
}
__device__ __forceinline__ void mma_f16(float c[4], const uint32_t a[4], const uint32_t b[2]) {
    asm volatile(
        "mma.sync.aligned.m16n8k16.row.col.f32.f16.f16.f32 "
        "{%0,%1,%2,%3}, {%4,%5,%6,%7}, {%8,%9}, {%0,%1,%2,%3};"
        : "+f"(c[0]), "+f"(c[1]), "+f"(c[2]), "+f"(c[3])
        : "r"(a[0]), "r"(a[1]), "r"(a[2]), "r"(a[3]), "r"(b[0]), "r"(b[1]));
}
__device__ __forceinline__ void ldsm_x4(uint32_t& r0, uint32_t& r1, uint32_t& r2, uint32_t& r3,
                                        uint32_t saddr) {
    asm volatile("ldmatrix.sync.aligned.m8n8.x4.shared.b16 {%0,%1,%2,%3}, [%4];"
                 : "=r"(r0), "=r"(r1), "=r"(r2), "=r"(r3) : "r"(saddr));
}
__device__ __forceinline__ void ldsm_x4_t(uint32_t& r0, uint32_t& r1, uint32_t& r2, uint32_t& r3,
                                          uint32_t saddr) {
    asm volatile("ldmatrix.sync.aligned.m8n8.x4.trans.shared.b16 {%0,%1,%2,%3}, [%4];"
                 : "=r"(r0), "=r"(r1), "=r"(r2), "=r"(r3) : "r"(saddr));
}

// ---- shared geometry ----
// Split-fp16 GEMMs (K1/K2a): 4 tiles [128][40] halves per stage, 2 stages.
#define T_ELEM   (128 * 40)                  // halves per tile
#define STG_ELEM (4 * T_ELEM)                // AH, AL, BH, BL
#define K12_SMEM (2 * STG_ELEM * 2)          // 81920 B
// K3: 128x128 block tile, BK=32, 4 stages. A tile [128][40], B tile [32][136].
#define K3_NS 4
#define A3_ELEM (128 * 40)
#define B3_ELEM (32 * 136)
#define S3_ELEM (A3_ELEM + B3_ELEM)
#define K3_SMEM (K3_NS * S3_ELEM * 2)        // 75776 B

// ============================================================================
// K0a: split 2^13*W into fp16 hi/lo (tiny).
// ============================================================================
__global__ void k0_splitW(const float* __restrict__ Wq, const float* __restrict__ Wk)
{
    const int i = blockIdx.x * 256 + threadIdx.x;
    if (i >= MIDC * C_CH) return;
    __half h, l;
    split_h16(Wq[i] * 8192.0f, h, l);
    g_Wh[0][i] = h; g_Wl[0][i] = l;
    split_h16(Wk[i] * 8192.0f, h, l);
    g_Wh[1][i] = h; g_Wl[1][i] = l;
}

// ============================================================================
// K0b: cam -> fp16 (elementwise, vectorized).
// ============================================================================
__global__ void k0_camh(const float* __restrict__ cam)
{
    const size_t i4 = (size_t)blockIdx.x * 256 + threadIdx.x;
    const size_t n4 = (size_t)BATCH * C_CH * N_SP / 4;
    if (i4 >= n4) return;
    float4 v = ((const float4*)cam)[i4];
    ((__half2*)g_camh)[i4 * 2]     = __floats2half2_rn(v.x, v.y);
    ((__half2*)g_camh)[i4 * 2 + 1] = __floats2half2_rn(v.z, v.w);
}

// ============================================================================
// K0c: feat [b][c][n] f32 -> xT hi/lo fp16 [b][n][c]. 64x64 smem transpose.
// ============================================================================
__global__ void k0_featT(const float* __restrict__ feat)
{
    __shared__ float tile[64][65];
    const int n0 = blockIdx.x * 64;
    const int c0 = blockIdx.y * 64;
    const int b  = blockIdx.z;
    const float* src = feat + (size_t)b * C_CH * N_SP;
    __half* dh = g_xTh + (size_t)b * N_SP * C_CH;
    __half* dl = g_xTl + (size_t)b * N_SP * C_CH;

    const int r  = threadIdx.x >> 5;
    const int c2 = (threadIdx.x & 31) * 2;

    #pragma unroll
    for (int w = 0; w < 8; w++) {
        float2 v = *(const float2*)(src + (size_t)(c0 + r + w * 8) * N_SP + n0 + c2);
        tile[r + w * 8][c2]     = v.x;
        tile[r + w * 8][c2 + 1] = v.y;
    }
    __syncthreads();
    #pragma unroll
    for (int w = 0; w < 8; w++) {
        int nl = r + w * 8;
        float x0 = tile[c2][nl], x1 = tile[c2 + 1][nl];
        __half h0, l0, h1, l1;
        split_h16(x0, h0, l0);
        split_h16(x1, h1, l1);
        size_t o = (size_t)(n0 + nl) * C_CH + c0 + c2;
        *(__half2*)(dh + o) = __halves2half2(h0, h1);
        *(__half2*)(dl + o) = __halves2half2(l0, l1);
    }
}

// ============================================================================
// K1: projections via split-fp16 (3-term) mma m16n8k16 + ldmatrix.
// Block 128x128, 8 warps (2m x 4n) of 64x32, BK=32, double-buffered cp.async.
// ============================================================================
__global__ __launch_bounds__(256, 2) void k1_proj(void)
{
    const int nblk = blockIdx.x;          // 0..8
    const int mblk = blockIdx.y;          // 0..1
    const int b    = blockIdx.z;
    const __half* Wh = g_Wh[mblk];
    const __half* Wl = g_Wl[mblk];
    const __half* Xh = g_xTh + ((size_t)b * N_SP + nblk * 128) * C_CH;
    const __half* Xl = g_xTl + ((size_t)b * N_SP + nblk * 128) * C_CH;

    extern __shared__ __half smemh[];
    const uint32_t sb = (uint32_t)__cvta_generic_to_shared(smemh);

    const int tid  = threadIdx.x;
    const int warp = tid >> 5, lane = tid & 31;
    const int wm = warp >> 2, wn = warp & 3;   // 2m x 4n of 64x32
    const int g = lane >> 2, tig = lane & 3;
    const int n0 = nblk * 128;

    const uint32_t aRow = lane & 15;
    const uint32_t aCol = (lane >> 4) << 3;
    const uint32_t bRow = (lane & 7) + ((lane >> 4) << 3);
    const uint32_t bCol = ((lane >> 3) & 1) << 3;

    float acc[4][4][4] = {};

    auto loadStage = [&](int kt, int buf) {
        const int k0 = kt * 32;
        __half* st = smemh + buf * STG_ELEM;
        #pragma unroll
        for (int it = 0; it < 2; it++) {
            int id = tid + it * 256;
            int row = id >> 2;
            int ch  = (id & 3) * 8;
            cp_async16(st +              row * 40 + ch, Wh + (size_t)row * C_CH + k0 + ch);
            cp_async16(st + T_ELEM     + row * 40 + ch, Wl + (size_t)row * C_CH + k0 + ch);
            cp_async16(st + 2 * T_ELEM + row * 40 + ch, Xh + (size_t)row * C_CH + k0 + ch);
            cp_async16(st + 3 * T_ELEM + row * 40 + ch, Xl + (size_t)row * C_CH + k0 + ch);
        }
    };

    const int KT = C_CH / 32;   // 64
    loadStage(0, 0); cp_commit();

    for (int kt = 0; kt < KT; kt++) {
        cp_wait<0>();
        __syncthreads();
        const int buf = kt & 1;
        if (kt + 1 < KT) { loadStage(kt + 1, (kt + 1) & 1); cp_commit(); }

        const uint32_t stg = sb + buf * (STG_ELEM * 2);
        #pragma unroll
        for (int ks = 0; ks < 2; ks++) {
            const int kb = ks * 16;
            uint32_t bh[4][2], bl[4][2];
            #pragma unroll
            for (int fnp = 0; fnp < 2; fnp++) {
                uint32_t ad = stg + (2 * T_ELEM + (wn * 32 + fnp * 16 + bRow) * 40 + kb + bCol) * 2;
                ldsm_x4(bh[fnp * 2][0], bh[fnp * 2][1], bh[fnp * 2 + 1][0], bh[fnp * 2 + 1][1], ad);
                ldsm_x4(bl[fnp * 2][0], bl[fnp * 2][1], bl[fnp * 2 + 1][0], bl[fnp * 2 + 1][1],
                        ad + T_ELEM * 2);
            }
            #pragma unroll
            for (int fm = 0; fm < 4; fm++) {
                uint32_t ad = stg + ((wm * 64 + fm * 16 + aRow) * 40 + kb + aCol) * 2;
                uint32_t ah[4], al[4];
                ldsm_x4(ah[0], ah[1], ah[2], ah[3], ad);
                ldsm_x4(al[0], al[1], al[2], al[3], ad + T_ELEM * 2);
                #pragma unroll
                for (int fn = 0; fn < 4; fn++) {
                    mma_f16(acc[fm][fn], ah, bh[fn]);
                    mma_f16(acc[fm][fn], al, bh[fn]);
                    mma_f16(acc[fm][fn], ah, bl[fn]);
                }
            }
        }
    }

    // epilogue: v = acc * 2^-7 = 2^6 * (q|k); store split fp16 at [n][m]
    __half* oh = (mblk == 0 ? g_qh : g_kh) + (size_t)b * N_SP * MIDC;
    __half* ol = (mblk == 0 ? g_ql : g_kl) + (size_t)b * N_SP * MIDC;
    #pragma unroll
    for (int fm = 0; fm < 4; fm++) {
        #pragma unroll
        for (int fn = 0; fn < 4; fn++) {
            int m = wm * 64 + fm * 16 + g;
            int n = n0 + wn * 32 + fn * 8 + tig * 2;
            #pragma unroll
            for (int e = 0; e < 4; e++) {
                int mm = m + (e >> 1) * 8;
                int nn = n + (e & 1);
                float v = acc[fm][fn][e] * 0.0078125f;
                __half h, l;
                split_h16(v, h, l);
                oh[(size_t)nn * MIDC + mm] = h;
                ol[(size_t)nn * MIDC + mm] = l;
            }
        }
    }
}

// ============================================================================
// K2a: logits via split-fp16 (3-term). L[i][j] = 2^-12 * sum_m (2^6 q)(2^6 k).
// Block 128x128, 8 warps (2m x 4n) of 64x32, K=128, BK=32, double-buffered.
// ============================================================================
__global__ __launch_bounds__(256, 2) void k2_logits(void)
{
    const int jblk = blockIdx.x;   // 0..8
    const int iblk = blockIdx.y;   // 0..8
    const int b    = blockIdx.z;
    const __half* Qh = g_qh + ((size_t)b * N_SP + iblk * 128) * MIDC;
    const __half* Ql = g_ql + ((size_t)b * N_SP + iblk * 128) * MIDC;
    const __half* Kh = g_kh + ((size_t)b * N_SP + jblk * 128) * MIDC;
    const __half* Kl = g_kl + ((size_t)b * N_SP + jblk * 128) * MIDC;
    float* L = g_attn + (size_t)b * N_SP * N_SP;

    extern __shared__ __half smemh[];
    const uint32_t sb = (uint32_t)__cvta_generic_to_shared(smemh);

    const int tid  = threadIdx.x;
    const int warp = tid >> 5, lane = tid & 31;
    const int wm = warp >> 2, wn = warp & 3;
    const int g = lane >> 2, tig = lane & 3;
    const int i0 = iblk * 128, j0 = jblk * 128;

    const uint32_t aRow = lane & 15;
    const uint32_t aCol = (lane >> 4) << 3;
    const uint32_t bRow = (lane & 7) + ((lane >> 4) << 3);
    const uint32_t bCol = ((lane >> 3) & 1) << 3;

    float acc[4][4][4] = {};

    auto loadStage = [&](int kt, int buf) {
        const int k0 = kt * 32;
        __half* st = smemh + buf * STG_ELEM;
        #pragma unroll
        for (int it = 0; it < 2; it++) {
            int id = tid + it * 256;
            int row = id >> 2;
            int ch  = (id & 3) * 8;
            cp_async16(st +              row * 40 + ch, Qh + (size_t)row * MIDC + k0 + ch);
            cp_async16(st + T_ELEM     + row * 40 + ch, Ql + (size_t)row * MIDC + k0 + ch);
            cp_async16(st + 2 * T_ELEM + row * 40 + ch, Kh + (size_t)row * MIDC + k0 + ch);
            cp_async16(st + 3 * T_ELEM + row * 40 + ch, Kl + (size_t)row * MIDC + k0 + ch);
        }
    };

    const int KT = MIDC / 32;   // 4
    loadStage(0, 0); cp_commit();

    for (int kt = 0; kt < KT; kt++) {
        cp_wait<0>();
        __syncthreads();
        const int buf = kt & 1;
        if (kt + 1 < KT) { loadStage(kt + 1, (kt + 1) & 1); cp_commit(); }

        const uint32_t stg = sb + buf * (STG_ELEM * 2);
        #pragma unroll
        for (int ks = 0; ks < 2; ks++) {
            const int kb = ks * 16;
            uint32_t bh[4][2], bl[4][2];
            #pragma unroll
            for (int fnp = 0; fnp < 2; fnp++) {
                uint32_t ad = stg + (2 * T_ELEM + (wn * 32 + fnp * 16 + bRow) * 40 + kb + bCol) * 2;
                ldsm_x4(bh[fnp * 2][0], bh[fnp * 2][1], bh[fnp * 2 + 1][0], bh[fnp * 2 + 1][1], ad);
                ldsm_x4(bl[fnp * 2][0], bl[fnp * 2][1], bl[fnp * 2 + 1][0], bl[fnp * 2 + 1][1],
                        ad + T_ELEM * 2);
            }
            #pragma unroll
            for (int fm = 0; fm < 4; fm++) {
                uint32_t ad = stg + ((wm * 64 + fm * 16 + aRow) * 40 + kb + aCol) * 2;
                uint32_t ah[4], al[4];
                ldsm_x4(ah[0], ah[1], ah[2], ah[3], ad);
                ldsm_x4(al[0], al[1], al[2], al[3], ad + T_ELEM * 2);
                #pragma unroll
                for (int fn = 0; fn < 4; fn++) {
                    mma_f16(acc[fm][fn], ah, bh[fn]);
                    mma_f16(acc[fm][fn], al, bh[fn]);
                    mma_f16(acc[fm][fn], ah, bl[fn]);
                }
            }
        }
    }

    const float s = 2.44140625e-4f;   // 2^-12
    #pragma unroll
    for (int fm = 0; fm < 4; fm++) {
        #pragma unroll
        for (int fn = 0; fn < 4; fn++) {
            int ii  = i0 + wm * 64 + fm * 16 + g;
            int col = j0 + wn * 32 + fn * 8 + tig * 2;
            *(float2*)(L + (size_t)ii * N_SP + col) =
                make_float2(acc[fm][fn][0] * s, acc[fm][fn][1] * s);
            *(float2*)(L + (size_t)(ii + 8) * N_SP + col) =
                make_float2(acc[fm][fn][2] * s, acc[fm][fn][3] * s);
        }
    }
}

// ============================================================================
// K2b: row softmax (length 1152), one warp per row. f32 in, fp16 out.
// ============================================================================
__global__ void k2_softmax()
{
    const int row  = blockIdx.x * 8 + (threadIdx.x >> 5);
    const int lane = threadIdx.x & 31;
    const float* r   = g_attn   + (size_t)row * N_SP;
    __half*      r16 = g_attn16 + (size_t)row * N_SP;

    float f[36];
    float mx = -1e30f;
    #pragma unroll
    for (int t = 0; t < 36; t++) {
        f[t] = r[lane + 32 * t];
        mx = fmaxf(mx, f[t]);
    }
    #pragma unroll
    for (int o = 16; o > 0; o >>= 1) mx = fmaxf(mx, __shfl_xor_sync(0xffffffffu, mx, o));

    float s = 0.0f;
    #pragma unroll
    for (int t = 0; t < 36; t++) {
        f[t] = __expf(f[t] - mx);
        s += f[t];
    }
    #pragma unroll
    for (int o = 16; o > 0; o >>= 1) s += __shfl_xor_sync(0xffffffffu, s, o);

    const float inv = 1.0f / s;
    #pragma unroll
    for (int t = 0; t < 36; t++)
        r16[lane + 32 * t] = __float2half_rn(f[t] * inv);
}

// ============================================================================
// K3: refined = cam @ attn via FP16 mma + ldmatrix (B via .trans from attn16
// [i][j] directly -- no pre-transpose kernel).
// Block 128x128, 8 warps (2m x 4n) of 64x32, BK=32, 4-stage cp.async.
// A tile [128 c][40 k-halves]; B tile [32 k=i][136 j-halves].
// ============================================================================
__global__ __launch_bounds__(256, 2) void k3_refined(
    const float* __restrict__ cam,
    const float* __restrict__ alphaPtr,
    float* __restrict__ out)
{
    const int jblk = blockIdx.x;   // 0..8
    const int cblk = blockIdx.y;   // 0..15
    const int b    = blockIdx.z;

    const __half* Ahg = g_camh   + (size_t)b * C_CH * N_SP;
    const __half* Bhg = g_attn16 + (size_t)b * N_SP * N_SP;   // [i][j]
    const float*  Af  = cam      + (size_t)b * C_CH * N_SP;

    extern __shared__ __half smemh[];
    const uint32_t sbase = (uint32_t)__cvta_generic_to_shared(smemh);

    const int tid  = threadIdx.x;
    const int warp = tid >> 5, lane = tid & 31;
    const int wm = warp >> 2, wn = warp & 3;   // 2m x 4n of 64x32
    const int g = lane >> 2, tig = lane & 3;
    const int c0 = cblk * 128, j0 = jblk * 128;

    const uint32_t aRow = lane & 15;
    const uint32_t aCol = (lane >> 4) << 3;
    // trans-B lane addressing: mat0(k0-7,n0-7) mat1(k8-15,n0-7) mat2(k0-7,n8-15) mat3(k8-15,n8-15)
    const uint32_t tKrow = (lane & 7) + (((lane >> 3) & 1) << 3);
    const uint32_t tNcol = (lane >> 4) << 3;

    float acc[4][4][4] = {};

    auto loadStage = [&](int kt, int buf) {
        const int k0 = kt * 32;
        __half* st = smemh + buf * S3_ELEM;
        #pragma unroll
        for (int it = 0; it < 2; it++) {              // A: 128 rows x 32 halves
            int id  = tid + it * 256;
            int row = id >> 2;
            int ch  = (id & 3) * 8;
            cp_async16(st + row * 40 + ch, Ahg + (size_t)(c0 + row) * N_SP + k0 + ch);
        }
        #pragma unroll
        for (int it = 0; it < 2; it++) {              // B: 32 rows (i) x 128 halves (j)
            int id  = tid + it * 256;
            int row = id >> 4;
            int ch  = (id & 15) * 8;
            cp_async16(st + A3_ELEM + row * 136 + ch,
                       Bhg + (size_t)(k0 + row) * N_SP + j0 + ch);
        }
    };

    const int KT = N_SP / 32;   // 36
    loadStage(0, 0); cp_commit();
    loadStage(1, 1); cp_commit();
    loadStage(2, 2); cp_commit();

    for (int kt = 0; kt < KT; kt++) {
        if (kt < KT - 2) cp_wait<2>(); else if (kt == KT - 2) cp_wait<1>(); else cp_wait<0>();
        __syncthreads();
        const int buf = kt % K3_NS;
        if (kt + 3 < KT) { loadStage(kt + 3, (kt + 3) % K3_NS); cp_commit(); }

        const uint32_t stg = sbase + buf * (S3_ELEM * 2);
        #pragma unroll
        for (int ks = 0; ks < 2; ks++) {
            const int kb = ks * 16;
            uint32_t bfr[4][2];
            #pragma unroll
            for (int fnp = 0; fnp < 2; fnp++) {
                uint32_t ad = stg + (A3_ELEM + (kb + tKrow) * 136 +
                                     wn * 32 + fnp * 16 + tNcol) * 2;
                ldsm_x4_t(bfr[fnp * 2][0], bfr[fnp * 2][1],
                          bfr[fnp * 2 + 1][0], bfr[fnp * 2 + 1][1], ad);
            }
            #pragma unroll
            for (int fm = 0; fm < 4; fm++) {
                uint32_t ad = stg + ((wm * 64 + fm * 16 + aRow) * 40 + kb + aCol) * 2;
                uint32_t afr[4];
                ldsm_x4(afr[0], afr[1], afr[2], afr[3], ad);
                #pragma unroll
                for (int fn = 0; fn < 4; fn++)
                    mma_f16(acc[fm][fn], afr, bfr[fn]);
            }
        }
    }

    const float alpha = alphaPtr[0];
    const size_t base = (size_t)b * C_CH * N_SP;
    #pragma unroll
    for (int fm = 0; fm < 4; fm++) {
        #pragma unroll
        for (int fn = 0; fn < 4; fn++) {
            int mrow = c0 + wm * 64 + fm * 16 + g;
            int col  = j0 + wn * 32 + fn * 8 + tig * 2;
            const float2 cv0 = *(const float2*)(Af + (size_t)mrow * N_SP + col);
            const float2 cv1 = *(const float2*)(Af + (size_t)(mrow + 8) * N_SP + col);
            float2 r0, r1;
            r0.x = fmaf(alpha, acc[fm][fn][0], cv0.x);
            r0.y = fmaf(alpha, acc[fm][fn][1], cv0.y);
            r1.x = fmaf(alpha, acc[fm][fn][2], cv1.x);
            r1.y = fmaf(alpha, acc[fm][fn][3], cv1.y);
            *(float2*)(out + base + (size_t)mrow * N_SP + col)       = r0;
            *(float2*)(out + base + (size_t)(mrow + 8) * N_SP + col) = r1;
        }
    }
}

// ============================================================================
extern "C" void kernel_launch(void* const* d_in, const int* in_sizes, int n_in,
                              void* d_out, int out_size)
{
    (void)in_sizes; (void)n_in; (void)out_size;
    const float* feat  = (const float*)d_in[0];
    const float* cam   = (const float*)d_in[1];
    const float* Wq    = (const float*)d_in[2];
    const float* Wk    = (const float*)d_in[3];
    const float* alpha = (const float*)d_in[4];
    float* out = (float*)d_out;

    cudaFuncSetAttribute(k1_proj,    cudaFuncAttributeMaxDynamicSharedMemorySize, K12_SMEM);
    cudaFuncSetAttribute(k2_logits,  cudaFuncAttributeMaxDynamicSharedMemorySize, K12_SMEM);
    cudaFuncSetAttribute(k3_refined, cudaFuncAttributeMaxDynamicSharedMemorySize, K3_SMEM);

    k0_splitW<<<(MIDC * C_CH + 255) / 256, 256>>>(Wq, Wk);
    k0_camh<<<(int)(((size_t)BATCH * C_CH * N_SP / 4 + 255) / 256), 256>>>(cam);
    k0_featT<<<dim3(N_SP / 64, C_CH / 64, BATCH), 256>>>(feat);
    k1_proj<<<dim3(9, 2, BATCH), 256, K12_SMEM>>>();
    k2_logits<<<dim3(9, 9, BATCH), 256, K12_SMEM>>>();
    k2_softmax<<<(BATCH * N_SP) / 8, 256>>>();
    k3_refined<<<dim3(9, 16, BATCH), 256, K3_SMEM>>>(cam, alpha, out);
}

// round 10
// speedup vs baseline: 1.8653x; 1.0666x over previous
#include <cuda_runtime.h>
#include <cuda_fp16.h>
#include <cstdint>
#include <cstddef>

#define BATCH 32
#define C_CH  2048
#define N_SP  1152   // 48*24
#define MIDC  128

// ---------------- scratch (device globals; no allocation allowed) ----------------
__device__ __align__(128) float  g_attn[(size_t)BATCH * N_SP * N_SP];    // logits [b][i][j] f32
__device__ __align__(128) __half g_attn16[(size_t)BATCH * N_SP * N_SP];  // softmax [b][i][j] fp16
__device__ __align__(128) __half g_camh[(size_t)BATCH * C_CH * N_SP];    // cam fp16
__device__ __align__(128) __half g_Wh[2][(size_t)MIDC * C_CH];           // fp16 hi of 2^13*W
__device__ __align__(128) __half g_Wl[2][(size_t)MIDC * C_CH];           // fp16 lo
__device__ __align__(128) __half g_xTh[(size_t)BATCH * N_SP * C_CH];     // featT hi [b][n][k]
__device__ __align__(128) __half g_xTl[(size_t)BATCH * N_SP * C_CH];     // featT lo
__device__ __align__(128) __half g_qh[(size_t)BATCH * N_SP * MIDC];      // split(2^6 q) [n][m]
__device__ __align__(128) __half g_ql[(size_t)BATCH * N_SP * MIDC];
__device__ __align__(128) __half g_kh[(size_t)BATCH * N_SP * MIDC];      // split(2^6 k) [n][m]
__device__ __align__(128) __half g_kl[(size_t)BATCH * N_SP * MIDC];

// ---------------- helpers ----------------
__device__ __forceinline__ void split_h16(float x, __half& h, __half& l) {
    h = __float2half_rn(x);
    l = __float2half_rn(x - __half2float(h));
}
__device__ __forceinline__ void cp_async16(void* smem, const void* gmem) {
    uint32_t s = (uint32_t)__cvta_generic_to_shared(smem);
    asm volatile("cp.async.cg.shared.global [%0], [%1], 16;" :: "r"(s), "l"(gmem));
}
__device__ __forceinline__ void cp_commit() {
    asm volatile("cp.async.commit_group;" ::: "memory");
}
template <int NN>
__device__ __forceinline__ void cp_wait() {
    asm volatile("cp.async.wait_group %0;" :: "n"(NN) : "memory");
}
__device__ __forceinline__ void mma_f16(float c[4], const uint32_t a[4], const uint32_t b[2]) {
    asm volatile(
        "mma.sync.aligned.m16n8k16.row.col.f32.f16.f16.f32 "
        "{%0,%1,%2,%3}, {%4,%5,%6,%7}, {%8,%9}, {%0,%1,%2,%3};"
        : "+f"(c[0]), "+f"(c[1]), "+f"(c[2]), "+f"(c[3])
        : "r"(a[0]), "r"(a[1]), "r"(a[2]), "r"(a[3]), "r"(b[0]), "r"(b[1]));
}
__device__ __forceinline__ void ldsm_x4(uint32_t& r0, uint32_t& r1, uint32_t& r2, uint32_t& r3,
                                        uint32_t saddr) {
    asm volatile("ldmatrix.sync.aligned.m8n8.x4.shared.b16 {%0,%1,%2,%3}, [%4];"
                 : "=r"(r0), "=r"(r1), "=r"(r2), "=r"(r3) : "r"(saddr));
}
__device__ __forceinline__ void ldsm_x4_t(uint32_t& r0, uint32_t& r1, uint32_t& r2, uint32_t& r3,
                                          uint32_t saddr) {
    asm volatile("ldmatrix.sync.aligned.m8n8.x4.trans.shared.b16 {%0,%1,%2,%3}, [%4];"
                 : "=r"(r0), "=r"(r1), "=r"(r2), "=r"(r3) : "r"(saddr));
}

// ---- shared geometry ----
// Split-fp16 GEMMs (K1/K2a): 4 tiles [128][40] halves per stage, 2 stages.
#define T_ELEM   (128 * 40)                  // halves per tile
#define STG_ELEM (4 * T_ELEM)                // AH, AL, BH, BL
#define K12_SMEM (2 * STG_ELEM * 2)          // 81920 B
// K3: 128x128 block tile, BK=32, 4 stages. A tile [128][40], B tile [32][136].
#define K3_NS 4
#define A3_ELEM (128 * 40)
#define B3_ELEM (32 * 136)
#define S3_ELEM (A3_ELEM + B3_ELEM)
#define K3_SMEM (K3_NS * S3_ELEM * 2)        // 75776 B

// ============================================================================
// K0a: split 2^13*W into fp16 hi/lo (tiny).
// ============================================================================
__global__ void k0_splitW(const float* __restrict__ Wq, const float* __restrict__ Wk)
{
    const int i = blockIdx.x * 256 + threadIdx.x;
    if (i >= MIDC * C_CH) return;
    __half h, l;
    split_h16(Wq[i] * 8192.0f, h, l);
    g_Wh[0][i] = h; g_Wl[0][i] = l;
    split_h16(Wk[i] * 8192.0f, h, l);
    g_Wh[1][i] = h; g_Wl[1][i] = l;
}

// ============================================================================
// K0b: cam -> fp16 (elementwise, vectorized).
// ============================================================================
__global__ void k0_camh(const float* __restrict__ cam)
{
    const size_t i4 = (size_t)blockIdx.x * 256 + threadIdx.x;
    const size_t n4 = (size_t)BATCH * C_CH * N_SP / 4;
    if (i4 >= n4) return;
    float4 v = ((const float4*)cam)[i4];
    ((__half2*)g_camh)[i4 * 2]     = __floats2half2_rn(v.x, v.y);
    ((__half2*)g_camh)[i4 * 2 + 1] = __floats2half2_rn(v.z, v.w);
}

// ============================================================================
// K0c: feat [b][c][n] f32 -> xT hi/lo fp16 [b][n][c]. 64x64 smem transpose.
// ============================================================================
__global__ void k0_featT(const float* __restrict__ feat)
{
    __shared__ float tile[64][65];
    const int n0 = blockIdx.x * 64;
    const int c0 = blockIdx.y * 64;
    const int b  = blockIdx.z;
    const float* src = feat + (size_t)b * C_CH * N_SP;
    __half* dh = g_xTh + (size_t)b * N_SP * C_CH;
    __half* dl = g_xTl + (size_t)b * N_SP * C_CH;

    const int r  = threadIdx.x >> 5;
    const int c2 = (threadIdx.x & 31) * 2;

    #pragma unroll
    for (int w = 0; w < 8; w++) {
        float2 v = *(const float2*)(src + (size_t)(c0 + r + w * 8) * N_SP + n0 + c2);
        tile[r + w * 8][c2]     = v.x;
        tile[r + w * 8][c2 + 1] = v.y;
    }
    __syncthreads();
    #pragma unroll
    for (int w = 0; w < 8; w++) {
        int nl = r + w * 8;
        float x0 = tile[c2][nl], x1 = tile[c2 + 1][nl];
        __half h0, l0, h1, l1;
        split_h16(x0, h0, l0);
        split_h16(x1, h1, l1);
        size_t o = (size_t)(n0 + nl) * C_CH + c0 + c2;
        *(__half2*)(dh + o) = __halves2half2(h0, h1);
        *(__half2*)(dl + o) = __halves2half2(l0, l1);
    }
}

// ============================================================================
// K1: projections via split-fp16 (3-term) mma m16n8k16 + ldmatrix.
// Block 128x128, 8 warps (2m x 4n) of 64x32, BK=32, double-buffered cp.async.
// ============================================================================
__global__ __launch_bounds__(256, 2) void k1_proj(void)
{
    const int nblk = blockIdx.x;          // 0..8
    const int mblk = blockIdx.y;          // 0..1
    const int b    = blockIdx.z;
    const __half* Wh = g_Wh[mblk];
    const __half* Wl = g_Wl[mblk];
    const __half* Xh = g_xTh + ((size_t)b * N_SP + nblk * 128) * C_CH;
    const __half* Xl = g_xTl + ((size_t)b * N_SP + nblk * 128) * C_CH;

    extern __shared__ __half smemh[];
    const uint32_t sb = (uint32_t)__cvta_generic_to_shared(smemh);

    const int tid  = threadIdx.x;
    const int warp = tid >> 5, lane = tid & 31;
    const int wm = warp >> 2, wn = warp & 3;   // 2m x 4n of 64x32
    const int g = lane >> 2, tig = lane & 3;
    const int n0 = nblk * 128;

    const uint32_t aRow = lane & 15;
    const uint32_t aCol = (lane >> 4) << 3;
    const uint32_t bRow = (lane & 7) + ((lane >> 4) << 3);
    const uint32_t bCol = ((lane >> 3) & 1) << 3;

    float acc[4][4][4] = {};

    auto loadStage = [&](int kt, int buf) {
        const int k0 = kt * 32;
        __half* st = smemh + buf * STG_ELEM;
        #pragma unroll
        for (int it = 0; it < 2; it++) {
            int id = tid + it * 256;
            int row = id >> 2;
            int ch  = (id & 3) * 8;
            cp_async16(st +              row * 40 + ch, Wh + (size_t)row * C_CH + k0 + ch);
            cp_async16(st + T_ELEM     + row * 40 + ch, Wl + (size_t)row * C_CH + k0 + ch);
            cp_async16(st + 2 * T_ELEM + row * 40 + ch, Xh + (size_t)row * C_CH + k0 + ch);
            cp_async16(st + 3 * T_ELEM + row * 40 + ch, Xl + (size_t)row * C_CH + k0 + ch);
        }
    };

    const int KT = C_CH / 32;   // 64
    loadStage(0, 0); cp_commit();

    for (int kt = 0; kt < KT; kt++) {
        cp_wait<0>();
        __syncthreads();
        const int buf = kt & 1;
        if (kt + 1 < KT) { loadStage(kt + 1, (kt + 1) & 1); cp_commit(); }

        const uint32_t stg = sb + buf * (STG_ELEM * 2);
        #pragma unroll
        for (int ks = 0; ks < 2; ks++) {
            const int kb = ks * 16;
            uint32_t bh[4][2], bl[4][2];
            #pragma unroll
            for (int fnp = 0; fnp < 2; fnp++) {
                uint32_t ad = stg + (2 * T_ELEM + (wn * 32 + fnp * 16 + bRow) * 40 + kb + bCol) * 2;
                ldsm_x4(bh[fnp * 2][0], bh[fnp * 2][1], bh[fnp * 2 + 1][0], bh[fnp * 2 + 1][1], ad);
                ldsm_x4(bl[fnp * 2][0], bl[fnp * 2][1], bl[fnp * 2 + 1][0], bl[fnp * 2 + 1][1],
                        ad + T_ELEM * 2);
            }
            #pragma unroll
            for (int fm = 0; fm < 4; fm++) {
                uint32_t ad = stg + ((wm * 64 + fm * 16 + aRow) * 40 + kb + aCol) * 2;
                uint32_t ah[4], al[4];
                ldsm_x4(ah[0], ah[1], ah[2], ah[3], ad);
                ldsm_x4(al[0], al[1], al[2], al[3], ad + T_ELEM * 2);
                #pragma unroll
                for (int fn = 0; fn < 4; fn++) {
                    mma_f16(acc[fm][fn], ah, bh[fn]);
                    mma_f16(acc[fm][fn], al, bh[fn]);
                    mma_f16(acc[fm][fn], ah, bl[fn]);
                }
            }
        }
    }

    // epilogue: v = acc * 2^-7 = 2^6 * (q|k); store split fp16 at [n][m]
    __half* oh = (mblk == 0 ? g_qh : g_kh) + (size_t)b * N_SP * MIDC;
    __half* ol = (mblk == 0 ? g_ql : g_kl) + (size_t)b * N_SP * MIDC;
    #pragma unroll
    for (int fm = 0; fm < 4; fm++) {
        #pragma unroll
        for (int fn = 0; fn < 4; fn++) {
            int m = wm * 64 + fm * 16 + g;
            int n = n0 + wn * 32 + fn * 8 + tig * 2;
            #pragma unroll
            for (int e = 0; e < 4; e++) {
                int mm = m + (e >> 1) * 8;
                int nn = n + (e & 1);
                float v = acc[fm][fn][e] * 0.0078125f;
                __half h, l;
                split_h16(v, h, l);
                oh[(size_t)nn * MIDC + mm] = h;
                ol[(size_t)nn * MIDC + mm] = l;
            }
        }
    }
}

// ============================================================================
// K2a: logits via split-fp16 (3-term). L[i][j] = 2^-12 * sum_m (2^6 q)(2^6 k).
// Block 128x128, 8 warps (2m x 4n) of 64x32, K=128, BK=32, double-buffered.
// ============================================================================
__global__ __launch_bounds__(256, 2) void k2_logits(void)
{
    const int jblk = blockIdx.x;   // 0..8
    const int iblk = blockIdx.y;   // 0..8
    const int b    = blockIdx.z;
    const __half* Qh = g_qh + ((size_t)b * N_SP + iblk * 128) * MIDC;
    const __half* Ql = g_ql + ((size_t)b * N_SP + iblk * 128) * MIDC;
    const __half* Kh = g_kh + ((size_t)b * N_SP + jblk * 128) * MIDC;
    const __half* Kl = g_kl + ((size_t)b * N_SP + jblk * 128) * MIDC;
    float* L = g_attn + (size_t)b * N_SP * N_SP;

    extern __shared__ __half smemh[];
    const uint32_t sb = (uint32_t)__cvta_generic_to_shared(smemh);

    const int tid  = threadIdx.x;
    const int warp = tid >> 5, lane = tid & 31;
    const int wm = warp >> 2, wn = warp & 3;
    const int g = lane >> 2, tig = lane & 3;
    const int i0 = iblk * 128, j0 = jblk * 128;

    const uint32_t aRow = lane & 15;
    const uint32_t aCol = (lane >> 4) << 3;
    const uint32_t bRow = (lane & 7) + ((lane >> 4) << 3);
    const uint32_t bCol = ((lane >> 3) & 1) << 3;

    float acc[4][4][4] = {};

    auto loadStage = [&](int kt, int buf) {
        const int k0 = kt * 32;
        __half* st = smemh + buf * STG_ELEM;
        #pragma unroll
        for (int it = 0; it < 2; it++) {
            int id = tid + it * 256;
            int row = id >> 2;
            int ch  = (id & 3) * 8;
            cp_async16(st +              row * 40 + ch, Qh + (size_t)row * MIDC + k0 + ch);
            cp_async16(st + T_ELEM     + row * 40 + ch, Ql + (size_t)row * MIDC + k0 + ch);
            cp_async16(st + 2 * T_ELEM + row * 40 + ch, Kh + (size_t)row * MIDC + k0 + ch);
            cp_async16(st + 3 * T_ELEM + row * 40 + ch, Kl + (size_t)row * MIDC + k0 + ch);
        }
    };

    const int KT = MIDC / 32;   // 4
    loadStage(0, 0); cp_commit();

    for (int kt = 0; kt < KT; kt++) {
        cp_wait<0>();
        __syncthreads();
        const int buf = kt & 1;
        if (kt + 1 < KT) { loadStage(kt + 1, (kt + 1) & 1); cp_commit(); }

        const uint32_t stg = sb + buf * (STG_ELEM * 2);
        #pragma unroll
        for (int ks = 0; ks < 2; ks++) {
            const int kb = ks * 16;
            uint32_t bh[4][2], bl[4][2];
            #pragma unroll
            for (int fnp = 0; fnp < 2; fnp++) {
                uint32_t ad = stg + (2 * T_ELEM + (wn * 32 + fnp * 16 + bRow) * 40 + kb + bCol) * 2;
                ldsm_x4(bh[fnp * 2][0], bh[fnp * 2][1], bh[fnp * 2 + 1][0], bh[fnp * 2 + 1][1], ad);
                ldsm_x4(bl[fnp * 2][0], bl[fnp * 2][1], bl[fnp * 2 + 1][0], bl[fnp * 2 + 1][1],
                        ad + T_ELEM * 2);
            }
            #pragma unroll
            for (int fm = 0; fm < 4; fm++) {
                uint32_t ad = stg + ((wm * 64 + fm * 16 + aRow) * 40 + kb + aCol) * 2;
                uint32_t ah[4], al[4];
                ldsm_x4(ah[0], ah[1], ah[2], ah[3], ad);
                ldsm_x4(al[0], al[1], al[2], al[3], ad + T_ELEM * 2);
                #pragma unroll
                for (int fn = 0; fn < 4; fn++) {
                    mma_f16(acc[fm][fn], ah, bh[fn]);
                    mma_f16(acc[fm][fn], al, bh[fn]);
                    mma_f16(acc[fm][fn], ah, bl[fn]);
                }
            }
        }
    }

    const float s = 2.44140625e-4f;   // 2^-12
    #pragma unroll
    for (int fm = 0; fm < 4; fm++) {
        #pragma unroll
        for (int fn = 0; fn < 4; fn++) {
            int ii  = i0 + wm * 64 + fm * 16 + g;
            int col = j0 + wn * 32 + fn * 8 + tig * 2;
            *(float2*)(L + (size_t)ii * N_SP + col) =
                make_float2(acc[fm][fn][0] * s, acc[fm][fn][1] * s);
            *(float2*)(L + (size_t)(ii + 8) * N_SP + col) =
                make_float2(acc[fm][fn][2] * s, acc[fm][fn][3] * s);
        }
    }
}

// ============================================================================
// K2b: row softmax (length 1152), one warp per row. f32 in, fp16 out.
// ============================================================================
__global__ void k2_softmax()
{
    const int row  = blockIdx.x * 8 + (threadIdx.x >> 5);
    const int lane = threadIdx.x & 31;
    const float* r   = g_attn   + (size_t)row * N_SP;
    __half*      r16 = g_attn16 + (size_t)row * N_SP;

    float f[36];
    float mx = -1e30f;
    #pragma unroll
    for (int t = 0; t < 36; t++) {
        f[t] = r[lane + 32 * t];
        mx = fmaxf(mx, f[t]);
    }
    #pragma unroll
    for (int o = 16; o > 0; o >>= 1) mx = fmaxf(mx, __shfl_xor_sync(0xffffffffu, mx, o));

    float s = 0.0f;
    #pragma unroll
    for (int t = 0; t < 36; t++) {
        f[t] = __expf(f[t] - mx);
        s += f[t];
    }
    #pragma unroll
    for (int o = 16; o > 0; o >>= 1) s += __shfl_xor_sync(0xffffffffu, s, o);

    const float inv = 1.0f / s;
    #pragma unroll
    for (int t = 0; t < 36; t++)
        r16[lane + 32 * t] = __float2half_rn(f[t] * inv);
}

// ============================================================================
// K3: refined = cam @ attn via FP16 mma + ldmatrix (B via .trans from attn16
// [i][j] directly -- no pre-transpose kernel).
// Block 128x128, 4 warps (2m x 2n) of 64x64, BK=32, 4-stage cp.async,
// 128 threads, 2 CTAs/SM. 128 B/HMMA of LDSM traffic (optimal under reg cap).
// ============================================================================
__global__ __launch_bounds__(128, 2) void k3_refined(
    const float* __restrict__ cam,
    const float* __restrict__ alphaPtr,
    float* __restrict__ out)
{
    const int jblk = blockIdx.x;   // 0..8
    const int cblk = blockIdx.y;   // 0..15
    const int b    = blockIdx.z;

    const __half* Ahg = g_camh   + (size_t)b * C_CH * N_SP;
    const __half* Bhg = g_attn16 + (size_t)b * N_SP * N_SP;   // [i][j]
    const float*  Af  = cam      + (size_t)b * C_CH * N_SP;

    extern __shared__ __half smemh[];
    const uint32_t sbase = (uint32_t)__cvta_generic_to_shared(smemh);

    const int tid  = threadIdx.x;
    const int warp = tid >> 5, lane = tid & 31;
    const int wm = warp >> 1, wn = warp & 1;   // 2m x 2n of 64x64
    const int g = lane >> 2, tig = lane & 3;
    const int c0 = cblk * 128, j0 = jblk * 128;

    const uint32_t aRow = lane & 15;
    const uint32_t aCol = (lane >> 4) << 3;
    // trans-B lane addressing
    const uint32_t tKrow = (lane & 7) + (((lane >> 3) & 1) << 3);
    const uint32_t tNcol = (lane >> 4) << 3;

    float acc[4][8][4] = {};

    auto loadStage = [&](int kt, int buf) {
        const int k0 = kt * 32;
        __half* st = smemh + buf * S3_ELEM;
        #pragma unroll
        for (int it = 0; it < 4; it++) {              // A: 128 rows x 32 halves
            int id  = tid + it * 128;
            int row = id >> 2;
            int ch  = (id & 3) * 8;
            cp_async16(st + row * 40 + ch, Ahg + (size_t)(c0 + row) * N_SP + k0 + ch);
        }
        #pragma unroll
        for (int it = 0; it < 4; it++) {              // B: 32 rows (i) x 128 halves (j)
            int id  = tid + it * 128;
            int row = id >> 4;
            int ch  = (id & 15) * 8;
            cp_async16(st + A3_ELEM + row * 136 + ch,
                       Bhg + (size_t)(k0 + row) * N_SP + j0 + ch);
        }
    };

    const int KT = N_SP / 32;   // 36
    loadStage(0, 0); cp_commit();
    loadStage(1, 1); cp_commit();
    loadStage(2, 2); cp_commit();

    for (int kt = 0; kt < KT; kt++) {
        if (kt < KT - 2) cp_wait<2>(); else if (kt == KT - 2) cp_wait<1>(); else cp_wait<0>();
        __syncthreads();
        const int buf = kt % K3_NS;
        if (kt + 3 < KT) { loadStage(kt + 3, (kt + 3) % K3_NS); cp_commit(); }

        const uint32_t stg = sbase + buf * (S3_ELEM * 2);
        #pragma unroll
        for (int ks = 0; ks < 2; ks++) {
            const int kb = ks * 16;
            uint32_t bfr[8][2];
            #pragma unroll
            for (int fnp = 0; fnp < 4; fnp++) {
                uint32_t ad = stg + (A3_ELEM + (kb + tKrow) * 136 +
                                     wn * 64 + fnp * 16 + tNcol) * 2;
                ldsm_x4_t(bfr[fnp * 2][0], bfr[fnp * 2][1],
                          bfr[fnp * 2 + 1][0], bfr[fnp * 2 + 1][1], ad);
            }
            #pragma unroll
            for (int fm = 0; fm < 4; fm++) {
                uint32_t ad = stg + ((wm * 64 + fm * 16 + aRow) * 40 + kb + aCol) * 2;
                uint32_t afr[4];
                ldsm_x4(afr[0], afr[1], afr[2], afr[3], ad);
                #pragma unroll
                for (int fn = 0; fn < 8; fn++)
                    mma_f16(acc[fm][fn], afr, bfr[fn]);
            }
        }
    }

    const float alpha = alphaPtr[0];
    const size_t base = (size_t)b * C_CH * N_SP;
    #pragma unroll
    for (int fm = 0; fm < 4; fm++) {
        #pragma unroll
        for (int fn = 0; fn < 8; fn++) {
            int mrow = c0 + wm * 64 + fm * 16 + g;
            int col  = j0 + wn * 64 + fn * 8 + tig * 2;
            const float2 cv0 = *(const float2*)(Af + (size_t)mrow * N_SP + col);
            const float2 cv1 = *(const float2*)(Af + (size_t)(mrow + 8) * N_SP + col);
            float2 r0, r1;
            r0.x = fmaf(alpha, acc[fm][fn][0], cv0.x);
            r0.y = fmaf(alpha, acc[fm][fn][1], cv0.y);
            r1.x = fmaf(alpha, acc[fm][fn][2], cv1.x);
            r1.y = fmaf(alpha, acc[fm][fn][3], cv1.y);
            *(float2*)(out + base + (size_t)mrow * N_SP + col)       = r0;
            *(float2*)(out + base + (size_t)(mrow + 8) * N_SP + col) = r1;
        }
    }
}

// ============================================================================
extern "C" void kernel_launch(void* const* d_in, const int* in_sizes, int n_in,
                              void* d_out, int out_size)
{
    (void)in_sizes; (void)n_in; (void)out_size;
    const float* feat  = (const float*)d_in[0];
    const float* cam   = (const float*)d_in[1];
    const float* Wq    = (const float*)d_in[2];
    const float* Wk    = (const float*)d_in[3];
    const float* alpha = (const float*)d_in[4];
    float* out = (float*)d_out;

    cudaFuncSetAttribute(k1_proj,    cudaFuncAttributeMaxDynamicSharedMemorySize, K12_SMEM);
    cudaFuncSetAttribute(k2_logits,  cudaFuncAttributeMaxDynamicSharedMemorySize, K12_SMEM);
    cudaFuncSetAttribute(k3_refined, cudaFuncAttributeMaxDynamicSharedMemorySize, K3_SMEM);

    k0_splitW<<<(MIDC * C_CH + 255) / 256, 256>>>(Wq, Wk);
    k0_camh<<<(int)(((size_t)BATCH * C_CH * N_SP / 4 + 255) / 256), 256>>>(cam);
    k0_featT<<<dim3(N_SP / 64, C_CH / 64, BATCH), 256>>>(feat);
    k1_proj<<<dim3(9, 2, BATCH), 256, K12_SMEM>>>();
    k2_logits<<<dim3(9, 9, BATCH), 256, K12_SMEM>>>();
    k2_softmax<<<(BATCH * N_SP) / 8, 256>>>();
    k3_refined<<<dim3(9, 16, BATCH), 128, K3_SMEM>>>(cam, alpha, out);
}

// round 11
// speedup vs baseline: 2.0268x; 1.0866x over previous
#include <cuda_runtime.h>
#include <cuda_fp16.h>
#include <cstdint>
#include <cstddef>

#define BATCH 32
#define C_CH  2048
#define N_SP  1152   // 48*24
#define MIDC  128

// ---------------- scratch (device globals; no allocation allowed) ----------------
__device__ __align__(128) float  g_attn[(size_t)BATCH * N_SP * N_SP];    // logits [b][i][j] f32
__device__ __align__(128) __half g_attn16[(size_t)BATCH * N_SP * N_SP];  // softmax [b][i][j] fp16
__device__ __align__(128) __half g_Wh[2][(size_t)MIDC * C_CH];           // fp16 hi of 2^13*W
__device__ __align__(128) __half g_Wl[2][(size_t)MIDC * C_CH];           // fp16 lo
__device__ __align__(128) __half g_qh[(size_t)BATCH * N_SP * MIDC];      // split(2^6 q) [n][m]
__device__ __align__(128) __half g_ql[(size_t)BATCH * N_SP * MIDC];
__device__ __align__(128) __half g_kh[(size_t)BATCH * N_SP * MIDC];      // split(2^6 k) [n][m]
__device__ __align__(128) __half g_kl[(size_t)BATCH * N_SP * MIDC];

// ---------------- helpers ----------------
__device__ __forceinline__ void split_h16(float x, __half& h, __half& l) {
    h = __float2half_rn(x);
    l = __float2half_rn(x - __half2float(h));
}
__device__ __forceinline__ void cp_async16(void* smem, const void* gmem) {
    uint32_t s = (uint32_t)__cvta_generic_to_shared(smem);
    asm volatile("cp.async.cg.shared.global [%0], [%1], 16;" :: "r"(s), "l"(gmem));
}
__device__ __forceinline__ void cp_commit() {
    asm volatile("cp.async.commit_group;" ::: "memory");
}
template <int NN>
__device__ __forceinline__ void cp_wait() {
    asm volatile("cp.async.wait_group %0;" :: "n"(NN) : "memory");
}
__device__ __forceinline__ void mma_f16(float c[4], const uint32_t a[4], const uint32_t b[2]) {
    asm volatile(
        "mma.sync.aligned.m16n8k16.row.col.f32.f16.f16.f32 "
        "{%0,%1,%2,%3}, {%4,%5,%6,%7}, {%8,%9}, {%0,%1,%2,%3};"
        : "+f"(c[0]), "+f"(c[1]), "+f"(c[2]), "+f"(c[3])
        : "r"(a[0]), "r"(a[1]), "r"(a[2]), "r"(a[3]), "r"(b[0]), "r"(b[1]));
}
__device__ __forceinline__ void ldsm_x4(uint32_t& r0, uint32_t& r1, uint32_t& r2, uint32_t& r3,
                                        uint32_t saddr) {
    asm volatile("ldmatrix.sync.aligned.m8n8.x4.shared.b16 {%0,%1,%2,%3}, [%4];"
                 : "=r"(r0), "=r"(r1), "=r"(r2), "=r"(r3) : "r"(saddr));
}
__device__ __forceinline__ void ldsm_x4_t(uint32_t& r0, uint32_t& r1, uint32_t& r2, uint32_t& r3,
                                          uint32_t saddr) {
    asm volatile("ldmatrix.sync.aligned.m8n8.x4.trans.shared.b16 {%0,%1,%2,%3}, [%4];"
                 : "=r"(r0), "=r"(r1), "=r"(r2), "=r"(r3) : "r"(saddr));
}

// ---- shared geometry ----
// K1: A = W hi/lo tiles [128][40] halves (cp.async), B = x hi/lo tiles [32][136]
//     (in-kernel split from f32 LDG). 2 stages.
#define K1A_T 5120                       // halves per A tile
#define K1B_T 4352                       // halves per B tile
#define K1_STG (2 * K1A_T + 2 * K1B_T)   // 18944 halves / stage
#define K1_SMEM (2 * K1_STG * 2)         // 75776 B
// K2a: 4 tiles [128][40] per stage, 2 stages (unchanged).
#define T_ELEM   (128 * 40)
#define STG_ELEM (4 * T_ELEM)
#define K12_SMEM (2 * STG_ELEM * 2)      // 81920 B
// K3: A tile [128][40] (in-kernel cvt from f32 LDG), B tile [32][136] (cp.async). 2 stages.
#define K3A_T 5120
#define K3B_T 4352
#define K3_STG (K3A_T + K3B_T)           // 9472 halves / stage
#define K3_SMEM (2 * K3_STG * 2)         // 37888 B

// ============================================================================
// K0a: split 2^13*W into fp16 hi/lo (tiny).
// ============================================================================
__global__ void k0_splitW(const float* __restrict__ Wq, const float* __restrict__ Wk)
{
    const int i = blockIdx.x * 256 + threadIdx.x;
    if (i >= MIDC * C_CH) return;
    __half h, l;
    split_h16(Wq[i] * 8192.0f, h, l);
    g_Wh[0][i] = h; g_Wl[0][i] = l;
    split_h16(Wk[i] * 8192.0f, h, l);
    g_Wh[1][i] = h; g_Wl[1][i] = l;
}

// ============================================================================
// K1: projections via split-fp16 (3-term) mma m16n8k16.
// D[m][n] = sum_k (2^13 W)[m,k] * x[k,n]; x split in-kernel from f32 feat.
// Block 128x128, 4 warps (2x2) of 64x64, BK=32, 2-stage pipeline:
//   A (W hi/lo) via cp.async; B (x) via f32 LDG -> split -> smem, trans-LDSM.
// ============================================================================
__global__ __launch_bounds__(128, 2) void k1_proj(const float* __restrict__ feat)
{
    const int nblk = blockIdx.x;          // 0..8
    const int mblk = blockIdx.y;          // 0..1
    const int b    = blockIdx.z;
    const __half* Wh = g_Wh[mblk];
    const __half* Wl = g_Wl[mblk];
    const float*  X  = feat + (size_t)b * C_CH * N_SP;   // [c][n]

    extern __shared__ __half smemh[];
    const uint32_t sb = (uint32_t)__cvta_generic_to_shared(smemh);

    const int tid  = threadIdx.x;
    const int warp = tid >> 5, lane = tid & 31;
    const int wm = warp >> 1, wn = warp & 1;   // 2m x 2n of 64x64
    const int g = lane >> 2, tig = lane & 3;
    const int n0 = nblk * 128;

    const uint32_t aRow = lane & 15;
    const uint32_t aCol = (lane >> 4) << 3;
    const uint32_t tKrow = (lane & 7) + (((lane >> 3) & 1) << 3);
    const uint32_t tNcol = (lane >> 4) << 3;

    float acc[4][8][4] = {};
    float4 xb[8];

    auto ldgB = [&](int kt) {
        const int k0 = kt * 32;
        #pragma unroll
        for (int it = 0; it < 8; it++) {
            int id  = tid + it * 128;
            int row = id >> 5;           // 0..31 (k within tile)
            int nc  = (id & 31) * 4;     // n within tile
            xb[it] = *(const float4*)(X + (size_t)(k0 + row) * N_SP + n0 + nc);
        }
    };
    auto stsB = [&](int buf) {
        __half* st = smemh + buf * K1_STG + 2 * K1A_T;   // Bh base
        #pragma unroll
        for (int it = 0; it < 8; it++) {
            int id  = tid + it * 128;
            int row = id >> 5;
            int nc  = (id & 31) * 4;
            __half h0, l0, h1, l1, h2, l2, h3, l3;
            split_h16(xb[it].x, h0, l0); split_h16(xb[it].y, h1, l1);
            split_h16(xb[it].z, h2, l2); split_h16(xb[it].w, h3, l3);
            __half* ph = st + row * 136 + nc;
            *(__half2*)(ph)     = __halves2half2(h0, h1);
            *(__half2*)(ph + 2) = __halves2half2(h2, h3);
            __half* pl = ph + K1B_T;
            *(__half2*)(pl)     = __halves2half2(l0, l1);
            *(__half2*)(pl + 2) = __halves2half2(l2, l3);
        }
    };
    auto ldA = [&](int kt, int buf) {
        const int k0 = kt * 32;
        __half* st = smemh + buf * K1_STG;
        #pragma unroll
        for (int it = 0; it < 4; it++) {     // 128 rows x 32 halves = 512 chunks of 16B
            int id  = tid + it * 128;
            int row = id >> 2;
            int ch  = (id & 3) * 8;
            cp_async16(st + row * 40 + ch,         Wh + (size_t)row * C_CH + k0 + ch);
            cp_async16(st + K1A_T + row * 40 + ch, Wl + (size_t)row * C_CH + k0 + ch);
        }
    };

    const int KT = C_CH / 32;   // 64
    ldA(0, 0); cp_commit();
    ldA(1, 1); cp_commit();
    ldgB(0);

    for (int kt = 0; kt < KT; kt++) {
        const int buf = kt & 1;
        __syncthreads();                       // MMA(kt-1) finished both buffers' readers
        if (kt >= 1 && kt + 1 < KT) { ldA(kt + 1, (kt + 1) & 1); cp_commit(); }
        stsB(buf);                             // B(kt) split into smem
        if (kt + 1 < KT) ldgB(kt + 1);
        if (kt + 1 < KT) cp_wait<1>(); else cp_wait<0>();
        __syncthreads();                       // STS visible + A(kt) landed

        const uint32_t stg  = sb + buf * (K1_STG * 2);
        const uint32_t stgB = stg + 2 * K1A_T * 2;
        #pragma unroll
        for (int ks = 0; ks < 2; ks++) {
            const int kb = ks * 16;
            uint32_t bh[8][2], bl[8][2];
            #pragma unroll
            for (int fnp = 0; fnp < 4; fnp++) {
                uint32_t ad = stgB + ((kb + tKrow) * 136 + wn * 64 + fnp * 16 + tNcol) * 2;
                ldsm_x4_t(bh[fnp * 2][0], bh[fnp * 2][1],
                          bh[fnp * 2 + 1][0], bh[fnp * 2 + 1][1], ad);
                ldsm_x4_t(bl[fnp * 2][0], bl[fnp * 2][1],
                          bl[fnp * 2 + 1][0], bl[fnp * 2 + 1][1], ad + K1B_T * 2);
            }
            #pragma unroll
            for (int fm = 0; fm < 4; fm++) {
                uint32_t ad = stg + ((wm * 64 + fm * 16 + aRow) * 40 + kb + aCol) * 2;
                uint32_t ah[4], al[4];
                ldsm_x4(ah[0], ah[1], ah[2], ah[3], ad);
                ldsm_x4(al[0], al[1], al[2], al[3], ad + K1A_T * 2);
                #pragma unroll
                for (int fn = 0; fn < 8; fn++) {
                    mma_f16(acc[fm][fn], ah, bh[fn]);
                    mma_f16(acc[fm][fn], al, bh[fn]);
                    mma_f16(acc[fm][fn], ah, bl[fn]);
                }
            }
        }
    }

    // epilogue: v = acc * 2^-7 = 2^6 * (q|k); store split fp16 at [n][m]
    __half* oh = (mblk == 0 ? g_qh : g_kh) + (size_t)b * N_SP * MIDC;
    __half* ol = (mblk == 0 ? g_ql : g_kl) + (size_t)b * N_SP * MIDC;
    #pragma unroll
    for (int fm = 0; fm < 4; fm++) {
        #pragma unroll
        for (int fn = 0; fn < 8; fn++) {
            int m = wm * 64 + fm * 16 + g;
            int n = n0 + wn * 64 + fn * 8 + tig * 2;
            #pragma unroll
            for (int e = 0; e < 4; e++) {
                int mm = m + (e >> 1) * 8;
                int nn = n + (e & 1);
                float v = acc[fm][fn][e] * 0.0078125f;
                __half h, l;
                split_h16(v, h, l);
                oh[(size_t)nn * MIDC + mm] = h;
                ol[(size_t)nn * MIDC + mm] = l;
            }
        }
    }
}

// ============================================================================
// K2a: logits via split-fp16 (3-term). L[i][j] = 2^-12 * sum_m (2^6 q)(2^6 k).
// Block 128x128, 8 warps (2m x 4n) of 64x32, K=128, BK=32, double-buffered.
// ============================================================================
__global__ __launch_bounds__(256, 2) void k2_logits(void)
{
    const int jblk = blockIdx.x;   // 0..8
    const int iblk = blockIdx.y;   // 0..8
    const int b    = blockIdx.z;
    const __half* Qh = g_qh + ((size_t)b * N_SP + iblk * 128) * MIDC;
    const __half* Ql = g_ql + ((size_t)b * N_SP + iblk * 128) * MIDC;
    const __half* Kh = g_kh + ((size_t)b * N_SP + jblk * 128) * MIDC;
    const __half* Kl = g_kl + ((size_t)b * N_SP + jblk * 128) * MIDC;
    float* L = g_attn + (size_t)b * N_SP * N_SP;

    extern __shared__ __half smemh[];
    const uint32_t sb = (uint32_t)__cvta_generic_to_shared(smemh);

    const int tid  = threadIdx.x;
    const int warp = tid >> 5, lane = tid & 31;
    const int wm = warp >> 2, wn = warp & 3;
    const int g = lane >> 2, tig = lane & 3;
    const int i0 = iblk * 128, j0 = jblk * 128;

    const uint32_t aRow = lane & 15;
    const uint32_t aCol = (lane >> 4) << 3;
    const uint32_t bRow = (lane & 7) + ((lane >> 4) << 3);
    const uint32_t bCol = ((lane >> 3) & 1) << 3;

    float acc[4][4][4] = {};

    auto loadStage = [&](int kt, int buf) {
        const int k0 = kt * 32;
        __half* st = smemh + buf * STG_ELEM;
        #pragma unroll
        for (int it = 0; it < 2; it++) {
            int id = tid + it * 256;
            int row = id >> 2;
            int ch  = (id & 3) * 8;
            cp_async16(st +              row * 40 + ch, Qh + (size_t)row * MIDC + k0 + ch);
            cp_async16(st + T_ELEM     + row * 40 + ch, Ql + (size_t)row * MIDC + k0 + ch);
            cp_async16(st + 2 * T_ELEM + row * 40 + ch, Kh + (size_t)row * MIDC + k0 + ch);
            cp_async16(st + 3 * T_ELEM + row * 40 + ch, Kl + (size_t)row * MIDC + k0 + ch);
        }
    };

    const int KT = MIDC / 32;   // 4
    loadStage(0, 0); cp_commit();

    for (int kt = 0; kt < KT; kt++) {
        cp_wait<0>();
        __syncthreads();
        const int buf = kt & 1;
        if (kt + 1 < KT) { loadStage(kt + 1, (kt + 1) & 1); cp_commit(); }

        const uint32_t stg = sb + buf * (STG_ELEM * 2);
        #pragma unroll
        for (int ks = 0; ks < 2; ks++) {
            const int kb = ks * 16;
            uint32_t bh[4][2], bl[4][2];
            #pragma unroll
            for (int fnp = 0; fnp < 2; fnp++) {
                uint32_t ad = stg + (2 * T_ELEM + (wn * 32 + fnp * 16 + bRow) * 40 + kb + bCol) * 2;
                ldsm_x4(bh[fnp * 2][0], bh[fnp * 2][1], bh[fnp * 2 + 1][0], bh[fnp * 2 + 1][1], ad);
                ldsm_x4(bl[fnp * 2][0], bl[fnp * 2][1], bl[fnp * 2 + 1][0], bl[fnp * 2 + 1][1],
                        ad + T_ELEM * 2);
            }
            #pragma unroll
            for (int fm = 0; fm < 4; fm++) {
                uint32_t ad = stg + ((wm * 64 + fm * 16 + aRow) * 40 + kb + aCol) * 2;
                uint32_t ah[4], al[4];
                ldsm_x4(ah[0], ah[1], ah[2], ah[3], ad);
                ldsm_x4(al[0], al[1], al[2], al[3], ad + T_ELEM * 2);
                #pragma unroll
                for (int fn = 0; fn < 4; fn++) {
                    mma_f16(acc[fm][fn], ah, bh[fn]);
                    mma_f16(acc[fm][fn], al, bh[fn]);
                    mma_f16(acc[fm][fn], ah, bl[fn]);
                }
            }
        }
    }

    const float s = 2.44140625e-4f;   // 2^-12
    #pragma unroll
    for (int fm = 0; fm < 4; fm++) {
        #pragma unroll
        for (int fn = 0; fn < 4; fn++) {
            int ii  = i0 + wm * 64 + fm * 16 + g;
            int col = j0 + wn * 32 + fn * 8 + tig * 2;
            *(float2*)(L + (size_t)ii * N_SP + col) =
                make_float2(acc[fm][fn][0] * s, acc[fm][fn][1] * s);
            *(float2*)(L + (size_t)(ii + 8) * N_SP + col) =
                make_float2(acc[fm][fn][2] * s, acc[fm][fn][3] * s);
        }
    }
}

// ============================================================================
// K2b: row softmax (length 1152), one warp per row. f32 in, fp16 out.
// ============================================================================
__global__ void k2_softmax()
{
    const int row  = blockIdx.x * 8 + (threadIdx.x >> 5);
    const int lane = threadIdx.x & 31;
    const float* r   = g_attn   + (size_t)row * N_SP;
    __half*      r16 = g_attn16 + (size_t)row * N_SP;

    float f[36];
    float mx = -1e30f;
    #pragma unroll
    for (int t = 0; t < 36; t++) {
        f[t] = r[lane + 32 * t];
        mx = fmaxf(mx, f[t]);
    }
    #pragma unroll
    for (int o = 16; o > 0; o >>= 1) mx = fmaxf(mx, __shfl_xor_sync(0xffffffffu, mx, o));

    float s = 0.0f;
    #pragma unroll
    for (int t = 0; t < 36; t++) {
        f[t] = __expf(f[t] - mx);
        s += f[t];
    }
    #pragma unroll
    for (int o = 16; o > 0; o >>= 1) s += __shfl_xor_sync(0xffffffffu, s, o);

    const float inv = 1.0f / s;
    #pragma unroll
    for (int t = 0; t < 36; t++)
        r16[lane + 32 * t] = __float2half_rn(f[t] * inv);
}

// ============================================================================
// K3: refined = cam @ attn via FP16 mma; cam converted to fp16 in-kernel.
// Block 128x128, 4 warps (2m x 2n) of 64x64, BK=32, 2-stage pipeline:
//   A (cam) via f32 LDG -> cvt -> smem; B (attn16 [i][j]) via cp.async + trans-LDSM.
// ============================================================================
__global__ __launch_bounds__(128, 2) void k3_refined(
    const float* __restrict__ cam,
    const float* __restrict__ alphaPtr,
    float* __restrict__ out)
{
    const int jblk = blockIdx.x;   // 0..8
    const int cblk = blockIdx.y;   // 0..15
    const int b    = blockIdx.z;

    const __half* Bhg = g_attn16 + (size_t)b * N_SP * N_SP;   // [i][j]
    const float*  Af  = cam      + (size_t)b * C_CH * N_SP;

    extern __shared__ __half smemh[];
    const uint32_t sb = (uint32_t)__cvta_generic_to_shared(smemh);

    const int tid  = threadIdx.x;
    const int warp = tid >> 5, lane = tid & 31;
    const int wm = warp >> 1, wn = warp & 1;   // 2m x 2n of 64x64
    const int g = lane >> 2, tig = lane & 3;
    const int c0 = cblk * 128, j0 = jblk * 128;

    const uint32_t aRow = lane & 15;
    const uint32_t aCol = (lane >> 4) << 3;
    const uint32_t tKrow = (lane & 7) + (((lane >> 3) & 1) << 3);
    const uint32_t tNcol = (lane >> 4) << 3;

    float acc[4][8][4] = {};
    float4 xa[8];

    auto ldgA = [&](int kt) {
        const int k0 = kt * 32;
        #pragma unroll
        for (int it = 0; it < 8; it++) {
            int id  = tid + it * 128;
            int row = id >> 3;           // 0..127 (c)
            int kc  = (id & 7) * 4;      // k within tile
            xa[it] = *(const float4*)(Af + (size_t)(c0 + row) * N_SP + k0 + kc);
        }
    };
    auto stsA = [&](int buf) {
        __half* st = smemh + buf * K3_STG;
        #pragma unroll
        for (int it = 0; it < 8; it++) {
            int id  = tid + it * 128;
            int row = id >> 3;
            int kc  = (id & 7) * 4;
            __half* p = st + row * 40 + kc;
            *(__half2*)(p)     = __floats2half2_rn(xa[it].x, xa[it].y);
            *(__half2*)(p + 2) = __floats2half2_rn(xa[it].z, xa[it].w);
        }
    };
    auto cpB = [&](int kt, int buf) {
        const int k0 = kt * 32;
        __half* st = smemh + buf * K3_STG + K3A_T;
        #pragma unroll
        for (int it = 0; it < 4; it++) {      // 32 rows (i) x 128 halves (j) = 512 x 16B
            int id  = tid + it * 128;
            int row = id >> 4;
            int ch  = (id & 15) * 8;
            cp_async16(st + row * 136 + ch, Bhg + (size_t)(k0 + row) * N_SP + j0 + ch);
        }
    };

    const int KT = N_SP / 32;   // 36
    cpB(0, 0); cp_commit();
    cpB(1, 1); cp_commit();
    ldgA(0);

    for (int kt = 0; kt < KT; kt++) {
        const int buf = kt & 1;
        __syncthreads();                    // MMA(kt-1) done
        if (kt >= 1 && kt + 1 < KT) { cpB(kt + 1, (kt + 1) & 1); cp_commit(); }
        stsA(buf);
        if (kt + 1 < KT) ldgA(kt + 1);
        if (kt + 1 < KT) cp_wait<1>(); else cp_wait<0>();
        __syncthreads();

        const uint32_t stg  = sb + buf * (K3_STG * 2);
        const uint32_t stgB = stg + K3A_T * 2;
        #pragma unroll
        for (int ks = 0; ks < 2; ks++) {
            const int kb = ks * 16;
            uint32_t bfr[8][2];
            #pragma unroll
            for (int fnp = 0; fnp < 4; fnp++) {
                uint32_t ad = stgB + ((kb + tKrow) * 136 + wn * 64 + fnp * 16 + tNcol) * 2;
                ldsm_x4_t(bfr[fnp * 2][0], bfr[fnp * 2][1],
                          bfr[fnp * 2 + 1][0], bfr[fnp * 2 + 1][1], ad);
            }
            #pragma unroll
            for (int fm = 0; fm < 4; fm++) {
                uint32_t ad = stg + ((wm * 64 + fm * 16 + aRow) * 40 + kb + aCol) * 2;
                uint32_t afr[4];
                ldsm_x4(afr[0], afr[1], afr[2], afr[3], ad);
                #pragma unroll
                for (int fn = 0; fn < 8; fn++)
                    mma_f16(acc[fm][fn], afr, bfr[fn]);
            }
        }
    }

    const float alpha = alphaPtr[0];
    const size_t base = (size_t)b * C_CH * N_SP;
    #pragma unroll
    for (int fm = 0; fm < 4; fm++) {
        #pragma unroll
        for (int fn = 0; fn < 8; fn++) {
            int mrow = c0 + wm * 64 + fm * 16 + g;
            int col  = j0 + wn * 64 + fn * 8 + tig * 2;
            const float2 cv0 = *(const float2*)(Af + (size_t)mrow * N_SP + col);
            const float2 cv1 = *(const float2*)(Af + (size_t)(mrow + 8) * N_SP + col);
            float2 r0, r1;
            r0.x = fmaf(alpha, acc[fm][fn][0], cv0.x);
            r0.y = fmaf(alpha, acc[fm][fn][1], cv0.y);
            r1.x = fmaf(alpha, acc[fm][fn][2], cv1.x);
            r1.y = fmaf(alpha, acc[fm][fn][3], cv1.y);
            *(float2*)(out + base + (size_t)mrow * N_SP + col)       = r0;
            *(float2*)(out + base + (size_t)(mrow + 8) * N_SP + col) = r1;
        }
    }
}

// ============================================================================
extern "C" void kernel_launch(void* const* d_in, const int* in_sizes, int n_in,
                              void* d_out, int out_size)
{
    (void)in_sizes; (void)n_in; (void)out_size;
    const float* feat  = (const float*)d_in[0];
    const float* cam   = (const float*)d_in[1];
    const float* Wq    = (const float*)d_in[2];
    const float* Wk    = (const float*)d_in[3];
    const float* alpha = (const float*)d_in[4];
    float* out = (float*)d_out;

    cudaFuncSetAttribute(k1_proj,    cudaFuncAttributeMaxDynamicSharedMemorySize, K1_SMEM);
    cudaFuncSetAttribute(k2_logits,  cudaFuncAttributeMaxDynamicSharedMemorySize, K12_SMEM);
    cudaFuncSetAttribute(k3_refined, cudaFuncAttributeMaxDynamicSharedMemorySize, K3_SMEM);

    k0_splitW<<<(MIDC * C_CH + 255) / 256, 256>>>(Wq, Wk);
    k1_proj<<<dim3(9, 2, BATCH), 128, K1_SMEM>>>(feat);
    k2_logits<<<dim3(9, 9, BATCH), 256, K12_SMEM>>>();
    k2_softmax<<<(BATCH * N_SP) / 8, 256>>>();
    k3_refined<<<dim3(9, 16, BATCH), 128, K3_SMEM>>>(cam, alpha, out);
}

// round 12
// speedup vs baseline: 2.0628x; 1.0177x over previous
#include <cuda_runtime.h>
#include <cuda_fp16.h>
#include <cstdint>
#include <cstddef>

#define BATCH 32
#define C_CH  2048
#define N_SP  1152   // 48*24
#define MIDC  128

// ---------------- scratch (device globals; no allocation allowed) ----------------
__device__ __align__(128) float  g_attn[(size_t)BATCH * N_SP * N_SP];    // logits [b][i][j] f32
__device__ __align__(128) __half g_attn16[(size_t)BATCH * N_SP * N_SP];  // softmax [b][i][j] fp16
__device__ __align__(128) __half g_Wh[2][(size_t)MIDC * C_CH];           // fp16 hi of 2^13*W
__device__ __align__(128) __half g_Wl[2][(size_t)MIDC * C_CH];           // fp16 lo
__device__ __align__(128) __half g_qh[(size_t)BATCH * N_SP * MIDC];      // split(2^6 q) [n][m]
__device__ __align__(128) __half g_ql[(size_t)BATCH * N_SP * MIDC];
__device__ __align__(128) __half g_kh[(size_t)BATCH * N_SP * MIDC];      // split(2^6 k) [n][m]
__device__ __align__(128) __half g_kl[(size_t)BATCH * N_SP * MIDC];

// ---------------- helpers ----------------
__device__ __forceinline__ void split_h16(float x, __half& h, __half& l) {
    h = __float2half_rn(x);
    l = __float2half_rn(x - __half2float(h));
}
__device__ __forceinline__ void cp_async16(void* smem, const void* gmem) {
    uint32_t s = (uint32_t)__cvta_generic_to_shared(smem);
    asm volatile("cp.async.cg.shared.global [%0], [%1], 16;" :: "r"(s), "l"(gmem));
}
__device__ __forceinline__ void cp_commit() {
    asm volatile("cp.async.commit_group;" ::: "memory");
}
template <int NN>
__device__ __forceinline__ void cp_wait() {
    asm volatile("cp.async.wait_group %0;" :: "n"(NN) : "memory");
}
__device__ __forceinline__ void mma_f16(float c[4], const uint32_t a[4], const uint32_t b[2]) {
    asm volatile(
        "mma.sync.aligned.m16n8k16.row.col.f32.f16.f16.f32 "
        "{%0,%1,%2,%3}, {%4,%5,%6,%7}, {%8,%9}, {%0,%1,%2,%3};"
        : "+f"(c[0]), "+f"(c[1]), "+f"(c[2]), "+f"(c[3])
        : "r"(a[0]), "r"(a[1]), "r"(a[2]), "r"(a[3]), "r"(b[0]), "r"(b[1]));
}
__device__ __forceinline__ void ldsm_x4(uint32_t& r0, uint32_t& r1, uint32_t& r2, uint32_t& r3,
                                        uint32_t saddr) {
    asm volatile("ldmatrix.sync.aligned.m8n8.x4.shared.b16 {%0,%1,%2,%3}, [%4];"
                 : "=r"(r0), "=r"(r1), "=r"(r2), "=r"(r3) : "r"(saddr));
}
__device__ __forceinline__ void ldsm_x4_t(uint32_t& r0, uint32_t& r1, uint32_t& r2, uint32_t& r3,
                                          uint32_t saddr) {
    asm volatile("ldmatrix.sync.aligned.m8n8.x4.trans.shared.b16 {%0,%1,%2,%3}, [%4];"
                 : "=r"(r0), "=r"(r1), "=r"(r2), "=r"(r3) : "r"(saddr));
}

// ---- shared geometry ----
#define K1A_T 5120                       // halves per A tile (W hi or lo) [128][40]
#define K1B_T 4352                       // halves per B tile (x hi or lo) [32][136]
#define K1_STG (2 * K1A_T + 2 * K1B_T)   // 18944 halves / stage
#define K1_SMEM (2 * K1_STG * 2)         // 75776 B
#define T_ELEM   (128 * 40)
#define STG_ELEM (4 * T_ELEM)
#define K12_SMEM (2 * STG_ELEM * 2)      // 81920 B
#define K3A_T 5120
#define K3B_T 4352
#define K3_STG (K3A_T + K3B_T)           // 9472 halves / stage
#define K3_SMEM (2 * K3_STG * 2)         // 37888 B

// ============================================================================
// K0a: split 2^13*W into fp16 hi/lo (tiny).
// ============================================================================
__global__ void k0_splitW(const float* __restrict__ Wq, const float* __restrict__ Wk)
{
    const int i = blockIdx.x * 256 + threadIdx.x;
    if (i >= MIDC * C_CH) return;
    __half h, l;
    split_h16(Wq[i] * 8192.0f, h, l);
    g_Wh[0][i] = h; g_Wl[0][i] = l;
    split_h16(Wk[i] * 8192.0f, h, l);
    g_Wh[1][i] = h; g_Wl[1][i] = l;
}

// ============================================================================
// K1: projections via split-fp16 (3-term) mma m16n8k16.
// Block 128x128, 4 warps (2x2) of 64x64, BK=32, one-barrier double-buffer:
//   A (W hi/lo) cp.async prefetch-1; B (x f32 LDG -> split -> STS) prefetch-1
//   staged AROUND the MMA block.
// ============================================================================
__global__ __launch_bounds__(128, 2) void k1_proj(const float* __restrict__ feat)
{
    const int nblk = blockIdx.x;          // 0..8
    const int mblk = blockIdx.y;          // 0..1
    const int b    = blockIdx.z;
    const __half* Wh = g_Wh[mblk];
    const __half* Wl = g_Wl[mblk];
    const float*  X  = feat + (size_t)b * C_CH * N_SP;   // [c][n]

    extern __shared__ __half smemh[];
    const uint32_t sb = (uint32_t)__cvta_generic_to_shared(smemh);

    const int tid  = threadIdx.x;
    const int warp = tid >> 5, lane = tid & 31;
    const int wm = warp >> 1, wn = warp & 1;   // 2m x 2n of 64x64
    const int g = lane >> 2, tig = lane & 3;
    const int n0 = nblk * 128;

    const uint32_t aRow = lane & 15;
    const uint32_t aCol = (lane >> 4) << 3;
    const uint32_t tKrow = (lane & 7) + (((lane >> 3) & 1) << 3);
    const uint32_t tNcol = (lane >> 4) << 3;

    float acc[4][8][4] = {};
    float4 xb[8];

    auto ldgB = [&](int kt) {
        const int k0 = kt * 32;
        #pragma unroll
        for (int it = 0; it < 8; it++) {
            int id  = tid + it * 128;
            int row = id >> 5;           // k within tile
            int nc  = (id & 31) * 4;     // n within tile
            xb[it] = *(const float4*)(X + (size_t)(k0 + row) * N_SP + n0 + nc);
        }
    };
    auto stsB = [&](int buf) {
        __half* st = smemh + buf * K1_STG + 2 * K1A_T;
        #pragma unroll
        for (int it = 0; it < 8; it++) {
            int id  = tid + it * 128;
            int row = id >> 5;
            int nc  = (id & 31) * 4;
            __half h0, l0, h1, l1, h2, l2, h3, l3;
            split_h16(xb[it].x, h0, l0); split_h16(xb[it].y, h1, l1);
            split_h16(xb[it].z, h2, l2); split_h16(xb[it].w, h3, l3);
            __half* ph = st + row * 136 + nc;
            *(__half2*)(ph)     = __halves2half2(h0, h1);
            *(__half2*)(ph + 2) = __halves2half2(h2, h3);
            __half* pl = ph + K1B_T;
            *(__half2*)(pl)     = __halves2half2(l0, l1);
            *(__half2*)(pl + 2) = __halves2half2(l2, l3);
        }
    };
    auto ldA = [&](int kt, int buf) {
        const int k0 = kt * 32;
        __half* st = smemh + buf * K1_STG;
        #pragma unroll
        for (int it = 0; it < 4; it++) {
            int id  = tid + it * 128;
            int row = id >> 2;
            int ch  = (id & 3) * 8;
            cp_async16(st + row * 40 + ch,         Wh + (size_t)row * C_CH + k0 + ch);
            cp_async16(st + K1A_T + row * 40 + ch, Wl + (size_t)row * C_CH + k0 + ch);
        }
    };

    const int KT = C_CH / 32;   // 64
    // prologue: buf0 <- A(0),B(0); regs <- B(1)
    ldgB(0);
    ldA(0, 0); cp_commit();
    stsB(0);
    ldgB(1);

    for (int kt = 0; kt < KT; kt++) {
        const int buf = kt & 1;
        cp_wait<0>();
        __syncthreads();                  // buf data visible; buf^1 readers done
        if (kt + 1 < KT) { ldA(kt + 1, buf ^ 1); cp_commit(); }

        const uint32_t stg  = sb + buf * (K1_STG * 2);
        const uint32_t stgB = stg + 2 * K1A_T * 2;
        #pragma unroll
        for (int ks = 0; ks < 2; ks++) {
            const int kb = ks * 16;
            uint32_t bh[8][2], bl[8][2];
            #pragma unroll
            for (int fnp = 0; fnp < 4; fnp++) {
                uint32_t ad = stgB + ((kb + tKrow) * 136 + wn * 64 + fnp * 16 + tNcol) * 2;
                ldsm_x4_t(bh[fnp * 2][0], bh[fnp * 2][1],
                          bh[fnp * 2 + 1][0], bh[fnp * 2 + 1][1], ad);
                ldsm_x4_t(bl[fnp * 2][0], bl[fnp * 2][1],
                          bl[fnp * 2 + 1][0], bl[fnp * 2 + 1][1], ad + K1B_T * 2);
            }
            #pragma unroll
            for (int fm = 0; fm < 4; fm++) {
                uint32_t ad = stg + ((wm * 64 + fm * 16 + aRow) * 40 + kb + aCol) * 2;
                uint32_t ah[4], al[4];
                ldsm_x4(ah[0], ah[1], ah[2], ah[3], ad);
                ldsm_x4(al[0], al[1], al[2], al[3], ad + K1A_T * 2);
                #pragma unroll
                for (int fn = 0; fn < 8; fn++) {
                    mma_f16(acc[fm][fn], ah, bh[fn]);
                    mma_f16(acc[fm][fn], al, bh[fn]);
                    mma_f16(acc[fm][fn], ah, bl[fn]);
                }
            }
        }

        if (kt + 1 < KT) {
            stsB(buf ^ 1);                 // B(kt+1) from regs
            if (kt + 2 < KT) ldgB(kt + 2); // regs <- B(kt+2)
        }
    }

    // epilogue: v = acc * 2^-7 = 2^6 * (q|k); store split fp16 at [n][m]
    __half* oh = (mblk == 0 ? g_qh : g_kh) + (size_t)b * N_SP * MIDC;
    __half* ol = (mblk == 0 ? g_ql : g_kl) + (size_t)b * N_SP * MIDC;
    #pragma unroll
    for (int fm = 0; fm < 4; fm++) {
        #pragma unroll
        for (int fn = 0; fn < 8; fn++) {
            int m = wm * 64 + fm * 16 + g;
            int n = n0 + wn * 64 + fn * 8 + tig * 2;
            #pragma unroll
            for (int e = 0; e < 4; e++) {
                int mm = m + (e >> 1) * 8;
                int nn = n + (e & 1);
                float v = acc[fm][fn][e] * 0.0078125f;
                __half h, l;
                split_h16(v, h, l);
                oh[(size_t)nn * MIDC + mm] = h;
                ol[(size_t)nn * MIDC + mm] = l;
            }
        }
    }
}

// ============================================================================
// K2a: logits via split-fp16 (3-term). L[i][j] = 2^-12 * sum_m (2^6 q)(2^6 k).
// Block 128x128, 8 warps (2m x 4n) of 64x32, K=128, BK=32, double-buffered.
// ============================================================================
__global__ __launch_bounds__(256, 2) void k2_logits(void)
{
    const int jblk = blockIdx.x;   // 0..8
    const int iblk = blockIdx.y;   // 0..8
    const int b    = blockIdx.z;
    const __half* Qh = g_qh + ((size_t)b * N_SP + iblk * 128) * MIDC;
    const __half* Ql = g_ql + ((size_t)b * N_SP + iblk * 128) * MIDC;
    const __half* Kh = g_kh + ((size_t)b * N_SP + jblk * 128) * MIDC;
    const __half* Kl = g_kl + ((size_t)b * N_SP + jblk * 128) * MIDC;
    float* L = g_attn + (size_t)b * N_SP * N_SP;

    extern __shared__ __half smemh[];
    const uint32_t sb = (uint32_t)__cvta_generic_to_shared(smemh);

    const int tid  = threadIdx.x;
    const int warp = tid >> 5, lane = tid & 31;
    const int wm = warp >> 2, wn = warp & 3;
    const int g = lane >> 2, tig = lane & 3;
    const int i0 = iblk * 128, j0 = jblk * 128;

    const uint32_t aRow = lane & 15;
    const uint32_t aCol = (lane >> 4) << 3;
    const uint32_t bRow = (lane & 7) + ((lane >> 4) << 3);
    const uint32_t bCol = ((lane >> 3) & 1) << 3;

    float acc[4][4][4] = {};

    auto loadStage = [&](int kt, int buf) {
        const int k0 = kt * 32;
        __half* st = smemh + buf * STG_ELEM;
        #pragma unroll
        for (int it = 0; it < 2; it++) {
            int id = tid + it * 256;
            int row = id >> 2;
            int ch  = (id & 3) * 8;
            cp_async16(st +              row * 40 + ch, Qh + (size_t)row * MIDC + k0 + ch);
            cp_async16(st + T_ELEM     + row * 40 + ch, Ql + (size_t)row * MIDC + k0 + ch);
            cp_async16(st + 2 * T_ELEM + row * 40 + ch, Kh + (size_t)row * MIDC + k0 + ch);
            cp_async16(st + 3 * T_ELEM + row * 40 + ch, Kl + (size_t)row * MIDC + k0 + ch);
        }
    };

    const int KT = MIDC / 32;   // 4
    loadStage(0, 0); cp_commit();

    for (int kt = 0; kt < KT; kt++) {
        cp_wait<0>();
        __syncthreads();
        const int buf = kt & 1;
        if (kt + 1 < KT) { loadStage(kt + 1, (kt + 1) & 1); cp_commit(); }

        const uint32_t stg = sb + buf * (STG_ELEM * 2);
        #pragma unroll
        for (int ks = 0; ks < 2; ks++) {
            const int kb = ks * 16;
            uint32_t bh[4][2], bl[4][2];
            #pragma unroll
            for (int fnp = 0; fnp < 2; fnp++) {
                uint32_t ad = stg + (2 * T_ELEM + (wn * 32 + fnp * 16 + bRow) * 40 + kb + bCol) * 2;
                ldsm_x4(bh[fnp * 2][0], bh[fnp * 2][1], bh[fnp * 2 + 1][0], bh[fnp * 2 + 1][1], ad);
                ldsm_x4(bl[fnp * 2][0], bl[fnp * 2][1], bl[fnp * 2 + 1][0], bl[fnp * 2 + 1][1],
                        ad + T_ELEM * 2);
            }
            #pragma unroll
            for (int fm = 0; fm < 4; fm++) {
                uint32_t ad = stg + ((wm * 64 + fm * 16 + aRow) * 40 + kb + aCol) * 2;
                uint32_t ah[4], al[4];
                ldsm_x4(ah[0], ah[1], ah[2], ah[3], ad);
                ldsm_x4(al[0], al[1], al[2], al[3], ad + T_ELEM * 2);
                #pragma unroll
                for (int fn = 0; fn < 4; fn++) {
                    mma_f16(acc[fm][fn], ah, bh[fn]);
                    mma_f16(acc[fm][fn], al, bh[fn]);
                    mma_f16(acc[fm][fn], ah, bl[fn]);
                }
            }
        }
    }

    const float s = 2.44140625e-4f;   // 2^-12
    #pragma unroll
    for (int fm = 0; fm < 4; fm++) {
        #pragma unroll
        for (int fn = 0; fn < 4; fn++) {
            int ii  = i0 + wm * 64 + fm * 16 + g;
            int col = j0 + wn * 32 + fn * 8 + tig * 2;
            *(float2*)(L + (size_t)ii * N_SP + col) =
                make_float2(acc[fm][fn][0] * s, acc[fm][fn][1] * s);
            *(float2*)(L + (size_t)(ii + 8) * N_SP + col) =
                make_float2(acc[fm][fn][2] * s, acc[fm][fn][3] * s);
        }
    }
}

// ============================================================================
// K2b: row softmax (length 1152), one warp per row. f32 in, fp16 out.
// ============================================================================
__global__ void k2_softmax()
{
    const int row  = blockIdx.x * 8 + (threadIdx.x >> 5);
    const int lane = threadIdx.x & 31;
    const float* r   = g_attn   + (size_t)row * N_SP;
    __half*      r16 = g_attn16 + (size_t)row * N_SP;

    float f[36];
    float mx = -1e30f;
    #pragma unroll
    for (int t = 0; t < 36; t++) {
        f[t] = r[lane + 32 * t];
        mx = fmaxf(mx, f[t]);
    }
    #pragma unroll
    for (int o = 16; o > 0; o >>= 1) mx = fmaxf(mx, __shfl_xor_sync(0xffffffffu, mx, o));

    float s = 0.0f;
    #pragma unroll
    for (int t = 0; t < 36; t++) {
        f[t] = __expf(f[t] - mx);
        s += f[t];
    }
    #pragma unroll
    for (int o = 16; o > 0; o >>= 1) s += __shfl_xor_sync(0xffffffffu, s, o);

    const float inv = 1.0f / s;
    #pragma unroll
    for (int t = 0; t < 36; t++)
        r16[lane + 32 * t] = __float2half_rn(f[t] * inv);
}

// ============================================================================
// K3: refined = cam @ attn via FP16 mma; cam converted to fp16 in-kernel.
// Block 128x128, 4 warps (2m x 2n) of 64x64, BK=32, one-barrier double-buffer:
//   B (attn16) cp.async prefetch-1; A (cam f32 LDG -> cvt -> STS) prefetch-1
//   staged AROUND the MMA block.
// ============================================================================
__global__ __launch_bounds__(128, 2) void k3_refined(
    const float* __restrict__ cam,
    const float* __restrict__ alphaPtr,
    float* __restrict__ out)
{
    const int jblk = blockIdx.x;   // 0..8
    const int cblk = blockIdx.y;   // 0..15
    const int b    = blockIdx.z;

    const __half* Bhg = g_attn16 + (size_t)b * N_SP * N_SP;   // [i][j]
    const float*  Af  = cam      + (size_t)b * C_CH * N_SP;

    extern __shared__ __half smemh[];
    const uint32_t sb = (uint32_t)__cvta_generic_to_shared(smemh);

    const int tid  = threadIdx.x;
    const int warp = tid >> 5, lane = tid & 31;
    const int wm = warp >> 1, wn = warp & 1;   // 2m x 2n of 64x64
    const int g = lane >> 2, tig = lane & 3;
    const int c0 = cblk * 128, j0 = jblk * 128;

    const uint32_t aRow = lane & 15;
    const uint32_t aCol = (lane >> 4) << 3;
    const uint32_t tKrow = (lane & 7) + (((lane >> 3) & 1) << 3);
    const uint32_t tNcol = (lane >> 4) << 3;

    float acc[4][8][4] = {};
    float4 xa[8];

    auto ldgA = [&](int kt) {
        const int k0 = kt * 32;
        #pragma unroll
        for (int it = 0; it < 8; it++) {
            int id  = tid + it * 128;
            int row = id >> 3;
            int kc  = (id & 7) * 4;
            xa[it] = *(const float4*)(Af + (size_t)(c0 + row) * N_SP + k0 + kc);
        }
    };
    auto stsA = [&](int buf) {
        __half* st = smemh + buf * K3_STG;
        #pragma unroll
        for (int it = 0; it < 8; it++) {
            int id  = tid + it * 128;
            int row = id >> 3;
            int kc  = (id & 7) * 4;
            __half* p = st + row * 40 + kc;
            *(__half2*)(p)     = __floats2half2_rn(xa[it].x, xa[it].y);
            *(__half2*)(p + 2) = __floats2half2_rn(xa[it].z, xa[it].w);
        }
    };
    auto cpB = [&](int kt, int buf) {
        const int k0 = kt * 32;
        __half* st = smemh + buf * K3_STG + K3A_T;
        #pragma unroll
        for (int it = 0; it < 4; it++) {
            int id  = tid + it * 128;
            int row = id >> 4;
            int ch  = (id & 15) * 8;
            cp_async16(st + row * 136 + ch, Bhg + (size_t)(k0 + row) * N_SP + j0 + ch);
        }
    };

    const int KT = N_SP / 32;   // 36
    // prologue: buf0 <- A(0),B(0); regs <- A(1)
    ldgA(0);
    cpB(0, 0); cp_commit();
    stsA(0);
    ldgA(1);

    for (int kt = 0; kt < KT; kt++) {
        const int buf = kt & 1;
        cp_wait<0>();
        __syncthreads();
        if (kt + 1 < KT) { cpB(kt + 1, buf ^ 1); cp_commit(); }

        const uint32_t stg  = sb + buf * (K3_STG * 2);
        const uint32_t stgB = stg + K3A_T * 2;
        #pragma unroll
        for (int ks = 0; ks < 2; ks++) {
            const int kb = ks * 16;
            uint32_t bfr[8][2];
            #pragma unroll
            for (int fnp = 0; fnp < 4; fnp++) {
                uint32_t ad = stgB + ((kb + tKrow) * 136 + wn * 64 + fnp * 16 + tNcol) * 2;
                ldsm_x4_t(bfr[fnp * 2][0], bfr[fnp * 2][1],
                          bfr[fnp * 2 + 1][0], bfr[fnp * 2 + 1][1], ad);
            }
            #pragma unroll
            for (int fm = 0; fm < 4; fm++) {
                uint32_t ad = stg + ((wm * 64 + fm * 16 + aRow) * 40 + kb + aCol) * 2;
                uint32_t afr[4];
                ldsm_x4(afr[0], afr[1], afr[2], afr[3], ad);
                #pragma unroll
                for (int fn = 0; fn < 8; fn++)
                    mma_f16(acc[fm][fn], afr, bfr[fn]);
            }
        }

        if (kt + 1 < KT) {
            stsA(buf ^ 1);                  // A(kt+1) from regs
            if (kt + 2 < KT) ldgA(kt + 2);  // regs <- A(kt+2)
        }
    }

    const float alpha = alphaPtr[0];
    const size_t base = (size_t)b * C_CH * N_SP;
    #pragma unroll
    for (int fm = 0; fm < 4; fm++) {
        #pragma unroll
        for (int fn = 0; fn < 8; fn++) {
            int mrow = c0 + wm * 64 + fm * 16 + g;
            int col  = j0 + wn * 64 + fn * 8 + tig * 2;
            const float2 cv0 = *(const float2*)(Af + (size_t)mrow * N_SP + col);
            const float2 cv1 = *(const float2*)(Af + (size_t)(mrow + 8) * N_SP + col);
            float2 r0, r1;
            r0.x = fmaf(alpha, acc[fm][fn][0], cv0.x);
            r0.y = fmaf(alpha, acc[fm][fn][1], cv0.y);
            r1.x = fmaf(alpha, acc[fm][fn][2], cv1.x);
            r1.y = fmaf(alpha, acc[fm][fn][3], cv1.y);
            *(float2*)(out + base + (size_t)mrow * N_SP + col)       = r0;
            *(float2*)(out + base + (size_t)(mrow + 8) * N_SP + col) = r1;
        }
    }
}

// ============================================================================
extern "C" void kernel_launch(void* const* d_in, const int* in_sizes, int n_in,
                              void* d_out, int out_size)
{
    (void)in_sizes; (void)n_in; (void)out_size;
    const float* feat  = (const float*)d_in[0];
    const float* cam   = (const float*)d_in[1];
    const float* Wq    = (const float*)d_in[2];
    const float* Wk    = (const float*)d_in[3];
    const float* alpha = (const float*)d_in[4];
    float* out = (float*)d_out;

    cudaFuncSetAttribute(k1_proj,    cudaFuncAttributeMaxDynamicSharedMemorySize, K1_SMEM);
    cudaFuncSetAttribute(k2_logits,  cudaFuncAttributeMaxDynamicSharedMemorySize, K12_SMEM);
    cudaFuncSetAttribute(k3_refined, cudaFuncAttributeMaxDynamicSharedMemorySize, K3_SMEM);

    k0_splitW<<<(MIDC * C_CH + 255) / 256, 256>>>(Wq, Wk);
    k1_proj<<<dim3(9, 2, BATCH), 128, K1_SMEM>>>(feat);
    k2_logits<<<dim3(9, 9, BATCH), 256, K12_SMEM>>>();
    k2_softmax<<<(BATCH * N_SP) / 8, 256>>>();
    k3_refined<<<dim3(9, 16, BATCH), 128, K3_SMEM>>>(cam, alpha, out);
}

// round 13
// speedup vs baseline: 2.0977x; 1.0170x over previous
#include <cuda_runtime.h>
#include <cuda_fp16.h>
#include <cstdint>
#include <cstddef>

#define BATCH 32
#define C_CH  2048
#define N_SP  1152   // 48*24
#define MIDC  128

// ---------------- scratch (device globals; no allocation allowed) ----------------
__device__ __align__(128) float  g_attn[(size_t)BATCH * N_SP * N_SP];    // logits [b][i][j] f32
__device__ __align__(128) __half g_attn16[(size_t)BATCH * N_SP * N_SP];  // softmax [b][i][j] fp16
__device__ __align__(128) __half g_Wh[2][(size_t)MIDC * C_CH];           // fp16 hi of 2^13*W
__device__ __align__(128) __half g_Wl[2][(size_t)MIDC * C_CH];           // fp16 lo
__device__ __align__(128) __half g_qh[(size_t)BATCH * N_SP * MIDC];      // split(2^6 q) [n][m]
__device__ __align__(128) __half g_ql[(size_t)BATCH * N_SP * MIDC];
__device__ __align__(128) __half g_kh[(size_t)BATCH * N_SP * MIDC];      // split(2^6 k) [n][m]
__device__ __align__(128) __half g_kl[(size_t)BATCH * N_SP * MIDC];

// ---------------- helpers ----------------
__device__ __forceinline__ void split_h16(float x, __half& h, __half& l) {
    h = __float2half_rn(x);
    l = __float2half_rn(x - __half2float(h));
}
__device__ __forceinline__ void cp_async16(void* smem, const void* gmem) {
    uint32_t s = (uint32_t)__cvta_generic_to_shared(smem);
    asm volatile("cp.async.cg.shared.global [%0], [%1], 16;" :: "r"(s), "l"(gmem));
}
__device__ __forceinline__ void cp_commit() {
    asm volatile("cp.async.commit_group;" ::: "memory");
}
template <int NN>
__device__ __forceinline__ void cp_wait() {
    asm volatile("cp.async.wait_group %0;" :: "n"(NN) : "memory");
}
__device__ __forceinline__ void mma_f16(float c[4], const uint32_t a[4], const uint32_t b[2]) {
    asm volatile(
        "mma.sync.aligned.m16n8k16.row.col.f32.f16.f16.f32 "
        "{%0,%1,%2,%3}, {%4,%5,%6,%7}, {%8,%9}, {%0,%1,%2,%3};"
        : "+f"(c[0]), "+f"(c[1]), "+f"(c[2]), "+f"(c[3])
        : "r"(a[0]), "r"(a[1]), "r"(a[2]), "r"(a[3]), "r"(b[0]), "r"(b[1]));
}
__device__ __forceinline__ void ldsm_x4(uint32_t& r0, uint32_t& r1, uint32_t& r2, uint32_t& r3,
                                        uint32_t saddr) {
    asm volatile("ldmatrix.sync.aligned.m8n8.x4.shared.b16 {%0,%1,%2,%3}, [%4];"
                 : "=r"(r0), "=r"(r1), "=r"(r2), "=r"(r3) : "r"(saddr));
}
__device__ __forceinline__ void ldsm_x4_t(uint32_t& r0, uint32_t& r1, uint32_t& r2, uint32_t& r3,
                                          uint32_t saddr) {
    asm volatile("ldmatrix.sync.aligned.m8n8.x4.trans.shared.b16 {%0,%1,%2,%3}, [%4];"
                 : "=r"(r0), "=r"(r1), "=r"(r2), "=r"(r3) : "r"(saddr));
}

// ---- shared geometry ----
#define K1A_T 5120                       // halves per A tile (W hi or lo) [128][40]
#define K1B_T 4352                       // halves per B tile (x hi or lo) [32][136]
#define K1_STG (2 * K1A_T + 2 * K1B_T)
#define K1_SMEM (2 * K1_STG * 2)         // 75776 B
// K2a (Q-resident): Q tiles [128][136] hi+lo resident; K stages [128][136] hi+lo x2.
#define Q_T   (128 * 136)                // 17408 halves per tile
#define K2_QOFF 0
#define K2_KOFF (2 * Q_T)                // K stages start (halves)
#define K2_STG  (2 * Q_T)                // one K stage = Kh + Kl
#define K2_SMEM ((2 * Q_T + 2 * K2_STG) * 2)   // 208896 B
#define K3A_T 5120
#define K3B_T 4352
#define K3_STG (K3A_T + K3B_T)
#define K3_SMEM (2 * K3_STG * 2)         // 37888 B

// ============================================================================
// K0a: split 2^13*W into fp16 hi/lo (tiny).
// ============================================================================
__global__ void k0_splitW(const float* __restrict__ Wq, const float* __restrict__ Wk)
{
    const int i = blockIdx.x * 256 + threadIdx.x;
    if (i >= MIDC * C_CH) return;
    __half h, l;
    split_h16(Wq[i] * 8192.0f, h, l);
    g_Wh[0][i] = h; g_Wl[0][i] = l;
    split_h16(Wk[i] * 8192.0f, h, l);
    g_Wh[1][i] = h; g_Wl[1][i] = l;
}

// ============================================================================
// K1: projections via split-fp16 (3-term) mma m16n8k16. (unchanged)
// ============================================================================
__global__ __launch_bounds__(128, 2) void k1_proj(const float* __restrict__ feat)
{
    const int nblk = blockIdx.x;
    const int mblk = blockIdx.y;
    const int b    = blockIdx.z;
    const __half* Wh = g_Wh[mblk];
    const __half* Wl = g_Wl[mblk];
    const float*  X  = feat + (size_t)b * C_CH * N_SP;

    extern __shared__ __half smemh[];
    const uint32_t sb = (uint32_t)__cvta_generic_to_shared(smemh);

    const int tid  = threadIdx.x;
    const int warp = tid >> 5, lane = tid & 31;
    const int wm = warp >> 1, wn = warp & 1;
    const int g = lane >> 2, tig = lane & 3;
    const int n0 = nblk * 128;

    const uint32_t aRow = lane & 15;
    const uint32_t aCol = (lane >> 4) << 3;
    const uint32_t tKrow = (lane & 7) + (((lane >> 3) & 1) << 3);
    const uint32_t tNcol = (lane >> 4) << 3;

    float acc[4][8][4] = {};
    float4 xb[8];

    auto ldgB = [&](int kt) {
        const int k0 = kt * 32;
        #pragma unroll
        for (int it = 0; it < 8; it++) {
            int id  = tid + it * 128;
            int row = id >> 5;
            int nc  = (id & 31) * 4;
            xb[it] = *(const float4*)(X + (size_t)(k0 + row) * N_SP + n0 + nc);
        }
    };
    auto stsB = [&](int buf) {
        __half* st = smemh + buf * K1_STG + 2 * K1A_T;
        #pragma unroll
        for (int it = 0; it < 8; it++) {
            int id  = tid + it * 128;
            int row = id >> 5;
            int nc  = (id & 31) * 4;
            __half h0, l0, h1, l1, h2, l2, h3, l3;
            split_h16(xb[it].x, h0, l0); split_h16(xb[it].y, h1, l1);
            split_h16(xb[it].z, h2, l2); split_h16(xb[it].w, h3, l3);
            __half* ph = st + row * 136 + nc;
            *(__half2*)(ph)     = __halves2half2(h0, h1);
            *(__half2*)(ph + 2) = __halves2half2(h2, h3);
            __half* pl = ph + K1B_T;
            *(__half2*)(pl)     = __halves2half2(l0, l1);
            *(__half2*)(pl + 2) = __halves2half2(l2, l3);
        }
    };
    auto ldA = [&](int kt, int buf) {
        const int k0 = kt * 32;
        __half* st = smemh + buf * K1_STG;
        #pragma unroll
        for (int it = 0; it < 4; it++) {
            int id  = tid + it * 128;
            int row = id >> 2;
            int ch  = (id & 3) * 8;
            cp_async16(st + row * 40 + ch,         Wh + (size_t)row * C_CH + k0 + ch);
            cp_async16(st + K1A_T + row * 40 + ch, Wl + (size_t)row * C_CH + k0 + ch);
        }
    };

    const int KT = C_CH / 32;   // 64
    ldgB(0);
    ldA(0, 0); cp_commit();
    stsB(0);
    ldgB(1);

    for (int kt = 0; kt < KT; kt++) {
        const int buf = kt & 1;
        cp_wait<0>();
        __syncthreads();
        if (kt + 1 < KT) { ldA(kt + 1, buf ^ 1); cp_commit(); }

        const uint32_t stg  = sb + buf * (K1_STG * 2);
        const uint32_t stgB = stg + 2 * K1A_T * 2;
        #pragma unroll
        for (int ks = 0; ks < 2; ks++) {
            const int kb = ks * 16;
            uint32_t bh[8][2], bl[8][2];
            #pragma unroll
            for (int fnp = 0; fnp < 4; fnp++) {
                uint32_t ad = stgB + ((kb + tKrow) * 136 + wn * 64 + fnp * 16 + tNcol) * 2;
                ldsm_x4_t(bh[fnp * 2][0], bh[fnp * 2][1],
                          bh[fnp * 2 + 1][0], bh[fnp * 2 + 1][1], ad);
                ldsm_x4_t(bl[fnp * 2][0], bl[fnp * 2][1],
                          bl[fnp * 2 + 1][0], bl[fnp * 2 + 1][1], ad + K1B_T * 2);
            }
            #pragma unroll
            for (int fm = 0; fm < 4; fm++) {
                uint32_t ad = stg + ((wm * 64 + fm * 16 + aRow) * 40 + kb + aCol) * 2;
                uint32_t ah[4], al[4];
                ldsm_x4(ah[0], ah[1], ah[2], ah[3], ad);
                ldsm_x4(al[0], al[1], al[2], al[3], ad + K1A_T * 2);
                #pragma unroll
                for (int fn = 0; fn < 8; fn++) {
                    mma_f16(acc[fm][fn], ah, bh[fn]);
                    mma_f16(acc[fm][fn], al, bh[fn]);
                    mma_f16(acc[fm][fn], ah, bl[fn]);
                }
            }
        }

        if (kt + 1 < KT) {
            stsB(buf ^ 1);
            if (kt + 2 < KT) ldgB(kt + 2);
        }
    }

    __half* oh = (mblk == 0 ? g_qh : g_kh) + (size_t)b * N_SP * MIDC;
    __half* ol = (mblk == 0 ? g_ql : g_kl) + (size_t)b * N_SP * MIDC;
    #pragma unroll
    for (int fm = 0; fm < 4; fm++) {
        #pragma unroll
        for (int fn = 0; fn < 8; fn++) {
            int m = wm * 64 + fm * 16 + g;
            int n = n0 + wn * 64 + fn * 8 + tig * 2;
            #pragma unroll
            for (int e = 0; e < 4; e++) {
                int mm = m + (e >> 1) * 8;
                int nn = n + (e & 1);
                float v = acc[fm][fn][e] * 0.0078125f;
                __half h, l;
                split_h16(v, h, l);
                oh[(size_t)nn * MIDC + mm] = h;
                ol[(size_t)nn * MIDC + mm] = l;
            }
        }
    }
}

// ============================================================================
// K2a: logits, Q-resident persistent-j. grid (9 iblk, 32 b), 256 thr, 1 CTA/SM.
// Q hi/lo [128][136] resident; K hi/lo double-buffered; loop over 9 j-blocks.
// L[i][j] = 2^-12 * sum_m (2^6 q)(2^6 k), 3-term split-fp16.
// ============================================================================
__global__ __launch_bounds__(256, 1) void k2_logits(void)
{
    const int iblk = blockIdx.x;   // 0..8
    const int b    = blockIdx.y;
    const __half* Qh = g_qh + ((size_t)b * N_SP + iblk * 128) * MIDC;
    const __half* Ql = g_ql + ((size_t)b * N_SP + iblk * 128) * MIDC;
    const __half* Kh = g_kh + (size_t)b * N_SP * MIDC;
    const __half* Kl = g_kl + (size_t)b * N_SP * MIDC;
    float* L = g_attn + (size_t)b * N_SP * N_SP;

    extern __shared__ __half smemh[];
    const uint32_t sb = (uint32_t)__cvta_generic_to_shared(smemh);

    const int tid  = threadIdx.x;
    const int warp = tid >> 5, lane = tid & 31;
    const int wm = warp >> 2, wn = warp & 3;   // 2m x 4n of 64x32
    const int g = lane >> 2, tig = lane & 3;
    const int i0 = iblk * 128;

    const uint32_t aRow = lane & 15;
    const uint32_t aCol = (lane >> 4) << 3;
    const uint32_t bRow = (lane & 7) + ((lane >> 4) << 3);
    const uint32_t bCol = ((lane >> 3) & 1) << 3;

    // load Q tiles (hi/lo), full K=128: 128 rows x 16 chunks x 2 tiles
    {
        __half* st = smemh + K2_QOFF;
        #pragma unroll
        for (int it = 0; it < 8; it++) {
            int id  = tid + it * 256;
            int row = id >> 4;
            int ch  = (id & 15) * 8;
            cp_async16(st + row * 136 + ch,       Qh + (size_t)row * MIDC + ch);
            cp_async16(st + Q_T + row * 136 + ch, Ql + (size_t)row * MIDC + ch);
        }
        cp_commit();
    }
    auto ldK = [&](int jb, int buf) {
        __half* st = smemh + K2_KOFF + buf * K2_STG;
        const __half* kh = Kh + (size_t)jb * 128 * MIDC;
        const __half* kl = Kl + (size_t)jb * 128 * MIDC;
        #pragma unroll
        for (int it = 0; it < 8; it++) {
            int id  = tid + it * 256;
            int row = id >> 4;
            int ch  = (id & 15) * 8;
            cp_async16(st + row * 136 + ch,       kh + (size_t)row * MIDC + ch);
            cp_async16(st + Q_T + row * 136 + ch, kl + (size_t)row * MIDC + ch);
        }
        cp_commit();
    };

    ldK(0, 0);

    const float s = 2.44140625e-4f;   // 2^-12
    for (int jb = 0; jb < 9; jb++) {
        const int buf = jb & 1;
        cp_wait<0>();
        __syncthreads();                 // K(jb) + Q ready; buf^1 readers done
        if (jb + 1 < 9) ldK(jb + 1, buf ^ 1);

        const uint32_t stgQ = sb + K2_QOFF * 2;
        const uint32_t stgK = sb + (K2_KOFF + buf * K2_STG) * 2;

        float acc[4][4][4] = {};
        #pragma unroll
        for (int ks = 0; ks < 8; ks++) {
            const int kb = ks * 16;
            uint32_t bh[4][2], bl[4][2];
            #pragma unroll
            for (int fnp = 0; fnp < 2; fnp++) {
                uint32_t ad = stgK + ((wn * 32 + fnp * 16 + bRow) * 136 + kb + bCol) * 2;
                ldsm_x4(bh[fnp * 2][0], bh[fnp * 2][1], bh[fnp * 2 + 1][0], bh[fnp * 2 + 1][1], ad);
                ldsm_x4(bl[fnp * 2][0], bl[fnp * 2][1], bl[fnp * 2 + 1][0], bl[fnp * 2 + 1][1],
                        ad + Q_T * 2);
            }
            #pragma unroll
            for (int fm = 0; fm < 4; fm++) {
                uint32_t ad = stgQ + ((wm * 64 + fm * 16 + aRow) * 136 + kb + aCol) * 2;
                uint32_t ah[4], al[4];
                ldsm_x4(ah[0], ah[1], ah[2], ah[3], ad);
                ldsm_x4(al[0], al[1], al[2], al[3], ad + Q_T * 2);
                #pragma unroll
                for (int fn = 0; fn < 4; fn++) {
                    mma_f16(acc[fm][fn], ah, bh[fn]);
                    mma_f16(acc[fm][fn], al, bh[fn]);
                    mma_f16(acc[fm][fn], ah, bl[fn]);
                }
            }
        }

        const int j0 = jb * 128;
        #pragma unroll
        for (int fm = 0; fm < 4; fm++) {
            #pragma unroll
            for (int fn = 0; fn < 4; fn++) {
                int ii  = i0 + wm * 64 + fm * 16 + g;
                int col = j0 + wn * 32 + fn * 8 + tig * 2;
                *(float2*)(L + (size_t)ii * N_SP + col) =
                    make_float2(acc[fm][fn][0] * s, acc[fm][fn][1] * s);
                *(float2*)(L + (size_t)(ii + 8) * N_SP + col) =
                    make_float2(acc[fm][fn][2] * s, acc[fm][fn][3] * s);
            }
        }
    }
}

// ============================================================================
// K2b: row softmax (length 1152), one warp per row, float4 IO. f32 in, fp16 out.
// ============================================================================
__global__ void k2_softmax()
{
    const int row  = blockIdx.x * 8 + (threadIdx.x >> 5);
    const int lane = threadIdx.x & 31;
    const float* r   = g_attn   + (size_t)row * N_SP;
    __half*      r16 = g_attn16 + (size_t)row * N_SP;

    float4 f[9];
    float mx = -1e30f;
    #pragma unroll
    for (int t = 0; t < 9; t++) {
        f[t] = *(const float4*)(r + lane * 4 + t * 128);
        mx = fmaxf(mx, fmaxf(fmaxf(f[t].x, f[t].y), fmaxf(f[t].z, f[t].w)));
    }
    #pragma unroll
    for (int o = 16; o > 0; o >>= 1) mx = fmaxf(mx, __shfl_xor_sync(0xffffffffu, mx, o));

    float s = 0.0f;
    #pragma unroll
    for (int t = 0; t < 9; t++) {
        f[t].x = __expf(f[t].x - mx); f[t].y = __expf(f[t].y - mx);
        f[t].z = __expf(f[t].z - mx); f[t].w = __expf(f[t].w - mx);
        s += (f[t].x + f[t].y) + (f[t].z + f[t].w);
    }
    #pragma unroll
    for (int o = 16; o > 0; o >>= 1) s += __shfl_xor_sync(0xffffffffu, s, o);

    const float inv = 1.0f / s;
    #pragma unroll
    for (int t = 0; t < 9; t++) {
        __half2 h0 = __floats2half2_rn(f[t].x * inv, f[t].y * inv);
        __half2 h1 = __floats2half2_rn(f[t].z * inv, f[t].w * inv);
        *(__half2*)(r16 + lane * 4 + t * 128)     = h0;
        *(__half2*)(r16 + lane * 4 + t * 128 + 2) = h1;
    }
}

// ============================================================================
// K3: refined = cam @ attn via FP16 mma; cam converted in-kernel. (unchanged)
// ============================================================================
__global__ __launch_bounds__(128, 2) void k3_refined(
    const float* __restrict__ cam,
    const float* __restrict__ alphaPtr,
    float* __restrict__ out)
{
    const int jblk = blockIdx.x;
    const int cblk = blockIdx.y;
    const int b    = blockIdx.z;

    const __half* Bhg = g_attn16 + (size_t)b * N_SP * N_SP;
    const float*  Af  = cam      + (size_t)b * C_CH * N_SP;

    extern __shared__ __half smemh[];
    const uint32_t sb = (uint32_t)__cvta_generic_to_shared(smemh);

    const int tid  = threadIdx.x;
    const int warp = tid >> 5, lane = tid & 31;
    const int wm = warp >> 1, wn = warp & 1;
    const int g = lane >> 2, tig = lane & 3;
    const int c0 = cblk * 128, j0 = jblk * 128;

    const uint32_t aRow = lane & 15;
    const uint32_t aCol = (lane >> 4) << 3;
    const uint32_t tKrow = (lane & 7) + (((lane >> 3) & 1) << 3);
    const uint32_t tNcol = (lane >> 4) << 3;

    float acc[4][8][4] = {};
    float4 xa[8];

    auto ldgA = [&](int kt) {
        const int k0 = kt * 32;
        #pragma unroll
        for (int it = 0; it < 8; it++) {
            int id  = tid + it * 128;
            int row = id >> 3;
            int kc  = (id & 7) * 4;
            xa[it] = *(const float4*)(Af + (size_t)(c0 + row) * N_SP + k0 + kc);
        }
    };
    auto stsA = [&](int buf) {
        __half* st = smemh + buf * K3_STG;
        #pragma unroll
        for (int it = 0; it < 8; it++) {
            int id  = tid + it * 128;
            int row = id >> 3;
            int kc  = (id & 7) * 4;
            __half* p = st + row * 40 + kc;
            *(__half2*)(p)     = __floats2half2_rn(xa[it].x, xa[it].y);
            *(__half2*)(p + 2) = __floats2half2_rn(xa[it].z, xa[it].w);
        }
    };
    auto cpB = [&](int kt, int buf) {
        const int k0 = kt * 32;
        __half* st = smemh + buf * K3_STG + K3A_T;
        #pragma unroll
        for (int it = 0; it < 4; it++) {
            int id  = tid + it * 128;
            int row = id >> 4;
            int ch  = (id & 15) * 8;
            cp_async16(st + row * 136 + ch, Bhg + (size_t)(k0 + row) * N_SP + j0 + ch);
        }
    };

    const int KT = N_SP / 32;   // 36
    ldgA(0);
    cpB(0, 0); cp_commit();
    stsA(0);
    ldgA(1);

    for (int kt = 0; kt < KT; kt++) {
        const int buf = kt & 1;
        cp_wait<0>();
        __syncthreads();
        if (kt + 1 < KT) { cpB(kt + 1, buf ^ 1); cp_commit(); }

        const uint32_t stg  = sb + buf * (K3_STG * 2);
        const uint32_t stgB = stg + K3A_T * 2;
        #pragma unroll
        for (int ks = 0; ks < 2; ks++) {
            const int kb = ks * 16;
            uint32_t bfr[8][2];
            #pragma unroll
            for (int fnp = 0; fnp < 4; fnp++) {
                uint32_t ad = stgB + ((kb + tKrow) * 136 + wn * 64 + fnp * 16 + tNcol) * 2;
                ldsm_x4_t(bfr[fnp * 2][0], bfr[fnp * 2][1],
                          bfr[fnp * 2 + 1][0], bfr[fnp * 2 + 1][1], ad);
            }
            #pragma unroll
            for (int fm = 0; fm < 4; fm++) {
                uint32_t ad = stg + ((wm * 64 + fm * 16 + aRow) * 40 + kb + aCol) * 2;
                uint32_t afr[4];
                ldsm_x4(afr[0], afr[1], afr[2], afr[3], ad);
                #pragma unroll
                for (int fn = 0; fn < 8; fn++)
                    mma_f16(acc[fm][fn], afr, bfr[fn]);
            }
        }

        if (kt + 1 < KT) {
            stsA(buf ^ 1);
            if (kt + 2 < KT) ldgA(kt + 2);
        }
    }

    const float alpha = alphaPtr[0];
    const size_t base = (size_t)b * C_CH * N_SP;
    #pragma unroll
    for (int fm = 0; fm < 4; fm++) {
        #pragma unroll
        for (int fn = 0; fn < 8; fn++) {
            int mrow = c0 + wm * 64 + fm * 16 + g;
            int col  = j0 + wn * 64 + fn * 8 + tig * 2;
            const float2 cv0 = *(const float2*)(Af + (size_t)mrow * N_SP + col);
            const float2 cv1 = *(const float2*)(Af + (size_t)(mrow + 8) * N_SP + col);
            float2 r0, r1;
            r0.x = fmaf(alpha, acc[fm][fn][0], cv0.x);
            r0.y = fmaf(alpha, acc[fm][fn][1], cv0.y);
            r1.x = fmaf(alpha, acc[fm][fn][2], cv1.x);
            r1.y = fmaf(alpha, acc[fm][fn][3], cv1.y);
            *(float2*)(out + base + (size_t)mrow * N_SP + col)       = r0;
            *(float2*)(out + base + (size_t)(mrow + 8) * N_SP + col) = r1;
        }
    }
}

// ============================================================================
extern "C" void kernel_launch(void* const* d_in, const int* in_sizes, int n_in,
                              void* d_out, int out_size)
{
    (void)in_sizes; (void)n_in; (void)out_size;
    const float* feat  = (const float*)d_in[0];
    const float* cam   = (const float*)d_in[1];
    const float* Wq    = (const float*)d_in[2];
    const float* Wk    = (const float*)d_in[3];
    const float* alpha = (const float*)d_in[4];
    float* out = (float*)d_out;

    cudaFuncSetAttribute(k1_proj,    cudaFuncAttributeMaxDynamicSharedMemorySize, K1_SMEM);
    cudaFuncSetAttribute(k2_logits,  cudaFuncAttributeMaxDynamicSharedMemorySize, K2_SMEM);
    cudaFuncSetAttribute(k3_refined, cudaFuncAttributeMaxDynamicSharedMemorySize, K3_SMEM);

    k0_splitW<<<(MIDC * C_CH + 255) / 256, 256>>>(Wq, Wk);
    k1_proj<<<dim3(9, 2, BATCH), 128, K1_SMEM>>>(feat);
    k2_logits<<<dim3(9, BATCH), 256, K2_SMEM>>>();
    k2_softmax<<<(BATCH * N_SP) / 8, 256>>>();
    k3_refined<<<dim3(9, 16, BATCH), 128, K3_SMEM>>>(cam, alpha, out);
}